// round 1
// baseline (speedup 1.0000x reference)
#include <cuda_runtime.h>
#include <math.h>

#define B_    2
#define S_TOT 16384
#define D_    1024
#define CTX   1024
#define POOL  256
#define REM   15360
#define NH    16
#define HD    64
#define DFF   512

// ---------------- scratch (static device globals; no allocation) ----------------
__device__ float g_mlp_h[B_ * CTX * DFF];          //  4 MB
__device__ float g_comp_full[B_ * CTX * D_];       //  8 MB
__device__ float g_comp[B_ * POOL * D_];           //  2 MB
__device__ float g_Q[(size_t)B_ * S_TOT * D_];     // 128 MB
__device__ float g_Kinit[B_ * CTX * D_];           //  8 MB
__device__ float g_Vinit[B_ * CTX * D_];           //  8 MB
__device__ float g_Kcomp[B_ * POOL * D_];          //  2 MB
__device__ float g_Vcomp[B_ * POOL * D_];          //  2 MB
__device__ float g_attn[(size_t)B_ * S_TOT * D_];  // 128 MB

// ---------------- tiled SGEMM: C[M,N] = A[M,K] @ B[K,N] (+bias, +relu) ----------
// BM=128, BN=128, BK=8, 256 threads, 8x8 per thread. All dims multiples of tile.
template <bool RELU, bool BIAS>
__global__ __launch_bounds__(256) void sgemm128(
    const float* __restrict__ A, const float* __restrict__ Bm,
    const float* __restrict__ bias, float* __restrict__ C,
    int M, int N, int K)
{
    __shared__ float As[8][128];
    __shared__ float Bs[8][128];

    const int tid = threadIdx.x;
    const int bm = blockIdx.y * 128;
    const int bn = blockIdx.x * 128;

    const int aRow = tid >> 1;            // 0..127
    const int aCol = (tid & 1) * 4;       // 0 or 4
    const int bRow = tid >> 5;            // 0..7
    const int bCol = (tid & 31) * 4;      // 0..124

    const int tr = (tid >> 4) * 8;        // 0..120
    const int tc = (tid & 15) * 8;        // 0..120

    float acc[8][8];
#pragma unroll
    for (int i = 0; i < 8; i++)
#pragma unroll
        for (int j = 0; j < 8; j++) acc[i][j] = 0.f;

    const float* Aptr = A + (size_t)(bm + aRow) * K + aCol;
    const float* Bptr = Bm + (size_t)bRow * N + bn + bCol;

    for (int k0 = 0; k0 < K; k0 += 8) {
        float4 a4 = *(const float4*)(Aptr + k0);
        As[aCol + 0][aRow] = a4.x;
        As[aCol + 1][aRow] = a4.y;
        As[aCol + 2][aRow] = a4.z;
        As[aCol + 3][aRow] = a4.w;
        float4 b4 = *(const float4*)(Bptr + (size_t)k0 * N);
        *(float4*)&Bs[bRow][bCol] = b4;
        __syncthreads();

#pragma unroll
        for (int kk = 0; kk < 8; kk++) {
            float ar[8], br[8];
#pragma unroll
            for (int i = 0; i < 8; i++) ar[i] = As[kk][tr + i];
#pragma unroll
            for (int j = 0; j < 8; j++) br[j] = Bs[kk][tc + j];
#pragma unroll
            for (int i = 0; i < 8; i++)
#pragma unroll
                for (int j = 0; j < 8; j++)
                    acc[i][j] = fmaf(ar[i], br[j], acc[i][j]);
        }
        __syncthreads();
    }

#pragma unroll
    for (int i = 0; i < 8; i++) {
        float* crow = C + (size_t)(bm + tr + i) * N + bn + tc;
#pragma unroll
        for (int jc = 0; jc < 2; jc++) {
            float4 v;
            v.x = acc[i][jc * 4 + 0];
            v.y = acc[i][jc * 4 + 1];
            v.z = acc[i][jc * 4 + 2];
            v.w = acc[i][jc * 4 + 3];
            if (BIAS) {
                const float* bp = bias + bn + tc + jc * 4;
                v.x += bp[0]; v.y += bp[1]; v.z += bp[2]; v.w += bp[3];
            }
            if (RELU) {
                v.x = fmaxf(v.x, 0.f); v.y = fmaxf(v.y, 0.f);
                v.z = fmaxf(v.z, 0.f); v.w = fmaxf(v.w, 0.f);
            }
            *(float4*)(crow + jc * 4) = v;
        }
    }
}

// ---------------- pooling: mean over groups of 4 rows ---------------------------
__global__ void pool_mean(const float* __restrict__ full, float* __restrict__ comp)
{
    int idx = blockIdx.x * blockDim.x + threadIdx.x;  // < B_*POOL*D_
    int d = idx % D_;
    int p = (idx / D_) % POOL;
    int b = idx / (D_ * POOL);
    const float* src = full + ((size_t)b * CTX + p * 4) * D_ + d;
    comp[idx] = 0.25f * (src[0] + src[D_] + src[2 * D_] + src[3 * D_]);
}

// ---------------- cross attention: queries = remaining tokens, 256 keys ---------
// One thread per (query, head). Warp lanes share (b,h) and key index -> K/V loads
// are warp-uniform (L1 broadcast).
__global__ __launch_bounds__(128) void cross_attn(
    const float* __restrict__ Q, const float* __restrict__ K,
    const float* __restrict__ V, float* __restrict__ out)
{
    const int b = blockIdx.z, h = blockIdx.y;
    const int r = blockIdx.x * 128 + threadIdx.x;       // 0..REM-1
    const size_t qrow = (size_t)b * S_TOT + CTX + r;

    const float* q = Q + qrow * D_ + h * HD;
    float qv[HD];
#pragma unroll
    for (int i = 0; i < HD; i += 4) {
        float4 t = *(const float4*)(q + i);
        qv[i] = t.x; qv[i + 1] = t.y; qv[i + 2] = t.z; qv[i + 3] = t.w;
    }

    const float* Kb = K + (size_t)b * POOL * D_ + h * HD;
    const float* Vb = V + (size_t)b * POOL * D_ + h * HD;

    float m = -1e30f, l = 0.f;
    float o[HD];
#pragma unroll
    for (int i = 0; i < HD; i++) o[i] = 0.f;

    for (int j = 0; j < POOL; j++) {
        const float* krow = Kb + (size_t)j * D_;
        float s0 = 0.f, s1 = 0.f, s2 = 0.f, s3 = 0.f;
#pragma unroll
        for (int i4 = 0; i4 < 16; i4++) {
            float4 k4 = *(const float4*)(krow + i4 * 4);
            s0 = fmaf(qv[i4 * 4 + 0], k4.x, s0);
            s1 = fmaf(qv[i4 * 4 + 1], k4.y, s1);
            s2 = fmaf(qv[i4 * 4 + 2], k4.z, s2);
            s3 = fmaf(qv[i4 * 4 + 3], k4.w, s3);
        }
        float s = ((s0 + s1) + (s2 + s3)) * 0.125f;

        float mn = fmaxf(m, s);
        float corr = __expf(m - mn);
        float p = __expf(s - mn);
        l = l * corr + p;
        m = mn;

        const float* vrow = Vb + (size_t)j * D_;
#pragma unroll
        for (int i4 = 0; i4 < 16; i4++) {
            float4 v4 = *(const float4*)(vrow + i4 * 4);
            o[i4 * 4 + 0] = o[i4 * 4 + 0] * corr + p * v4.x;
            o[i4 * 4 + 1] = o[i4 * 4 + 1] * corr + p * v4.y;
            o[i4 * 4 + 2] = o[i4 * 4 + 2] * corr + p * v4.z;
            o[i4 * 4 + 3] = o[i4 * 4 + 3] * corr + p * v4.w;
        }
    }

    float inv = 1.f / l;
    float* op = out + qrow * D_ + h * HD;
#pragma unroll
    for (int i = 0; i < HD; i += 4) {
        float4 t;
        t.x = o[i] * inv; t.y = o[i + 1] * inv;
        t.z = o[i + 2] * inv; t.w = o[i + 3] * inv;
        *(float4*)(op + i) = t;
    }
}

// ---------------- causal self attention on initial tokens -----------------------
__global__ __launch_bounds__(128) void causal_attn(
    const float* __restrict__ Q, const float* __restrict__ K,
    const float* __restrict__ V, float* __restrict__ out)
{
    const int b = blockIdx.z, h = blockIdx.y;
    const int qp = blockIdx.x * 128 + threadIdx.x;      // 0..CTX-1
    const size_t qrow = (size_t)b * S_TOT + qp;

    const float* q = Q + qrow * D_ + h * HD;
    float qv[HD];
#pragma unroll
    for (int i = 0; i < HD; i += 4) {
        float4 t = *(const float4*)(q + i);
        qv[i] = t.x; qv[i + 1] = t.y; qv[i + 2] = t.z; qv[i + 3] = t.w;
    }

    const float* Kb = K + (size_t)b * CTX * D_ + h * HD;
    const float* Vb = V + (size_t)b * CTX * D_ + h * HD;

    float m = -1e30f, l = 0.f;
    float o[HD];
#pragma unroll
    for (int i = 0; i < HD; i++) o[i] = 0.f;

    for (int j = 0; j <= qp; j++) {
        const float* krow = Kb + (size_t)j * D_;
        float s0 = 0.f, s1 = 0.f, s2 = 0.f, s3 = 0.f;
#pragma unroll
        for (int i4 = 0; i4 < 16; i4++) {
            float4 k4 = *(const float4*)(krow + i4 * 4);
            s0 = fmaf(qv[i4 * 4 + 0], k4.x, s0);
            s1 = fmaf(qv[i4 * 4 + 1], k4.y, s1);
            s2 = fmaf(qv[i4 * 4 + 2], k4.z, s2);
            s3 = fmaf(qv[i4 * 4 + 3], k4.w, s3);
        }
        float s = ((s0 + s1) + (s2 + s3)) * 0.125f;

        float mn = fmaxf(m, s);
        float corr = __expf(m - mn);
        float p = __expf(s - mn);
        l = l * corr + p;
        m = mn;

        const float* vrow = Vb + (size_t)j * D_;
#pragma unroll
        for (int i4 = 0; i4 < 16; i4++) {
            float4 v4 = *(const float4*)(vrow + i4 * 4);
            o[i4 * 4 + 0] = o[i4 * 4 + 0] * corr + p * v4.x;
            o[i4 * 4 + 1] = o[i4 * 4 + 1] * corr + p * v4.y;
            o[i4 * 4 + 2] = o[i4 * 4 + 2] * corr + p * v4.z;
            o[i4 * 4 + 3] = o[i4 * 4 + 3] * corr + p * v4.w;
        }
    }

    float inv = 1.f / l;
    float* op = out + qrow * D_ + h * HD;
#pragma unroll
    for (int i = 0; i < HD; i += 4) {
        float4 t;
        t.x = o[i] * inv; t.y = o[i + 1] * inv;
        t.z = o[i + 2] * inv; t.w = o[i + 3] * inv;
        *(float4*)(op + i) = t;
    }
}

// ---------------- host launcher --------------------------------------------------
extern "C" void kernel_launch(void* const* d_in, const int* in_sizes, int n_in,
                              void* d_out, int out_size)
{
    const float* hs = (const float*)d_in[0];
    const float* Wq = (const float*)d_in[1];
    const float* Wk = (const float*)d_in[2];
    const float* Wv = (const float*)d_in[3];
    const float* Wo = (const float*)d_in[4];
    const float* W1 = (const float*)d_in[5];
    const float* b1 = (const float*)d_in[6];
    const float* W2 = (const float*)d_in[7];
    const float* b2 = (const float*)d_in[8];
    float* out = (float*)d_out;

    float *mlp_h, *comp_full, *comp, *Qb, *Kin, *Vin, *Kc, *Vc, *att;
    cudaGetSymbolAddress((void**)&mlp_h, g_mlp_h);
    cudaGetSymbolAddress((void**)&comp_full, g_comp_full);
    cudaGetSymbolAddress((void**)&comp, g_comp);
    cudaGetSymbolAddress((void**)&Qb, g_Q);
    cudaGetSymbolAddress((void**)&Kin, g_Kinit);
    cudaGetSymbolAddress((void**)&Vin, g_Vinit);
    cudaGetSymbolAddress((void**)&Kc, g_Kcomp);
    cudaGetSymbolAddress((void**)&Vc, g_Vcomp);
    cudaGetSymbolAddress((void**)&att, g_attn);

    // 1) MLP on initial tokens (per batch; initial rows are strided in hs)
    for (int b = 0; b < B_; b++) {
        sgemm128<true, true><<<dim3(DFF / 128, CTX / 128), 256>>>(
            hs + (size_t)b * S_TOT * D_, W1, b1, mlp_h + (size_t)b * CTX * DFF,
            CTX, DFF, D_);
    }
    for (int b = 0; b < B_; b++) {
        sgemm128<false, true><<<dim3(D_ / 128, CTX / 128), 256>>>(
            mlp_h + (size_t)b * CTX * DFF, W2, b2, comp_full + (size_t)b * CTX * D_,
            CTX, D_, DFF);
    }

    // 2) pool: (B, 256, 4, D).mean(axis=2)
    pool_mean<<<(B_ * POOL * D_) / 256, 256>>>(comp_full, comp);

    // 3) Q for ALL tokens (contiguous)
    sgemm128<false, false><<<dim3(D_ / 128, (B_ * S_TOT) / 128), 256>>>(
        hs, Wq, nullptr, Qb, B_ * S_TOT, D_, D_);

    // 4) K,V for initial tokens (per batch), K,V for comp (contiguous)
    for (int b = 0; b < B_; b++) {
        sgemm128<false, false><<<dim3(D_ / 128, CTX / 128), 256>>>(
            hs + (size_t)b * S_TOT * D_, Wk, nullptr, Kin + (size_t)b * CTX * D_,
            CTX, D_, D_);
        sgemm128<false, false><<<dim3(D_ / 128, CTX / 128), 256>>>(
            hs + (size_t)b * S_TOT * D_, Wv, nullptr, Vin + (size_t)b * CTX * D_,
            CTX, D_, D_);
    }
    sgemm128<false, false><<<dim3(D_ / 128, (B_ * POOL) / 128), 256>>>(
        comp, Wk, nullptr, Kc, B_ * POOL, D_, D_);
    sgemm128<false, false><<<dim3(D_ / 128, (B_ * POOL) / 128), 256>>>(
        comp, Wv, nullptr, Vc, B_ * POOL, D_, D_);

    // 5) attention
    cross_attn<<<dim3(REM / 128, NH, B_), 128>>>(Qb, Kc, Vc, att);
    causal_attn<<<dim3(CTX / 128, NH, B_), 128>>>(Qb, Kin, Vin, att);

    // 6) output projection straight into d_out (rows already in concat order)
    sgemm128<false, false><<<dim3(D_ / 128, (B_ * S_TOT) / 128), 256>>>(
        att, Wo, nullptr, out, B_ * S_TOT, D_, D_);

    (void)in_sizes; (void)n_in; (void)out_size;
}

// round 3
// speedup vs baseline: 1.1550x; 1.1550x over previous
#include <cuda_runtime.h>
#include <cuda_bf16.h>
#include <math.h>
#include <stdint.h>

#define B_    2
#define S_TOT 16384
#define D_    1024
#define CTX   1024
#define POOL  256
#define REM   15360
#define NH    16
#define HD    64
#define DFF   512

// ---------------- scratch (static device globals; no allocation) ----------------
__device__ float g_mlp_h[B_ * CTX * DFF];          //  4 MB
__device__ float g_comp_full[B_ * CTX * D_];       //  8 MB
__device__ float g_comp[B_ * POOL * D_];           //  2 MB
__device__ float g_Q[(size_t)B_ * S_TOT * D_];     // 128 MB
__device__ float g_Kinit[B_ * CTX * D_];           //  8 MB
__device__ float g_Vinit[B_ * CTX * D_];           //  8 MB
__device__ float g_Kcomp[B_ * POOL * D_];          //  2 MB
__device__ float g_Vcomp[B_ * POOL * D_];          //  2 MB
__device__ float g_attn[(size_t)B_ * S_TOT * D_];  // 128 MB

// ================= tensor-core GEMM: C = A[M,K] @ B[K,N], fp32 via bf16 split ===
// C = Ah*Bh + Al*Bh + Ah*Bl  (x = hi + lo, lo*lo dropped: ~2^-18 rel error)
// BM=BN=128, BK=32, 256 threads = 8 warps (4m x 2n), warp tile 32x64.

#define BK    32
#define LDA_S 40    // 32 + 8 pad (bf16 elems)
#define LDB_S 136   // 128 + 8 pad

__device__ __forceinline__ uint32_t smem_u32(const void* p) {
    return (uint32_t)__cvta_generic_to_shared(p);
}

__device__ __forceinline__ void ldsm_x4(uint32_t& r0, uint32_t& r1,
                                        uint32_t& r2, uint32_t& r3, uint32_t a) {
    asm volatile("ldmatrix.sync.aligned.m8n8.x4.shared.b16 {%0,%1,%2,%3},[%4];"
                 : "=r"(r0), "=r"(r1), "=r"(r2), "=r"(r3) : "r"(a));
}

__device__ __forceinline__ void ldsm_x4t(uint32_t& r0, uint32_t& r1,
                                         uint32_t& r2, uint32_t& r3, uint32_t a) {
    asm volatile("ldmatrix.sync.aligned.m8n8.x4.trans.shared.b16 {%0,%1,%2,%3},[%4];"
                 : "=r"(r0), "=r"(r1), "=r"(r2), "=r"(r3) : "r"(a));
}

__device__ __forceinline__ void mma16816(float* c, const uint32_t* a,
                                         uint32_t b0, uint32_t b1) {
    asm volatile(
        "mma.sync.aligned.m16n8k16.row.col.f32.bf16.bf16.f32 "
        "{%0,%1,%2,%3},{%4,%5,%6,%7},{%8,%9},{%0,%1,%2,%3};"
        : "+f"(c[0]), "+f"(c[1]), "+f"(c[2]), "+f"(c[3])
        : "r"(a[0]), "r"(a[1]), "r"(a[2]), "r"(a[3]), "r"(b0), "r"(b1));
}

template <bool RELU, bool BIAS>
__global__ __launch_bounds__(256) void hgemm128(
    const float* __restrict__ A, const float* __restrict__ Bm,
    const float* __restrict__ bias, float* __restrict__ C,
    int M, int N, int K)
{
    __shared__ __nv_bfloat16 As_hi[128 * LDA_S];
    __shared__ __nv_bfloat16 As_lo[128 * LDA_S];
    __shared__ __nv_bfloat16 Bs_hi[BK * LDB_S];
    __shared__ __nv_bfloat16 Bs_lo[BK * LDB_S];

    const int tid = threadIdx.x;
    const int lane = tid & 31;
    const int wid = tid >> 5;
    const int wm = (wid & 3) * 32;     // warp m offset in tile
    const int wn = (wid >> 2) * 64;    // warp n offset in tile
    const int bm = blockIdx.y * 128;
    const int bn = blockIdx.x * 128;

    // gmem load mapping: A tile 128x32, B tile 32x128, 16 floats per thread each
    const int arow = tid >> 1, acol = (tid & 1) * 16;
    const int brow = tid >> 3, bcol = (tid & 7) * 16;
    const float* Ag = A + (size_t)(bm + arow) * K + acol;
    const float* Bg = Bm + (size_t)brow * N + bn + bcol;

    float4 pa[4], pb[4];

#define LOAD_TILE(k0)                                                          \
    {                                                                          \
        _Pragma("unroll") for (int i = 0; i < 4; i++)                          \
            pa[i] = *(const float4*)(Ag + (k0) + i * 4);                       \
        _Pragma("unroll") for (int i = 0; i < 4; i++)                          \
            pb[i] = *(const float4*)(Bg + (size_t)(k0) * N + i * 4);           \
    }

#define STORE_TILE()                                                           \
    {                                                                          \
        _Pragma("unroll") for (int i = 0; i < 4; i++) {                        \
            float vv[4] = {pa[i].x, pa[i].y, pa[i].z, pa[i].w};                \
            _Pragma("unroll") for (int j = 0; j < 4; j++) {                    \
                float x = vv[j];                                               \
                __nv_bfloat16 h = __float2bfloat16(x);                         \
                __nv_bfloat16 l = __float2bfloat16(x - __bfloat162float(h));   \
                int idx = arow * LDA_S + acol + i * 4 + j;                     \
                As_hi[idx] = h; As_lo[idx] = l;                                \
            }                                                                  \
        }                                                                      \
        _Pragma("unroll") for (int i = 0; i < 4; i++) {                        \
            float vv[4] = {pb[i].x, pb[i].y, pb[i].z, pb[i].w};                \
            _Pragma("unroll") for (int j = 0; j < 4; j++) {                    \
                float x = vv[j];                                               \
                __nv_bfloat16 h = __float2bfloat16(x);                         \
                __nv_bfloat16 l = __float2bfloat16(x - __bfloat162float(h));   \
                int idx = brow * LDB_S + bcol + i * 4 + j;                     \
                Bs_hi[idx] = h; Bs_lo[idx] = l;                                \
            }                                                                  \
        }                                                                      \
    }

    float acc[2][8][4];
#pragma unroll
    for (int i = 0; i < 2; i++)
#pragma unroll
        for (int j = 0; j < 8; j++)
#pragma unroll
            for (int r = 0; r < 4; r++) acc[i][j][r] = 0.f;

    const uint32_t ah_base = smem_u32(As_hi);
    const uint32_t al_base = smem_u32(As_lo);
    const uint32_t bh_base = smem_u32(Bs_hi);
    const uint32_t bl_base = smem_u32(Bs_lo);

    // ldmatrix lane addressing
    const int a_r = lane & 15, a_c8 = (lane >> 4) * 8;   // A: m-row, k-half
    const int b_r = lane & 15, b_c8 = (lane >> 4) * 8;   // B: k-row, n-half

    LOAD_TILE(0);
    STORE_TILE();
    __syncthreads();

    for (int k0 = 0; k0 < K; k0 += BK) {
        const bool more = (k0 + BK) < K;
        if (more) LOAD_TILE(k0 + BK);

#pragma unroll
        for (int s = 0; s < 2; s++) {          // two k16 slices per BK=32
            const int ks = s * 16;
            uint32_t ah[2][4], al[2][4], bh[4][4], bl[4][4];
#pragma unroll
            for (int am = 0; am < 2; am++) {
                uint32_t addr = ah_base +
                    ((wm + am * 16 + a_r) * LDA_S + ks + a_c8) * 2;
                ldsm_x4(ah[am][0], ah[am][1], ah[am][2], ah[am][3], addr);
            }
#pragma unroll
            for (int p = 0; p < 4; p++) {      // each x4.trans covers 2 n-atoms
                uint32_t addr = bh_base +
                    ((ks + b_r) * LDB_S + wn + p * 16 + b_c8) * 2;
                ldsm_x4t(bh[p][0], bh[p][1], bh[p][2], bh[p][3], addr);
            }
            // hi * hi
#pragma unroll
            for (int am = 0; am < 2; am++)
#pragma unroll
                for (int p = 0; p < 4; p++) {
                    mma16816(acc[am][p * 2 + 0], ah[am], bh[p][0], bh[p][1]);
                    mma16816(acc[am][p * 2 + 1], ah[am], bh[p][2], bh[p][3]);
                }
            // lo * hi
#pragma unroll
            for (int am = 0; am < 2; am++) {
                uint32_t addr = al_base +
                    ((wm + am * 16 + a_r) * LDA_S + ks + a_c8) * 2;
                ldsm_x4(al[am][0], al[am][1], al[am][2], al[am][3], addr);
            }
#pragma unroll
            for (int am = 0; am < 2; am++)
#pragma unroll
                for (int p = 0; p < 4; p++) {
                    mma16816(acc[am][p * 2 + 0], al[am], bh[p][0], bh[p][1]);
                    mma16816(acc[am][p * 2 + 1], al[am], bh[p][2], bh[p][3]);
                }
            // hi * lo
#pragma unroll
            for (int p = 0; p < 4; p++) {
                uint32_t addr = bl_base +
                    ((ks + b_r) * LDB_S + wn + p * 16 + b_c8) * 2;
                ldsm_x4t(bl[p][0], bl[p][1], bl[p][2], bl[p][3], addr);
            }
#pragma unroll
            for (int am = 0; am < 2; am++)
#pragma unroll
                for (int p = 0; p < 4; p++) {
                    mma16816(acc[am][p * 2 + 0], ah[am], bl[p][0], bl[p][1]);
                    mma16816(acc[am][p * 2 + 1], ah[am], bl[p][2], bl[p][3]);
                }
        }

        __syncthreads();
        if (more) {
            STORE_TILE();
            __syncthreads();
        }
    }

    // epilogue: acc[am][an] -> rows bm+wm+am*16+{l>>2, +8}, cols bn+wn+an*8+(l&3)*2
#pragma unroll
    for (int am = 0; am < 2; am++) {
        const int r0 = bm + wm + am * 16 + (lane >> 2);
#pragma unroll
        for (int an = 0; an < 8; an++) {
            const int c = bn + wn + an * 8 + (lane & 3) * 2;
            float v0 = acc[am][an][0], v1 = acc[am][an][1];
            float v2 = acc[am][an][2], v3 = acc[am][an][3];
            if (BIAS) {
                float b0 = bias[c], b1 = bias[c + 1];
                v0 += b0; v1 += b1; v2 += b0; v3 += b1;
            }
            if (RELU) {
                v0 = fmaxf(v0, 0.f); v1 = fmaxf(v1, 0.f);
                v2 = fmaxf(v2, 0.f); v3 = fmaxf(v3, 0.f);
            }
            float* p0 = C + (size_t)r0 * N + c;
            float* p1 = C + (size_t)(r0 + 8) * N + c;
            p0[0] = v0; p0[1] = v1;
            p1[0] = v2; p1[1] = v3;
        }
    }
#undef LOAD_TILE
#undef STORE_TILE
}

// ---------------- pooling: mean over groups of 4 rows ---------------------------
__global__ void pool_mean(const float* __restrict__ full, float* __restrict__ comp)
{
    int idx = blockIdx.x * blockDim.x + threadIdx.x;  // < B_*POOL*D_
    int d = idx % D_;
    int p = (idx / D_) % POOL;
    int b = idx / (D_ * POOL);
    const float* src = full + ((size_t)b * CTX + p * 4) * D_ + d;
    comp[idx] = 0.25f * (src[0] + src[D_] + src[2 * D_] + src[3 * D_]);
}

// ---------------- cross attention: queries = remaining tokens, 256 keys ---------
__global__ __launch_bounds__(128) void cross_attn(
    const float* __restrict__ Q, const float* __restrict__ K,
    const float* __restrict__ V, float* __restrict__ out)
{
    const int b = blockIdx.z, h = blockIdx.y;
    const int r = blockIdx.x * 128 + threadIdx.x;       // 0..REM-1
    const size_t qrow = (size_t)b * S_TOT + CTX + r;

    const float* q = Q + qrow * D_ + h * HD;
    float qv[HD];
#pragma unroll
    for (int i = 0; i < HD; i += 4) {
        float4 t = *(const float4*)(q + i);
        qv[i] = t.x; qv[i + 1] = t.y; qv[i + 2] = t.z; qv[i + 3] = t.w;
    }

    const float* Kb = K + (size_t)b * POOL * D_ + h * HD;
    const float* Vb = V + (size_t)b * POOL * D_ + h * HD;

    float m = -1e30f, l = 0.f;
    float o[HD];
#pragma unroll
    for (int i = 0; i < HD; i++) o[i] = 0.f;

    for (int j = 0; j < POOL; j++) {
        const float* krow = Kb + (size_t)j * D_;
        float s0 = 0.f, s1 = 0.f, s2 = 0.f, s3 = 0.f;
#pragma unroll
        for (int i4 = 0; i4 < 16; i4++) {
            float4 k4 = *(const float4*)(krow + i4 * 4);
            s0 = fmaf(qv[i4 * 4 + 0], k4.x, s0);
            s1 = fmaf(qv[i4 * 4 + 1], k4.y, s1);
            s2 = fmaf(qv[i4 * 4 + 2], k4.z, s2);
            s3 = fmaf(qv[i4 * 4 + 3], k4.w, s3);
        }
        float s = ((s0 + s1) + (s2 + s3)) * 0.125f;

        float mn = fmaxf(m, s);
        float corr = __expf(m - mn);
        float p = __expf(s - mn);
        l = l * corr + p;
        m = mn;

        const float* vrow = Vb + (size_t)j * D_;
#pragma unroll
        for (int i4 = 0; i4 < 16; i4++) {
            float4 v4 = *(const float4*)(vrow + i4 * 4);
            o[i4 * 4 + 0] = o[i4 * 4 + 0] * corr + p * v4.x;
            o[i4 * 4 + 1] = o[i4 * 4 + 1] * corr + p * v4.y;
            o[i4 * 4 + 2] = o[i4 * 4 + 2] * corr + p * v4.z;
            o[i4 * 4 + 3] = o[i4 * 4 + 3] * corr + p * v4.w;
        }
    }

    float inv = 1.f / l;
    float* op = out + qrow * D_ + h * HD;
#pragma unroll
    for (int i = 0; i < HD; i += 4) {
        float4 t;
        t.x = o[i] * inv; t.y = o[i + 1] * inv;
        t.z = o[i + 2] * inv; t.w = o[i + 3] * inv;
        *(float4*)(op + i) = t;
    }
}

// ---------------- causal self attention on initial tokens -----------------------
__global__ __launch_bounds__(128) void causal_attn(
    const float* __restrict__ Q, const float* __restrict__ K,
    const float* __restrict__ V, float* __restrict__ out)
{
    const int b = blockIdx.z, h = blockIdx.y;
    const int qp = blockIdx.x * 128 + threadIdx.x;      // 0..CTX-1
    const size_t qrow = (size_t)b * S_TOT + qp;

    const float* q = Q + qrow * D_ + h * HD;
    float qv[HD];
#pragma unroll
    for (int i = 0; i < HD; i += 4) {
        float4 t = *(const float4*)(q + i);
        qv[i] = t.x; qv[i + 1] = t.y; qv[i + 2] = t.z; qv[i + 3] = t.w;
    }

    const float* Kb = K + (size_t)b * CTX * D_ + h * HD;
    const float* Vb = V + (size_t)b * CTX * D_ + h * HD;

    float m = -1e30f, l = 0.f;
    float o[HD];
#pragma unroll
    for (int i = 0; i < HD; i++) o[i] = 0.f;

    for (int j = 0; j <= qp; j++) {
        const float* krow = Kb + (size_t)j * D_;
        float s0 = 0.f, s1 = 0.f, s2 = 0.f, s3 = 0.f;
#pragma unroll
        for (int i4 = 0; i4 < 16; i4++) {
            float4 k4 = *(const float4*)(krow + i4 * 4);
            s0 = fmaf(qv[i4 * 4 + 0], k4.x, s0);
            s1 = fmaf(qv[i4 * 4 + 1], k4.y, s1);
            s2 = fmaf(qv[i4 * 4 + 2], k4.z, s2);
            s3 = fmaf(qv[i4 * 4 + 3], k4.w, s3);
        }
        float s = ((s0 + s1) + (s2 + s3)) * 0.125f;

        float mn = fmaxf(m, s);
        float corr = __expf(m - mn);
        float p = __expf(s - mn);
        l = l * corr + p;
        m = mn;

        const float* vrow = Vb + (size_t)j * D_;
#pragma unroll
        for (int i4 = 0; i4 < 16; i4++) {
            float4 v4 = *(const float4*)(vrow + i4 * 4);
            o[i4 * 4 + 0] = o[i4 * 4 + 0] * corr + p * v4.x;
            o[i4 * 4 + 1] = o[i4 * 4 + 1] * corr + p * v4.y;
            o[i4 * 4 + 2] = o[i4 * 4 + 2] * corr + p * v4.z;
            o[i4 * 4 + 3] = o[i4 * 4 + 3] * corr + p * v4.w;
        }
    }

    float inv = 1.f / l;
    float* op = out + qrow * D_ + h * HD;
#pragma unroll
    for (int i = 0; i < HD; i += 4) {
        float4 t;
        t.x = o[i] * inv; t.y = o[i + 1] * inv;
        t.z = o[i + 2] * inv; t.w = o[i + 3] * inv;
        *(float4*)(op + i) = t;
    }
}

// ---------------- host launcher --------------------------------------------------
extern "C" void kernel_launch(void* const* d_in, const int* in_sizes, int n_in,
                              void* d_out, int out_size)
{
    const float* hs = (const float*)d_in[0];
    const float* Wq = (const float*)d_in[1];
    const float* Wk = (const float*)d_in[2];
    const float* Wv = (const float*)d_in[3];
    const float* Wo = (const float*)d_in[4];
    const float* W1 = (const float*)d_in[5];
    const float* b1 = (const float*)d_in[6];
    const float* W2 = (const float*)d_in[7];
    const float* b2 = (const float*)d_in[8];
    float* out = (float*)d_out;

    float *mlp_h, *comp_full, *comp, *Qb, *Kin, *Vin, *Kc, *Vc, *att;
    cudaGetSymbolAddress((void**)&mlp_h, g_mlp_h);
    cudaGetSymbolAddress((void**)&comp_full, g_comp_full);
    cudaGetSymbolAddress((void**)&comp, g_comp);
    cudaGetSymbolAddress((void**)&Qb, g_Q);
    cudaGetSymbolAddress((void**)&Kin, g_Kinit);
    cudaGetSymbolAddress((void**)&Vin, g_Vinit);
    cudaGetSymbolAddress((void**)&Kc, g_Kcomp);
    cudaGetSymbolAddress((void**)&Vc, g_Vcomp);
    cudaGetSymbolAddress((void**)&att, g_attn);

    // 1) MLP on initial tokens (per batch; initial rows are strided in hs)
    for (int b = 0; b < B_; b++) {
        hgemm128<true, true><<<dim3(DFF / 128, CTX / 128), 256>>>(
            hs + (size_t)b * S_TOT * D_, W1, b1, mlp_h + (size_t)b * CTX * DFF,
            CTX, DFF, D_);
    }
    for (int b = 0; b < B_; b++) {
        hgemm128<false, true><<<dim3(D_ / 128, CTX / 128), 256>>>(
            mlp_h + (size_t)b * CTX * DFF, W2, b2, comp_full + (size_t)b * CTX * D_,
            CTX, D_, DFF);
    }

    // 2) pool: (B, 256, 4, D).mean(axis=2)
    pool_mean<<<(B_ * POOL * D_) / 256, 256>>>(comp_full, comp);

    // 3) Q for ALL tokens (contiguous)
    hgemm128<false, false><<<dim3(D_ / 128, (B_ * S_TOT) / 128), 256>>>(
        hs, Wq, nullptr, Qb, B_ * S_TOT, D_, D_);

    // 4) K,V for initial tokens (per batch), K,V for comp (contiguous)
    for (int b = 0; b < B_; b++) {
        hgemm128<false, false><<<dim3(D_ / 128, CTX / 128), 256>>>(
            hs + (size_t)b * S_TOT * D_, Wk, nullptr, Kin + (size_t)b * CTX * D_,
            CTX, D_, D_);
        hgemm128<false, false><<<dim3(D_ / 128, CTX / 128), 256>>>(
            hs + (size_t)b * S_TOT * D_, Wv, nullptr, Vin + (size_t)b * CTX * D_,
            CTX, D_, D_);
    }
    hgemm128<false, false><<<dim3(D_ / 128, (B_ * POOL) / 128), 256>>>(
        comp, Wk, nullptr, Kc, B_ * POOL, D_, D_);
    hgemm128<false, false><<<dim3(D_ / 128, (B_ * POOL) / 128), 256>>>(
        comp, Wv, nullptr, Vc, B_ * POOL, D_, D_);

    // 5) attention
    cross_attn<<<dim3(REM / 128, NH, B_), 128>>>(Qb, Kc, Vc, att);
    causal_attn<<<dim3(CTX / 128, NH, B_), 128>>>(Qb, Kin, Vin, att);

    // 6) output projection straight into d_out (rows already in concat order)
    hgemm128<false, false><<<dim3(D_ / 128, (B_ * S_TOT) / 128), 256>>>(
        att, Wo, nullptr, out, B_ * S_TOT, D_, D_);

    (void)in_sizes; (void)n_in; (void)out_size;
}

// round 6
// speedup vs baseline: 1.3180x; 1.1411x over previous
#include <cuda_runtime.h>
#include <cuda_bf16.h>
#include <math.h>
#include <stdint.h>

#define B_    2
#define S_TOT 16384
#define D_    1024
#define CTX   1024
#define POOL  256
#define REM   15360
#define NH    16
#define HD    64
#define DFF   512

// ---------------- scratch (static device globals; no allocation) ----------------
__device__ float g_comp_full[B_ * CTX * D_];                 // fp32
__device__ float g_Q[(size_t)B_ * S_TOT * D_];               // fp32, 128 MB
__device__ float g_Kinit[B_ * CTX * D_];
__device__ float g_Vinit[B_ * CTX * D_];
__device__ float g_Kcomp[B_ * POOL * D_];
__device__ float g_Vcomp[B_ * POOL * D_];

// bf16 split operand buffers
__device__ __nv_bfloat16 g_hs_hi[(size_t)B_ * S_TOT * D_];   // 64 MB
__device__ __nv_bfloat16 g_hs_lo[(size_t)B_ * S_TOT * D_];
__device__ __nv_bfloat16 g_att_hi[(size_t)B_ * S_TOT * D_];
__device__ __nv_bfloat16 g_att_lo[(size_t)B_ * S_TOT * D_];
__device__ __nv_bfloat16 g_mlp_hi[B_ * CTX * DFF];
__device__ __nv_bfloat16 g_mlp_lo[B_ * CTX * DFF];
__device__ __nv_bfloat16 g_comp_hi[B_ * POOL * D_];
__device__ __nv_bfloat16 g_comp_lo[B_ * POOL * D_];
__device__ __nv_bfloat16 g_Wq_hi[D_ * D_], g_Wq_lo[D_ * D_];
__device__ __nv_bfloat16 g_Wk_hi[D_ * D_], g_Wk_lo[D_ * D_];
__device__ __nv_bfloat16 g_Wv_hi[D_ * D_], g_Wv_lo[D_ * D_];
__device__ __nv_bfloat16 g_Wo_hi[D_ * D_], g_Wo_lo[D_ * D_];
__device__ __nv_bfloat16 g_W1_hi[D_ * DFF], g_W1_lo[D_ * DFF];
__device__ __nv_bfloat16 g_W2_hi[DFF * D_], g_W2_lo[DFF * D_];

// ---------------- helpers --------------------------------------------------------
__device__ __forceinline__ uint32_t smem_u32(const void* p) {
    return (uint32_t)__cvta_generic_to_shared(p);
}
__device__ __forceinline__ void cpa16(uint32_t dst, const void* src) {
    asm volatile("cp.async.cg.shared.global [%0],[%1],16;" :: "r"(dst), "l"(src));
}
__device__ __forceinline__ void cp_commit() {
    asm volatile("cp.async.commit_group;");
}
template <int NG>
__device__ __forceinline__ void cp_wait() {
    asm volatile("cp.async.wait_group %0;" :: "n"(NG));
}
__device__ __forceinline__ void ldsm_x4(uint32_t& r0, uint32_t& r1,
                                        uint32_t& r2, uint32_t& r3, uint32_t a) {
    asm volatile("ldmatrix.sync.aligned.m8n8.x4.shared.b16 {%0,%1,%2,%3},[%4];"
                 : "=r"(r0), "=r"(r1), "=r"(r2), "=r"(r3) : "r"(a));
}
__device__ __forceinline__ void ldsm_x4t(uint32_t& r0, uint32_t& r1,
                                         uint32_t& r2, uint32_t& r3, uint32_t a) {
    asm volatile("ldmatrix.sync.aligned.m8n8.x4.trans.shared.b16 {%0,%1,%2,%3},[%4];"
                 : "=r"(r0), "=r"(r1), "=r"(r2), "=r"(r3) : "r"(a));
}
__device__ __forceinline__ void mma16816(float* c, const uint32_t* a,
                                         uint32_t b0, uint32_t b1) {
    asm volatile(
        "mma.sync.aligned.m16n8k16.row.col.f32.bf16.bf16.f32 "
        "{%0,%1,%2,%3},{%4,%5,%6,%7},{%8,%9},{%0,%1,%2,%3};"
        : "+f"(c[0]), "+f"(c[1]), "+f"(c[2]), "+f"(c[3])
        : "r"(a[0]), "r"(a[1]), "r"(a[2]), "r"(a[3]), "r"(b0), "r"(b1));
}
__device__ __forceinline__ void split1(float x, __nv_bfloat16& h, __nv_bfloat16& l) {
    h = __float2bfloat16(x);
    l = __float2bfloat16(x - __bfloat162float(h));
}

// ---------------- fp32 -> (hi, lo) bf16 split, vectorized ------------------------
__global__ void split_f32(const float* __restrict__ src,
                          __nv_bfloat16* __restrict__ hi,
                          __nv_bfloat16* __restrict__ lo, int n4)
{
    int i = blockIdx.x * blockDim.x + threadIdx.x;
    if (i >= n4) return;
    float4 v = ((const float4*)src)[i];
    __nv_bfloat16 h[4], l[4];
    split1(v.x, h[0], l[0]); split1(v.y, h[1], l[1]);
    split1(v.z, h[2], l[2]); split1(v.w, h[3], l[3]);
    ((uint2*)hi)[i] = *(uint2*)h;
    ((uint2*)lo)[i] = *(uint2*)l;
}

// ================= pipelined bf16-split tensor-core GEMM =========================
// C = (Ahi+Alo)@(Bhi+Blo) approx = Ah*Bh + Al*Bh + Ah*Bl
// BM=BN=128, BK=32, 4-stage cp.async pipeline, 256 thr = 8 warps (4m x 2n).
#define BK      32
#define LDA_S   40      // bf16 elems per A smem row (32 + 8 pad)
#define LDB_S   136     // bf16 elems per B smem row (128 + 8 pad)
#define A_BYTES (128 * LDA_S * 2)   // 10240
#define B_BYTES (BK * LDB_S * 2)    // 8704
#define OFF_AL  A_BYTES
#define OFF_BH  (2 * A_BYTES)
#define OFF_BL  (2 * A_BYTES + B_BYTES)
#define STAGE_BYTES (2 * A_BYTES + 2 * B_BYTES)   // 37888
#define STAGES  4
#define SMEM_TOTAL_GEMM (STAGES * STAGE_BYTES)    // 151552

template <bool RELU, bool BIAS, bool OSPLIT>
__global__ __launch_bounds__(256) void hgemm(
    const __nv_bfloat16* __restrict__ Ahi, const __nv_bfloat16* __restrict__ Alo,
    const __nv_bfloat16* __restrict__ Bhi, const __nv_bfloat16* __restrict__ Blo,
    const float* __restrict__ bias,
    float* __restrict__ C,
    __nv_bfloat16* __restrict__ Chi, __nv_bfloat16* __restrict__ Clo,
    int M, int N, int K)
{
    extern __shared__ char smem[];
    const uint32_t sm_base = smem_u32(smem);

    const int tid = threadIdx.x;
    const int lane = tid & 31;
    const int wid = tid >> 5;
    const int wm = (wid & 3) * 32;
    const int wn = (wid >> 2) * 64;
    const int bm = blockIdx.y * 128;
    const int bn = blockIdx.x * 128;

    // gmem->smem mapping: A row=tid>>1, 32B at col (tid&1)*16; B row=tid>>3, 32B at col (tid&7)*16
    const int a_row = tid >> 1, a_col = (tid & 1) * 16;
    const int b_row = tid >> 3, b_col = (tid & 7) * 16;
    const __nv_bfloat16* Agh = Ahi + (size_t)(bm + a_row) * K + a_col;
    const __nv_bfloat16* Agl = Alo + (size_t)(bm + a_row) * K + a_col;
    const __nv_bfloat16* Bgh = Bhi + (size_t)b_row * N + bn + b_col;
    const __nv_bfloat16* Bgl = Blo + (size_t)b_row * N + bn + b_col;
    const uint32_t a_dst = sm_base + a_row * (LDA_S * 2) + a_col * 2;
    const uint32_t b_dst = sm_base + b_row * (LDB_S * 2) + b_col * 2;

#define LOAD_STAGE(stg, k0)                                                    \
    {                                                                          \
        uint32_t sb = (stg) * STAGE_BYTES;                                     \
        const __nv_bfloat16* ah = Agh + (k0);                                  \
        const __nv_bfloat16* al = Agl + (k0);                                  \
        cpa16(a_dst + sb, ah);                 cpa16(a_dst + sb + 16, ah + 8); \
        cpa16(a_dst + sb + OFF_AL, al);        cpa16(a_dst + sb + OFF_AL + 16, al + 8); \
        const __nv_bfloat16* bh = Bgh + (size_t)(k0) * N;                      \
        const __nv_bfloat16* bl = Bgl + (size_t)(k0) * N;                      \
        cpa16(b_dst + sb + OFF_BH, bh);        cpa16(b_dst + sb + OFF_BH + 16, bh + 8); \
        cpa16(b_dst + sb + OFF_BL, bl);        cpa16(b_dst + sb + OFF_BL + 16, bl + 8); \
    }

    float acc[2][8][4];
#pragma unroll
    for (int i = 0; i < 2; i++)
#pragma unroll
        for (int j = 0; j < 8; j++)
#pragma unroll
            for (int r = 0; r < 4; r++) acc[i][j][r] = 0.f;

    const int ktiles = K / BK;

    // prologue: stages 0..2
#pragma unroll
    for (int s = 0; s < STAGES - 1; s++) {
        if (s < ktiles) LOAD_STAGE(s, s * BK);
        cp_commit();
    }

    const int a_r = lane & 15, a_c8 = (lane >> 4) * 8;
    const int b_r = lane & 15, b_c8 = (lane >> 4) * 8;

    for (int it = 0; it < ktiles; it++) {
        cp_wait<STAGES - 2>();
        __syncthreads();

        if (it + STAGES - 1 < ktiles)
            LOAD_STAGE((it + STAGES - 1) & (STAGES - 1), (it + STAGES - 1) * BK);
        cp_commit();

        const uint32_t sb = sm_base + (it & (STAGES - 1)) * STAGE_BYTES;
        const uint32_t ah_b = sb, al_b = sb + OFF_AL;
        const uint32_t bh_b = sb + OFF_BH, bl_b = sb + OFF_BL;

#pragma unroll
        for (int s = 0; s < 2; s++) {
            const int ks = s * 16;
            uint32_t ah[2][4], al[2][4], bh[4][4], bl[4][4];
#pragma unroll
            for (int am = 0; am < 2; am++) {
                uint32_t addr = ah_b + ((wm + am * 16 + a_r) * LDA_S + ks + a_c8) * 2;
                ldsm_x4(ah[am][0], ah[am][1], ah[am][2], ah[am][3], addr);
            }
#pragma unroll
            for (int p = 0; p < 4; p++) {
                uint32_t addr = bh_b + ((ks + b_r) * LDB_S + wn + p * 16 + b_c8) * 2;
                ldsm_x4t(bh[p][0], bh[p][1], bh[p][2], bh[p][3], addr);
            }
#pragma unroll
            for (int am = 0; am < 2; am++)
#pragma unroll
                for (int p = 0; p < 4; p++) {
                    mma16816(acc[am][p * 2 + 0], ah[am], bh[p][0], bh[p][1]);
                    mma16816(acc[am][p * 2 + 1], ah[am], bh[p][2], bh[p][3]);
                }
#pragma unroll
            for (int am = 0; am < 2; am++) {
                uint32_t addr = al_b + ((wm + am * 16 + a_r) * LDA_S + ks + a_c8) * 2;
                ldsm_x4(al[am][0], al[am][1], al[am][2], al[am][3], addr);
            }
#pragma unroll
            for (int am = 0; am < 2; am++)
#pragma unroll
                for (int p = 0; p < 4; p++) {
                    mma16816(acc[am][p * 2 + 0], al[am], bh[p][0], bh[p][1]);
                    mma16816(acc[am][p * 2 + 1], al[am], bh[p][2], bh[p][3]);
                }
#pragma unroll
            for (int p = 0; p < 4; p++) {
                uint32_t addr = bl_b + ((ks + b_r) * LDB_S + wn + p * 16 + b_c8) * 2;
                ldsm_x4t(bl[p][0], bl[p][1], bl[p][2], bl[p][3], addr);
            }
#pragma unroll
            for (int am = 0; am < 2; am++)
#pragma unroll
                for (int p = 0; p < 4; p++) {
                    mma16816(acc[am][p * 2 + 0], ah[am], bl[p][0], bl[p][1]);
                    mma16816(acc[am][p * 2 + 1], ah[am], bl[p][2], bl[p][3]);
                }
        }
        __syncthreads();
    }

    // epilogue
#pragma unroll
    for (int am = 0; am < 2; am++) {
        const int r0 = bm + wm + am * 16 + (lane >> 2);
#pragma unroll
        for (int an = 0; an < 8; an++) {
            const int c = bn + wn + an * 8 + (lane & 3) * 2;
            float v0 = acc[am][an][0], v1 = acc[am][an][1];
            float v2 = acc[am][an][2], v3 = acc[am][an][3];
            if (BIAS) {
                float bb0 = bias[c], bb1 = bias[c + 1];
                v0 += bb0; v1 += bb1; v2 += bb0; v3 += bb1;
            }
            if (RELU) {
                v0 = fmaxf(v0, 0.f); v1 = fmaxf(v1, 0.f);
                v2 = fmaxf(v2, 0.f); v3 = fmaxf(v3, 0.f);
            }
            if (OSPLIT) {
                __nv_bfloat16 h0, l0, h1, l1;
                size_t i0 = (size_t)r0 * N + c, i1 = (size_t)(r0 + 8) * N + c;
                split1(v0, h0, l0); split1(v1, h1, l1);
                __nv_bfloat162 hh; hh.x = h0; hh.y = h1;
                __nv_bfloat162 ll; ll.x = l0; ll.y = l1;
                *(__nv_bfloat162*)(Chi + i0) = hh;
                *(__nv_bfloat162*)(Clo + i0) = ll;
                split1(v2, h0, l0); split1(v3, h1, l1);
                hh.x = h0; hh.y = h1; ll.x = l0; ll.y = l1;
                *(__nv_bfloat162*)(Chi + i1) = hh;
                *(__nv_bfloat162*)(Clo + i1) = ll;
            } else {
                float* p0 = C + (size_t)r0 * N + c;
                float* p1 = C + (size_t)(r0 + 8) * N + c;
                p0[0] = v0; p0[1] = v1;
                p1[0] = v2; p1[1] = v3;
            }
        }
    }
#undef LOAD_STAGE
}

// ---------------- pooling: mean over groups of 4 rows -> split bf16 --------------
__global__ void pool_mean_split(const float* __restrict__ full,
                                __nv_bfloat16* __restrict__ hi,
                                __nv_bfloat16* __restrict__ lo)
{
    int idx = blockIdx.x * blockDim.x + threadIdx.x;  // < B_*POOL*D_
    int d = idx % D_;
    int p = (idx / D_) % POOL;
    int b = idx / (D_ * POOL);
    const float* src = full + ((size_t)b * CTX + p * 4) * D_ + d;
    float v = 0.25f * (src[0] + src[D_] + src[2 * D_] + src[3 * D_]);
    __nv_bfloat16 h, l;
    split1(v, h, l);
    hi[idx] = h; lo[idx] = l;
}

// ---------------- attention (fp32 math, bf16-split output) -----------------------
__device__ __forceinline__ void attn_store_split(
    __nv_bfloat16* __restrict__ hi, __nv_bfloat16* __restrict__ lo,
    size_t base, const float* o, float inv)
{
#pragma unroll
    for (int i = 0; i < HD; i += 4) {
        __nv_bfloat16 h[4], l[4];
#pragma unroll
        for (int j = 0; j < 4; j++) split1(o[i + j] * inv, h[j], l[j]);
        *(uint2*)(hi + base + i) = *(uint2*)h;
        *(uint2*)(lo + base + i) = *(uint2*)l;
    }
}

__global__ __launch_bounds__(128) void cross_attn(
    const float* __restrict__ Q, const float* __restrict__ K,
    const float* __restrict__ V,
    __nv_bfloat16* __restrict__ Ohi, __nv_bfloat16* __restrict__ Olo)
{
    const int b = blockIdx.z, h = blockIdx.y;
    const int r = blockIdx.x * 128 + threadIdx.x;
    const size_t qrow = (size_t)b * S_TOT + CTX + r;

    const float* q = Q + qrow * D_ + h * HD;
    float qv[HD];
#pragma unroll
    for (int i = 0; i < HD; i += 4) {
        float4 t = *(const float4*)(q + i);
        qv[i] = t.x; qv[i + 1] = t.y; qv[i + 2] = t.z; qv[i + 3] = t.w;
    }

    const float* Kb = K + (size_t)b * POOL * D_ + h * HD;
    const float* Vb = V + (size_t)b * POOL * D_ + h * HD;

    float m = -1e30f, l = 0.f;
    float o[HD];
#pragma unroll
    for (int i = 0; i < HD; i++) o[i] = 0.f;

    for (int j = 0; j < POOL; j++) {
        const float* krow = Kb + (size_t)j * D_;
        float s0 = 0.f, s1 = 0.f, s2 = 0.f, s3 = 0.f;
#pragma unroll
        for (int i4 = 0; i4 < 16; i4++) {
            float4 k4 = *(const float4*)(krow + i4 * 4);
            s0 = fmaf(qv[i4 * 4 + 0], k4.x, s0);
            s1 = fmaf(qv[i4 * 4 + 1], k4.y, s1);
            s2 = fmaf(qv[i4 * 4 + 2], k4.z, s2);
            s3 = fmaf(qv[i4 * 4 + 3], k4.w, s3);
        }
        float s = ((s0 + s1) + (s2 + s3)) * 0.125f;

        float mn = fmaxf(m, s);
        float corr = __expf(m - mn);
        float p = __expf(s - mn);
        l = l * corr + p;
        m = mn;

        const float* vrow = Vb + (size_t)j * D_;
#pragma unroll
        for (int i4 = 0; i4 < 16; i4++) {
            float4 v4 = *(const float4*)(vrow + i4 * 4);
            o[i4 * 4 + 0] = o[i4 * 4 + 0] * corr + p * v4.x;
            o[i4 * 4 + 1] = o[i4 * 4 + 1] * corr + p * v4.y;
            o[i4 * 4 + 2] = o[i4 * 4 + 2] * corr + p * v4.z;
            o[i4 * 4 + 3] = o[i4 * 4 + 3] * corr + p * v4.w;
        }
    }
    attn_store_split(Ohi, Olo, qrow * D_ + h * HD, o, 1.f / l);
}

__global__ __launch_bounds__(128) void causal_attn(
    const float* __restrict__ Q, const float* __restrict__ K,
    const float* __restrict__ V,
    __nv_bfloat16* __restrict__ Ohi, __nv_bfloat16* __restrict__ Olo)
{
    const int b = blockIdx.z, h = blockIdx.y;
    const int qp = blockIdx.x * 128 + threadIdx.x;
    const size_t qrow = (size_t)b * S_TOT + qp;

    const float* q = Q + qrow * D_ + h * HD;
    float qv[HD];
#pragma unroll
    for (int i = 0; i < HD; i += 4) {
        float4 t = *(const float4*)(q + i);
        qv[i] = t.x; qv[i + 1] = t.y; qv[i + 2] = t.z; qv[i + 3] = t.w;
    }

    const float* Kb = K + (size_t)b * CTX * D_ + h * HD;
    const float* Vb = V + (size_t)b * CTX * D_ + h * HD;

    float m = -1e30f, l = 0.f;
    float o[HD];
#pragma unroll
    for (int i = 0; i < HD; i++) o[i] = 0.f;

    for (int j = 0; j <= qp; j++) {
        const float* krow = Kb + (size_t)j * D_;
        float s0 = 0.f, s1 = 0.f, s2 = 0.f, s3 = 0.f;
#pragma unroll
        for (int i4 = 0; i4 < 16; i4++) {
            float4 k4 = *(const float4*)(krow + i4 * 4);
            s0 = fmaf(qv[i4 * 4 + 0], k4.x, s0);
            s1 = fmaf(qv[i4 * 4 + 1], k4.y, s1);
            s2 = fmaf(qv[i4 * 4 + 2], k4.z, s2);
            s3 = fmaf(qv[i4 * 4 + 3], k4.w, s3);
        }
        float s = ((s0 + s1) + (s2 + s3)) * 0.125f;

        float mn = fmaxf(m, s);
        float corr = __expf(m - mn);
        float p = __expf(s - mn);
        l = l * corr + p;
        m = mn;

        const float* vrow = Vb + (size_t)j * D_;
#pragma unroll
        for (int i4 = 0; i4 < 16; i4++) {
            float4 v4 = *(const float4*)(vrow + i4 * 4);
            o[i4 * 4 + 0] = o[i4 * 4 + 0] * corr + p * v4.x;
            o[i4 * 4 + 1] = o[i4 * 4 + 1] * corr + p * v4.y;
            o[i4 * 4 + 2] = o[i4 * 4 + 2] * corr + p * v4.z;
            o[i4 * 4 + 3] = o[i4 * 4 + 3] * corr + p * v4.w;
        }
    }
    attn_store_split(Ohi, Olo, qrow * D_ + h * HD, o, 1.f / l);
}

// ---------------- host launcher --------------------------------------------------
extern "C" void kernel_launch(void* const* d_in, const int* in_sizes, int n_in,
                              void* d_out, int out_size)
{
    const float* hs = (const float*)d_in[0];
    const float* Wq = (const float*)d_in[1];
    const float* Wk = (const float*)d_in[2];
    const float* Wv = (const float*)d_in[3];
    const float* Wo = (const float*)d_in[4];
    const float* W1 = (const float*)d_in[5];
    const float* b1 = (const float*)d_in[6];
    const float* W2 = (const float*)d_in[7];
    const float* b2 = (const float*)d_in[8];
    float* out = (float*)d_out;

    float *comp_full, *Qb, *Kin, *Vin, *Kc, *Vc;
    __nv_bfloat16 *hsH, *hsL, *attH, *attL, *mlpH, *mlpL, *cmpH, *cmpL;
    __nv_bfloat16 *WqH, *WqL, *WkH, *WkL, *WvH, *WvL, *WoH, *WoL, *W1H, *W1L, *W2H, *W2L;
    cudaGetSymbolAddress((void**)&comp_full, g_comp_full);
    cudaGetSymbolAddress((void**)&Qb, g_Q);
    cudaGetSymbolAddress((void**)&Kin, g_Kinit);
    cudaGetSymbolAddress((void**)&Vin, g_Vinit);
    cudaGetSymbolAddress((void**)&Kc, g_Kcomp);
    cudaGetSymbolAddress((void**)&Vc, g_Vcomp);
    cudaGetSymbolAddress((void**)&hsH, g_hs_hi);  cudaGetSymbolAddress((void**)&hsL, g_hs_lo);
    cudaGetSymbolAddress((void**)&attH, g_att_hi); cudaGetSymbolAddress((void**)&attL, g_att_lo);
    cudaGetSymbolAddress((void**)&mlpH, g_mlp_hi); cudaGetSymbolAddress((void**)&mlpL, g_mlp_lo);
    cudaGetSymbolAddress((void**)&cmpH, g_comp_hi); cudaGetSymbolAddress((void**)&cmpL, g_comp_lo);
    cudaGetSymbolAddress((void**)&WqH, g_Wq_hi); cudaGetSymbolAddress((void**)&WqL, g_Wq_lo);
    cudaGetSymbolAddress((void**)&WkH, g_Wk_hi); cudaGetSymbolAddress((void**)&WkL, g_Wk_lo);
    cudaGetSymbolAddress((void**)&WvH, g_Wv_hi); cudaGetSymbolAddress((void**)&WvL, g_Wv_lo);
    cudaGetSymbolAddress((void**)&WoH, g_Wo_hi); cudaGetSymbolAddress((void**)&WoL, g_Wo_lo);
    cudaGetSymbolAddress((void**)&W1H, g_W1_hi); cudaGetSymbolAddress((void**)&W1L, g_W1_lo);
    cudaGetSymbolAddress((void**)&W2H, g_W2_hi); cudaGetSymbolAddress((void**)&W2L, g_W2_lo);

    cudaFuncSetAttribute(hgemm<false, false, false>,
                         cudaFuncAttributeMaxDynamicSharedMemorySize, SMEM_TOTAL_GEMM);
    cudaFuncSetAttribute(hgemm<true, true, true>,
                         cudaFuncAttributeMaxDynamicSharedMemorySize, SMEM_TOTAL_GEMM);
    cudaFuncSetAttribute(hgemm<false, true, false>,
                         cudaFuncAttributeMaxDynamicSharedMemorySize, SMEM_TOTAL_GEMM);

    // 0) split operands
    {
        int n4 = (B_ * S_TOT * D_) / 4;
        split_f32<<<(n4 + 255) / 256, 256>>>(hs, hsH, hsL, n4);
        int w4 = (D_ * D_) / 4;
        split_f32<<<(w4 + 255) / 256, 256>>>(Wq, WqH, WqL, w4);
        split_f32<<<(w4 + 255) / 256, 256>>>(Wk, WkH, WkL, w4);
        split_f32<<<(w4 + 255) / 256, 256>>>(Wv, WvH, WvL, w4);
        split_f32<<<(w4 + 255) / 256, 256>>>(Wo, WoH, WoL, w4);
        int f4 = (D_ * DFF) / 4;
        split_f32<<<(f4 + 255) / 256, 256>>>(W1, W1H, W1L, f4);
        split_f32<<<(f4 + 255) / 256, 256>>>(W2, W2H, W2L, f4);
    }

    // 1) MLP on initial tokens (per batch; strided rows) -> split output
    for (int b = 0; b < B_; b++) {
        hgemm<true, true, true><<<dim3(DFF / 128, CTX / 128), 256, SMEM_TOTAL_GEMM>>>(
            hsH + (size_t)b * S_TOT * D_, hsL + (size_t)b * S_TOT * D_,
            W1H, W1L, b1, nullptr,
            mlpH + (size_t)b * CTX * DFF, mlpL + (size_t)b * CTX * DFF,
            CTX, DFF, D_);
    }
    for (int b = 0; b < B_; b++) {
        hgemm<false, true, false><<<dim3(D_ / 128, CTX / 128), 256, SMEM_TOTAL_GEMM>>>(
            mlpH + (size_t)b * CTX * DFF, mlpL + (size_t)b * CTX * DFF,
            W2H, W2L, b2, comp_full + (size_t)b * CTX * D_, nullptr, nullptr,
            CTX, D_, DFF);
    }

    // 2) pool -> split comp
    pool_mean_split<<<(B_ * POOL * D_) / 256, 256>>>(comp_full, cmpH, cmpL);

    // 3) Q for ALL tokens
    hgemm<false, false, false><<<dim3(D_ / 128, (B_ * S_TOT) / 128), 256, SMEM_TOTAL_GEMM>>>(
        hsH, hsL, WqH, WqL, nullptr, Qb, nullptr, nullptr, B_ * S_TOT, D_, D_);

    // 4) K,V
    for (int b = 0; b < B_; b++) {
        hgemm<false, false, false><<<dim3(D_ / 128, CTX / 128), 256, SMEM_TOTAL_GEMM>>>(
            hsH + (size_t)b * S_TOT * D_, hsL + (size_t)b * S_TOT * D_,
            WkH, WkL, nullptr, Kin + (size_t)b * CTX * D_, nullptr, nullptr,
            CTX, D_, D_);
        hgemm<false, false, false><<<dim3(D_ / 128, CTX / 128), 256, SMEM_TOTAL_GEMM>>>(
            hsH + (size_t)b * S_TOT * D_, hsL + (size_t)b * S_TOT * D_,
            WvH, WvL, nullptr, Vin + (size_t)b * CTX * D_, nullptr, nullptr,
            CTX, D_, D_);
    }
    hgemm<false, false, false><<<dim3(D_ / 128, (B_ * POOL) / 128), 256, SMEM_TOTAL_GEMM>>>(
        cmpH, cmpL, WkH, WkL, nullptr, Kc, nullptr, nullptr, B_ * POOL, D_, D_);
    hgemm<false, false, false><<<dim3(D_ / 128, (B_ * POOL) / 128), 256, SMEM_TOTAL_GEMM>>>(
        cmpH, cmpL, WvH, WvL, nullptr, Vc, nullptr, nullptr, B_ * POOL, D_, D_);

    // 5) attention -> split att
    cross_attn<<<dim3(REM / 128, NH, B_), 128>>>(Qb, Kc, Vc, attH, attL);
    causal_attn<<<dim3(CTX / 128, NH, B_), 128>>>(Qb, Kin, Vin, attH, attL);

    // 6) output projection into d_out
    hgemm<false, false, false><<<dim3(D_ / 128, (B_ * S_TOT) / 128), 256, SMEM_TOTAL_GEMM>>>(
        attH, attL, WoH, WoL, nullptr, out, nullptr, nullptr, B_ * S_TOT, D_, D_);

    (void)in_sizes; (void)n_in; (void)out_size;
}

// round 8
// speedup vs baseline: 1.3538x; 1.0272x over previous
#include <cuda_runtime.h>
#include <cuda_bf16.h>
#include <math.h>
#include <stdint.h>

#define B_    2
#define S_TOT 16384
#define D_    1024
#define CTX   1024
#define POOL  256
#define REM   15360
#define NH    16
#define HD    64
#define DFF   512

// ---------------- scratch (static device globals; no allocation) ----------------
__device__ float g_comp_full[B_ * CTX * D_];
__device__ float g_Q[(size_t)B_ * S_TOT * D_];
__device__ float g_Kinit[B_ * CTX * D_];
__device__ float g_Vinit[B_ * CTX * D_];
__device__ float g_Kcomp[B_ * POOL * D_];
__device__ float g_Vcomp[B_ * POOL * D_];

__device__ __nv_bfloat16 g_hs_hi[(size_t)B_ * S_TOT * D_];
__device__ __nv_bfloat16 g_hs_lo[(size_t)B_ * S_TOT * D_];
__device__ __nv_bfloat16 g_att_hi[(size_t)B_ * S_TOT * D_];
__device__ __nv_bfloat16 g_att_lo[(size_t)B_ * S_TOT * D_];
__device__ __nv_bfloat16 g_mlp_hi[B_ * CTX * DFF];
__device__ __nv_bfloat16 g_mlp_lo[B_ * CTX * DFF];
__device__ __nv_bfloat16 g_comp_hi[B_ * POOL * D_];
__device__ __nv_bfloat16 g_comp_lo[B_ * POOL * D_];
__device__ __nv_bfloat16 g_Wq_hi[D_ * D_], g_Wq_lo[D_ * D_];
__device__ __nv_bfloat16 g_Wk_hi[D_ * D_], g_Wk_lo[D_ * D_];
__device__ __nv_bfloat16 g_Wv_hi[D_ * D_], g_Wv_lo[D_ * D_];
__device__ __nv_bfloat16 g_Wo_hi[D_ * D_], g_Wo_lo[D_ * D_];
__device__ __nv_bfloat16 g_W1_hi[D_ * DFF], g_W1_lo[D_ * DFF];
__device__ __nv_bfloat16 g_W2_hi[DFF * D_], g_W2_lo[DFF * D_];

// ---------------- helpers --------------------------------------------------------
__device__ __forceinline__ uint32_t smem_u32(const void* p) {
    return (uint32_t)__cvta_generic_to_shared(p);
}
__device__ __forceinline__ void cpa16(uint32_t dst, const void* src) {
    asm volatile("cp.async.cg.shared.global [%0],[%1],16;" :: "r"(dst), "l"(src));
}
__device__ __forceinline__ void cp_commit() {
    asm volatile("cp.async.commit_group;");
}
template <int NG>
__device__ __forceinline__ void cp_wait() {
    asm volatile("cp.async.wait_group %0;" :: "n"(NG));
}
__device__ __forceinline__ void ldsm_x4(uint32_t& r0, uint32_t& r1,
                                        uint32_t& r2, uint32_t& r3, uint32_t a) {
    asm volatile("ldmatrix.sync.aligned.m8n8.x4.shared.b16 {%0,%1,%2,%3},[%4];"
                 : "=r"(r0), "=r"(r1), "=r"(r2), "=r"(r3) : "r"(a));
}
__device__ __forceinline__ void ldsm_x4t(uint32_t& r0, uint32_t& r1,
                                         uint32_t& r2, uint32_t& r3, uint32_t a) {
    asm volatile("ldmatrix.sync.aligned.m8n8.x4.trans.shared.b16 {%0,%1,%2,%3},[%4];"
                 : "=r"(r0), "=r"(r1), "=r"(r2), "=r"(r3) : "r"(a));
}
__device__ __forceinline__ void mma16816(float* c, const uint32_t* a,
                                         uint32_t b0, uint32_t b1) {
    asm volatile(
        "mma.sync.aligned.m16n8k16.row.col.f32.bf16.bf16.f32 "
        "{%0,%1,%2,%3},{%4,%5,%6,%7},{%8,%9},{%0,%1,%2,%3};"
        : "+f"(c[0]), "+f"(c[1]), "+f"(c[2]), "+f"(c[3])
        : "r"(a[0]), "r"(a[1]), "r"(a[2]), "r"(a[3]), "r"(b0), "r"(b1));
}
__device__ __forceinline__ void split1(float x, __nv_bfloat16& h, __nv_bfloat16& l) {
    h = __float2bfloat16(x);
    l = __float2bfloat16(x - __bfloat162float(h));
}

// ---------------- fp32 -> (hi, lo) bf16 split, vectorized ------------------------
__global__ void split_f32(const float* __restrict__ src,
                          __nv_bfloat16* __restrict__ hi,
                          __nv_bfloat16* __restrict__ lo, int n4)
{
    int i = blockIdx.x * blockDim.x + threadIdx.x;
    if (i >= n4) return;
    float4 v = ((const float4*)src)[i];
    __nv_bfloat16 h[4], l[4];
    split1(v.x, h[0], l[0]); split1(v.y, h[1], l[1]);
    split1(v.z, h[2], l[2]); split1(v.w, h[3], l[3]);
    ((uint2*)hi)[i] = *(uint2*)h;
    ((uint2*)lo)[i] = *(uint2*)l;
}

// ================= pipelined bf16-split tensor-core GEMM (512 thr) ===============
// C = Ah*Bh + Al*Bh + Ah*Bl ; BM=BN=128, BK=64, 3-stage cp.async pipeline,
// 512 threads = 16 warps (4m x 4n), warp tile 32x32.
#define BK      64
#define LDA_S   72      // bf16 elems per A smem row (64 + 8 pad)
#define LDB_S   136     // bf16 elems per B smem row (128 + 8 pad)
#define A_BYTES (128 * LDA_S * 2)   // 18432
#define B_BYTES (BK * LDB_S * 2)    // 17408
#define OFF_AL  A_BYTES
#define OFF_BH  (2 * A_BYTES)
#define OFF_BL  (2 * A_BYTES + B_BYTES)
#define STAGE_BYTES (2 * A_BYTES + 2 * B_BYTES)   // 71680
#define STAGES  3
#define SMEM_TOTAL_GEMM (STAGES * STAGE_BYTES)    // 215040

template <bool RELU, bool BIAS, bool OSPLIT>
__global__ __launch_bounds__(512) void hgemm512(
    const __nv_bfloat16* __restrict__ Ahi, const __nv_bfloat16* __restrict__ Alo,
    const __nv_bfloat16* __restrict__ Bhi, const __nv_bfloat16* __restrict__ Blo,
    const float* __restrict__ bias,
    float* __restrict__ C,
    __nv_bfloat16* __restrict__ Chi, __nv_bfloat16* __restrict__ Clo,
    int M, int N, int K)
{
    extern __shared__ char smem[];
    const uint32_t sm_base = smem_u32(smem);

    const int tid = threadIdx.x;
    const int lane = tid & 31;
    const int wid = tid >> 5;
    const int wm = (wid & 3) * 32;      // warp m offset
    const int wn = (wid >> 2) * 32;     // warp n offset
    const int bm = blockIdx.y * 128;
    const int bn = blockIdx.x * 128;

    // gmem->smem: A row=tid>>2, 32B at col (tid&3)*16; B row=tid>>3, 32B at (tid&7)*16
    const int a_row = tid >> 2, a_col = (tid & 3) * 16;
    const int b_row = tid >> 3, b_col = (tid & 7) * 16;
    const __nv_bfloat16* Agh = Ahi + (size_t)(bm + a_row) * K + a_col;
    const __nv_bfloat16* Agl = Alo + (size_t)(bm + a_row) * K + a_col;
    const __nv_bfloat16* Bgh = Bhi + (size_t)b_row * N + bn + b_col;
    const __nv_bfloat16* Bgl = Blo + (size_t)b_row * N + bn + b_col;
    const uint32_t a_dst = sm_base + a_row * (LDA_S * 2) + a_col * 2;
    const uint32_t b_dst = sm_base + b_row * (LDB_S * 2) + b_col * 2;

#define LOAD_STAGE(stg, k0)                                                    \
    {                                                                          \
        uint32_t sb = (stg) * STAGE_BYTES;                                     \
        const __nv_bfloat16* ah = Agh + (k0);                                  \
        const __nv_bfloat16* al = Agl + (k0);                                  \
        cpa16(a_dst + sb, ah);                 cpa16(a_dst + sb + 16, ah + 8); \
        cpa16(a_dst + sb + OFF_AL, al);        cpa16(a_dst + sb + OFF_AL + 16, al + 8); \
        const __nv_bfloat16* bh = Bgh + (size_t)(k0) * N;                      \
        const __nv_bfloat16* bl = Bgl + (size_t)(k0) * N;                      \
        cpa16(b_dst + sb + OFF_BH, bh);        cpa16(b_dst + sb + OFF_BH + 16, bh + 8); \
        cpa16(b_dst + sb + OFF_BL, bl);        cpa16(b_dst + sb + OFF_BL + 16, bl + 8); \
    }

    float acc[2][4][4];
#pragma unroll
    for (int i = 0; i < 2; i++)
#pragma unroll
        for (int j = 0; j < 4; j++)
#pragma unroll
            for (int r = 0; r < 4; r++) acc[i][j][r] = 0.f;

    const int ktiles = K / BK;

    // prologue: stages 0..1
#pragma unroll
    for (int s = 0; s < STAGES - 1; s++) {
        if (s < ktiles) LOAD_STAGE(s, s * BK);
        cp_commit();
    }

    const int a_r = lane & 15, a_c8 = (lane >> 4) * 8;
    const int b_r = lane & 15, b_c8 = (lane >> 4) * 8;

    for (int it = 0; it < ktiles; it++) {
        cp_wait<STAGES - 2>();
        __syncthreads();

        if (it + STAGES - 1 < ktiles) {
            int ns = (it + STAGES - 1) % STAGES;
            LOAD_STAGE(ns, (it + STAGES - 1) * BK);
        }
        cp_commit();

        const uint32_t sb = sm_base + (it % STAGES) * STAGE_BYTES;
        const uint32_t ah_b = sb, al_b = sb + OFF_AL;
        const uint32_t bh_b = sb + OFF_BH, bl_b = sb + OFF_BL;

#pragma unroll
        for (int s = 0; s < 4; s++) {          // four k16 slices per BK=64
            const int ks = s * 16;
            uint32_t ah[2][4], al[2][4], bh[2][4], bl[2][4];
#pragma unroll
            for (int am = 0; am < 2; am++) {
                uint32_t addr = ah_b + ((wm + am * 16 + a_r) * LDA_S + ks + a_c8) * 2;
                ldsm_x4(ah[am][0], ah[am][1], ah[am][2], ah[am][3], addr);
            }
#pragma unroll
            for (int p = 0; p < 2; p++) {
                uint32_t addr = bh_b + ((ks + b_r) * LDB_S + wn + p * 16 + b_c8) * 2;
                ldsm_x4t(bh[p][0], bh[p][1], bh[p][2], bh[p][3], addr);
            }
            // hi * hi
#pragma unroll
            for (int am = 0; am < 2; am++)
#pragma unroll
                for (int p = 0; p < 2; p++) {
                    mma16816(acc[am][p * 2 + 0], ah[am], bh[p][0], bh[p][1]);
                    mma16816(acc[am][p * 2 + 1], ah[am], bh[p][2], bh[p][3]);
                }
            // lo * hi
#pragma unroll
            for (int am = 0; am < 2; am++) {
                uint32_t addr = al_b + ((wm + am * 16 + a_r) * LDA_S + ks + a_c8) * 2;
                ldsm_x4(al[am][0], al[am][1], al[am][2], al[am][3], addr);
            }
#pragma unroll
            for (int am = 0; am < 2; am++)
#pragma unroll
                for (int p = 0; p < 2; p++) {
                    mma16816(acc[am][p * 2 + 0], al[am], bh[p][0], bh[p][1]);
                    mma16816(acc[am][p * 2 + 1], al[am], bh[p][2], bh[p][3]);
                }
            // hi * lo
#pragma unroll
            for (int p = 0; p < 2; p++) {
                uint32_t addr = bl_b + ((ks + b_r) * LDB_S + wn + p * 16 + b_c8) * 2;
                ldsm_x4t(bl[p][0], bl[p][1], bl[p][2], bl[p][3], addr);
            }
#pragma unroll
            for (int am = 0; am < 2; am++)
#pragma unroll
                for (int p = 0; p < 2; p++) {
                    mma16816(acc[am][p * 2 + 0], ah[am], bl[p][0], bl[p][1]);
                    mma16816(acc[am][p * 2 + 1], ah[am], bl[p][2], bl[p][3]);
                }
        }
        __syncthreads();
    }

    // epilogue (validated mapping)
#pragma unroll
    for (int am = 0; am < 2; am++) {
        const int r0 = bm + wm + am * 16 + (lane >> 2);
#pragma unroll
        for (int an = 0; an < 4; an++) {
            const int c = bn + wn + an * 8 + (lane & 3) * 2;
            float v0 = acc[am][an][0], v1 = acc[am][an][1];
            float v2 = acc[am][an][2], v3 = acc[am][an][3];
            if (BIAS) {
                float bb0 = bias[c], bb1 = bias[c + 1];
                v0 += bb0; v1 += bb1; v2 += bb0; v3 += bb1;
            }
            if (RELU) {
                v0 = fmaxf(v0, 0.f); v1 = fmaxf(v1, 0.f);
                v2 = fmaxf(v2, 0.f); v3 = fmaxf(v3, 0.f);
            }
            if (OSPLIT) {
                __nv_bfloat16 h0, l0, h1, l1;
                size_t i0 = (size_t)r0 * N + c, i1 = (size_t)(r0 + 8) * N + c;
                split1(v0, h0, l0); split1(v1, h1, l1);
                __nv_bfloat162 hh; hh.x = h0; hh.y = h1;
                __nv_bfloat162 ll; ll.x = l0; ll.y = l1;
                *(__nv_bfloat162*)(Chi + i0) = hh;
                *(__nv_bfloat162*)(Clo + i0) = ll;
                split1(v2, h0, l0); split1(v3, h1, l1);
                hh.x = h0; hh.y = h1; ll.x = l0; ll.y = l1;
                *(__nv_bfloat162*)(Chi + i1) = hh;
                *(__nv_bfloat162*)(Clo + i1) = ll;
            } else {
                float* p0 = C + (size_t)r0 * N + c;
                float* p1 = C + (size_t)(r0 + 8) * N + c;
                p0[0] = v0; p0[1] = v1;
                p1[0] = v2; p1[1] = v3;
            }
        }
    }
#undef LOAD_STAGE
}

// ---------------- pooling: mean over groups of 4 rows -> split bf16 --------------
__global__ void pool_mean_split(const float* __restrict__ full,
                                __nv_bfloat16* __restrict__ hi,
                                __nv_bfloat16* __restrict__ lo)
{
    int idx = blockIdx.x * blockDim.x + threadIdx.x;
    int d = idx % D_;
    int p = (idx / D_) % POOL;
    int b = idx / (D_ * POOL);
    const float* src = full + ((size_t)b * CTX + p * 4) * D_ + d;
    float v = 0.25f * (src[0] + src[D_] + src[2 * D_] + src[3 * D_]);
    __nv_bfloat16 h, l;
    split1(v, h, l);
    hi[idx] = h; lo[idx] = l;
}

// ---------------- attention (fp32 math, bf16-split output) -----------------------
__device__ __forceinline__ void attn_store_split(
    __nv_bfloat16* __restrict__ hi, __nv_bfloat16* __restrict__ lo,
    size_t base, const float* o, float inv)
{
#pragma unroll
    for (int i = 0; i < HD; i += 4) {
        __nv_bfloat16 h[4], l[4];
#pragma unroll
        for (int j = 0; j < 4; j++) split1(o[i + j] * inv, h[j], l[j]);
        *(uint2*)(hi + base + i) = *(uint2*)h;
        *(uint2*)(lo + base + i) = *(uint2*)l;
    }
}

__global__ __launch_bounds__(128) void cross_attn(
    const float* __restrict__ Q, const float* __restrict__ K,
    const float* __restrict__ V,
    __nv_bfloat16* __restrict__ Ohi, __nv_bfloat16* __restrict__ Olo)
{
    const int b = blockIdx.z, h = blockIdx.y;
    const int r = blockIdx.x * 128 + threadIdx.x;
    const size_t qrow = (size_t)b * S_TOT + CTX + r;

    const float* q = Q + qrow * D_ + h * HD;
    float qv[HD];
#pragma unroll
    for (int i = 0; i < HD; i += 4) {
        float4 t = *(const float4*)(q + i);
        qv[i] = t.x; qv[i + 1] = t.y; qv[i + 2] = t.z; qv[i + 3] = t.w;
    }

    const float* Kb = K + (size_t)b * POOL * D_ + h * HD;
    const float* Vb = V + (size_t)b * POOL * D_ + h * HD;

    float m = -1e30f, l = 0.f;
    float o[HD];
#pragma unroll
    for (int i = 0; i < HD; i++) o[i] = 0.f;

    for (int j = 0; j < POOL; j++) {
        const float* krow = Kb + (size_t)j * D_;
        float s0 = 0.f, s1 = 0.f, s2 = 0.f, s3 = 0.f;
#pragma unroll
        for (int i4 = 0; i4 < 16; i4++) {
            float4 k4 = *(const float4*)(krow + i4 * 4);
            s0 = fmaf(qv[i4 * 4 + 0], k4.x, s0);
            s1 = fmaf(qv[i4 * 4 + 1], k4.y, s1);
            s2 = fmaf(qv[i4 * 4 + 2], k4.z, s2);
            s3 = fmaf(qv[i4 * 4 + 3], k4.w, s3);
        }
        float s = ((s0 + s1) + (s2 + s3)) * 0.125f;

        float mn = fmaxf(m, s);
        float corr = __expf(m - mn);
        float p = __expf(s - mn);
        l = l * corr + p;
        m = mn;

        const float* vrow = Vb + (size_t)j * D_;
#pragma unroll
        for (int i4 = 0; i4 < 16; i4++) {
            float4 v4 = *(const float4*)(vrow + i4 * 4);
            o[i4 * 4 + 0] = o[i4 * 4 + 0] * corr + p * v4.x;
            o[i4 * 4 + 1] = o[i4 * 4 + 1] * corr + p * v4.y;
            o[i4 * 4 + 2] = o[i4 * 4 + 2] * corr + p * v4.z;
            o[i4 * 4 + 3] = o[i4 * 4 + 3] * corr + p * v4.w;
        }
    }
    attn_store_split(Ohi, Olo, qrow * D_ + h * HD, o, 1.f / l);
}

__global__ __launch_bounds__(128) void causal_attn(
    const float* __restrict__ Q, const float* __restrict__ K,
    const float* __restrict__ V,
    __nv_bfloat16* __restrict__ Ohi, __nv_bfloat16* __restrict__ Olo)
{
    const int b = blockIdx.z, h = blockIdx.y;
    const int qp = blockIdx.x * 128 + threadIdx.x;
    const size_t qrow = (size_t)b * S_TOT + qp;

    const float* q = Q + qrow * D_ + h * HD;
    float qv[HD];
#pragma unroll
    for (int i = 0; i < HD; i += 4) {
        float4 t = *(const float4*)(q + i);
        qv[i] = t.x; qv[i + 1] = t.y; qv[i + 2] = t.z; qv[i + 3] = t.w;
    }

    const float* Kb = K + (size_t)b * CTX * D_ + h * HD;
    const float* Vb = V + (size_t)b * CTX * D_ + h * HD;

    float m = -1e30f, l = 0.f;
    float o[HD];
#pragma unroll
    for (int i = 0; i < HD; i++) o[i] = 0.f;

    for (int j = 0; j <= qp; j++) {
        const float* krow = Kb + (size_t)j * D_;
        float s0 = 0.f, s1 = 0.f, s2 = 0.f, s3 = 0.f;
#pragma unroll
        for (int i4 = 0; i4 < 16; i4++) {
            float4 k4 = *(const float4*)(krow + i4 * 4);
            s0 = fmaf(qv[i4 * 4 + 0], k4.x, s0);
            s1 = fmaf(qv[i4 * 4 + 1], k4.y, s1);
            s2 = fmaf(qv[i4 * 4 + 2], k4.z, s2);
            s3 = fmaf(qv[i4 * 4 + 3], k4.w, s3);
        }
        float s = ((s0 + s1) + (s2 + s3)) * 0.125f;

        float mn = fmaxf(m, s);
        float corr = __expf(m - mn);
        float p = __expf(s - mn);
        l = l * corr + p;
        m = mn;

        const float* vrow = Vb + (size_t)j * D_;
#pragma unroll
        for (int i4 = 0; i4 < 16; i4++) {
            float4 v4 = *(const float4*)(vrow + i4 * 4);
            o[i4 * 4 + 0] = o[i4 * 4 + 0] * corr + p * v4.x;
            o[i4 * 4 + 1] = o[i4 * 4 + 1] * corr + p * v4.y;
            o[i4 * 4 + 2] = o[i4 * 4 + 2] * corr + p * v4.z;
            o[i4 * 4 + 3] = o[i4 * 4 + 3] * corr + p * v4.w;
        }
    }
    attn_store_split(Ohi, Olo, qrow * D_ + h * HD, o, 1.f / l);
}

// ---------------- host launcher --------------------------------------------------
extern "C" void kernel_launch(void* const* d_in, const int* in_sizes, int n_in,
                              void* d_out, int out_size)
{
    const float* hs = (const float*)d_in[0];
    const float* Wq = (const float*)d_in[1];
    const float* Wk = (const float*)d_in[2];
    const float* Wv = (const float*)d_in[3];
    const float* Wo = (const float*)d_in[4];
    const float* W1 = (const float*)d_in[5];
    const float* b1 = (const float*)d_in[6];
    const float* W2 = (const float*)d_in[7];
    const float* b2 = (const float*)d_in[8];
    float* out = (float*)d_out;

    float *comp_full, *Qb, *Kin, *Vin, *Kc, *Vc;
    __nv_bfloat16 *hsH, *hsL, *attH, *attL, *mlpH, *mlpL, *cmpH, *cmpL;
    __nv_bfloat16 *WqH, *WqL, *WkH, *WkL, *WvH, *WvL, *WoH, *WoL, *W1H, *W1L, *W2H, *W2L;
    cudaGetSymbolAddress((void**)&comp_full, g_comp_full);
    cudaGetSymbolAddress((void**)&Qb, g_Q);
    cudaGetSymbolAddress((void**)&Kin, g_Kinit);
    cudaGetSymbolAddress((void**)&Vin, g_Vinit);
    cudaGetSymbolAddress((void**)&Kc, g_Kcomp);
    cudaGetSymbolAddress((void**)&Vc, g_Vcomp);
    cudaGetSymbolAddress((void**)&hsH, g_hs_hi);   cudaGetSymbolAddress((void**)&hsL, g_hs_lo);
    cudaGetSymbolAddress((void**)&attH, g_att_hi); cudaGetSymbolAddress((void**)&attL, g_att_lo);
    cudaGetSymbolAddress((void**)&mlpH, g_mlp_hi); cudaGetSymbolAddress((void**)&mlpL, g_mlp_lo);
    cudaGetSymbolAddress((void**)&cmpH, g_comp_hi); cudaGetSymbolAddress((void**)&cmpL, g_comp_lo);
    cudaGetSymbolAddress((void**)&WqH, g_Wq_hi); cudaGetSymbolAddress((void**)&WqL, g_Wq_lo);
    cudaGetSymbolAddress((void**)&WkH, g_Wk_hi); cudaGetSymbolAddress((void**)&WkL, g_Wk_lo);
    cudaGetSymbolAddress((void**)&WvH, g_Wv_hi); cudaGetSymbolAddress((void**)&WvL, g_Wv_lo);
    cudaGetSymbolAddress((void**)&WoH, g_Wo_hi); cudaGetSymbolAddress((void**)&WoL, g_Wo_lo);
    cudaGetSymbolAddress((void**)&W1H, g_W1_hi); cudaGetSymbolAddress((void**)&W1L, g_W1_lo);
    cudaGetSymbolAddress((void**)&W2H, g_W2_hi); cudaGetSymbolAddress((void**)&W2L, g_W2_lo);

    cudaFuncSetAttribute(hgemm512<false, false, false>,
                         cudaFuncAttributeMaxDynamicSharedMemorySize, SMEM_TOTAL_GEMM);
    cudaFuncSetAttribute(hgemm512<true, true, true>,
                         cudaFuncAttributeMaxDynamicSharedMemorySize, SMEM_TOTAL_GEMM);
    cudaFuncSetAttribute(hgemm512<false, true, false>,
                         cudaFuncAttributeMaxDynamicSharedMemorySize, SMEM_TOTAL_GEMM);

    // 0) split operands
    {
        int n4 = (B_ * S_TOT * D_) / 4;
        split_f32<<<(n4 + 255) / 256, 256>>>(hs, hsH, hsL, n4);
        int w4 = (D_ * D_) / 4;
        split_f32<<<(w4 + 255) / 256, 256>>>(Wq, WqH, WqL, w4);
        split_f32<<<(w4 + 255) / 256, 256>>>(Wk, WkH, WkL, w4);
        split_f32<<<(w4 + 255) / 256, 256>>>(Wv, WvH, WvL, w4);
        split_f32<<<(w4 + 255) / 256, 256>>>(Wo, WoH, WoL, w4);
        int f4 = (D_ * DFF) / 4;
        split_f32<<<(f4 + 255) / 256, 256>>>(W1, W1H, W1L, f4);
        split_f32<<<(f4 + 255) / 256, 256>>>(W2, W2H, W2L, f4);
    }

    // 1) MLP on initial tokens (per batch) -> split output
    for (int b = 0; b < B_; b++) {
        hgemm512<true, true, true><<<dim3(DFF / 128, CTX / 128), 512, SMEM_TOTAL_GEMM>>>(
            hsH + (size_t)b * S_TOT * D_, hsL + (size_t)b * S_TOT * D_,
            W1H, W1L, b1, nullptr,
            mlpH + (size_t)b * CTX * DFF, mlpL + (size_t)b * CTX * DFF,
            CTX, DFF, D_);
    }
    for (int b = 0; b < B_; b++) {
        hgemm512<false, true, false><<<dim3(D_ / 128, CTX / 128), 512, SMEM_TOTAL_GEMM>>>(
            mlpH + (size_t)b * CTX * DFF, mlpL + (size_t)b * CTX * DFF,
            W2H, W2L, b2, comp_full + (size_t)b * CTX * D_, nullptr, nullptr,
            CTX, D_, DFF);
    }

    // 2) pool -> split comp
    pool_mean_split<<<(B_ * POOL * D_) / 256, 256>>>(comp_full, cmpH, cmpL);

    // 3) Q for ALL tokens
    hgemm512<false, false, false><<<dim3(D_ / 128, (B_ * S_TOT) / 128), 512, SMEM_TOTAL_GEMM>>>(
        hsH, hsL, WqH, WqL, nullptr, Qb, nullptr, nullptr, B_ * S_TOT, D_, D_);

    // 4) K,V
    for (int b = 0; b < B_; b++) {
        hgemm512<false, false, false><<<dim3(D_ / 128, CTX / 128), 512, SMEM_TOTAL_GEMM>>>(
            hsH + (size_t)b * S_TOT * D_, hsL + (size_t)b * S_TOT * D_,
            WkH, WkL, nullptr, Kin + (size_t)b * CTX * D_, nullptr, nullptr,
            CTX, D_, D_);
        hgemm512<false, false, false><<<dim3(D_ / 128, CTX / 128), 512, SMEM_TOTAL_GEMM>>>(
            hsH + (size_t)b * S_TOT * D_, hsL + (size_t)b * S_TOT * D_,
            WvH, WvL, nullptr, Vin + (size_t)b * CTX * D_, nullptr, nullptr,
            CTX, D_, D_);
    }
    hgemm512<false, false, false><<<dim3(D_ / 128, (B_ * POOL) / 128), 512, SMEM_TOTAL_GEMM>>>(
        cmpH, cmpL, WkH, WkL, nullptr, Kc, nullptr, nullptr, B_ * POOL, D_, D_);
    hgemm512<false, false, false><<<dim3(D_ / 128, (B_ * POOL) / 128), 512, SMEM_TOTAL_GEMM>>>(
        cmpH, cmpL, WvH, WvL, nullptr, Vc, nullptr, nullptr, B_ * POOL, D_, D_);

    // 5) attention -> split att
    cross_attn<<<dim3(REM / 128, NH, B_), 128>>>(Qb, Kc, Vc, attH, attL);
    causal_attn<<<dim3(CTX / 128, NH, B_), 128>>>(Qb, Kin, Vin, attH, attL);

    // 6) output projection into d_out
    hgemm512<false, false, false><<<dim3(D_ / 128, (B_ * S_TOT) / 128), 512, SMEM_TOTAL_GEMM>>>(
        attH, attL, WoH, WoL, nullptr, out, nullptr, nullptr, B_ * S_TOT, D_, D_);

    (void)in_sizes; (void)n_in; (void)out_size;
}

// round 9
// speedup vs baseline: 1.4378x; 1.0620x over previous
#include <cuda_runtime.h>
#include <cuda_fp16.h>
#include <math.h>
#include <stdint.h>

#define B_    2
#define S_TOT 16384
#define D_    1024
#define CTX   1024
#define POOL  256
#define REM   15360
#define NH    16
#define HD    64
#define DFF   512

// ---------------- scratch (static device globals; no allocation) ----------------
__device__ float g_comp_full[B_ * CTX * D_];
__device__ float g_Q[(size_t)B_ * S_TOT * D_];
__device__ float g_Kinit[B_ * CTX * D_];
__device__ float g_Vinit[B_ * CTX * D_];
__device__ float g_Kcomp[B_ * POOL * D_];
__device__ float g_Vcomp[B_ * POOL * D_];

// fp16 split A-operands (hi exact-residual lo); weights single fp16
__device__ __half g_hs_hi[(size_t)B_ * S_TOT * D_];
__device__ __half g_hs_lo[(size_t)B_ * S_TOT * D_];
__device__ __half g_att_hi[(size_t)B_ * S_TOT * D_];
__device__ __half g_att_lo[(size_t)B_ * S_TOT * D_];
__device__ __half g_mlp_hi[B_ * CTX * DFF];
__device__ __half g_mlp_lo[B_ * CTX * DFF];
__device__ __half g_comp_hi[B_ * POOL * D_];
__device__ __half g_comp_lo[B_ * POOL * D_];
__device__ __half g_Wq_h[D_ * D_];
__device__ __half g_Wk_h[D_ * D_];
__device__ __half g_Wv_h[D_ * D_];
__device__ __half g_Wo_h[D_ * D_];
__device__ __half g_W1_h[D_ * DFF];
__device__ __half g_W2_h[DFF * D_];

// ---------------- helpers --------------------------------------------------------
__device__ __forceinline__ uint32_t smem_u32(const void* p) {
    return (uint32_t)__cvta_generic_to_shared(p);
}
__device__ __forceinline__ void cpa16(uint32_t dst, const void* src) {
    asm volatile("cp.async.cg.shared.global [%0],[%1],16;" :: "r"(dst), "l"(src));
}
__device__ __forceinline__ void cp_commit() {
    asm volatile("cp.async.commit_group;");
}
template <int NG>
__device__ __forceinline__ void cp_wait() {
    asm volatile("cp.async.wait_group %0;" :: "n"(NG));
}
__device__ __forceinline__ void ldsm_x4(uint32_t& r0, uint32_t& r1,
                                        uint32_t& r2, uint32_t& r3, uint32_t a) {
    asm volatile("ldmatrix.sync.aligned.m8n8.x4.shared.b16 {%0,%1,%2,%3},[%4];"
                 : "=r"(r0), "=r"(r1), "=r"(r2), "=r"(r3) : "r"(a));
}
__device__ __forceinline__ void ldsm_x4t(uint32_t& r0, uint32_t& r1,
                                         uint32_t& r2, uint32_t& r3, uint32_t a) {
    asm volatile("ldmatrix.sync.aligned.m8n8.x4.trans.shared.b16 {%0,%1,%2,%3},[%4];"
                 : "=r"(r0), "=r"(r1), "=r"(r2), "=r"(r3) : "r"(a));
}
__device__ __forceinline__ void mma16816h(float* c, const uint32_t* a,
                                          uint32_t b0, uint32_t b1) {
    asm volatile(
        "mma.sync.aligned.m16n8k16.row.col.f32.f16.f16.f32 "
        "{%0,%1,%2,%3},{%4,%5,%6,%7},{%8,%9},{%0,%1,%2,%3};"
        : "+f"(c[0]), "+f"(c[1]), "+f"(c[2]), "+f"(c[3])
        : "r"(a[0]), "r"(a[1]), "r"(a[2]), "r"(a[3]), "r"(b0), "r"(b1));
}
__device__ __forceinline__ void split1h(float x, __half& h, __half& l) {
    h = __float2half_rn(x);
    l = __float2half_rn(x - __half2float(h));
}

// ---------------- fp32 -> (hi, lo) fp16 split, vectorized ------------------------
__global__ void split_f16(const float* __restrict__ src,
                          __half* __restrict__ hi,
                          __half* __restrict__ lo, int n4)
{
    int i = blockIdx.x * blockDim.x + threadIdx.x;
    if (i >= n4) return;
    float4 v = ((const float4*)src)[i];
    __half h[4], l[4];
    split1h(v.x, h[0], l[0]); split1h(v.y, h[1], l[1]);
    split1h(v.z, h[2], l[2]); split1h(v.w, h[3], l[3]);
    ((uint2*)hi)[i] = *(uint2*)h;
    ((uint2*)lo)[i] = *(uint2*)l;
}

// ---------------- fp32 -> fp16 single (weights) ----------------------------------
__global__ void conv_f16(const float* __restrict__ src, __half* __restrict__ dst, int n4)
{
    int i = blockIdx.x * blockDim.x + threadIdx.x;
    if (i >= n4) return;
    float4 v = ((const float4*)src)[i];
    __half h[4];
    h[0] = __float2half_rn(v.x); h[1] = __float2half_rn(v.y);
    h[2] = __float2half_rn(v.z); h[3] = __float2half_rn(v.w);
    ((uint2*)dst)[i] = *(uint2*)h;
}

// ================= pipelined fp16 2-term tensor-core GEMM (512 thr) ==============
// C = (Ah + Al) @ B ; A exact in fp16 pair, B single fp16 (2^-12 rounding).
// BM=BN=128, BK=64, 4-stage cp.async pipeline, 16 warps (4m x 4n), warp 32x32.
#define BK      64
#define LDA_S   72      // fp16 elems per A smem row (64 + 8 pad)
#define LDB_S   136     // fp16 elems per B smem row (128 + 8 pad)
#define A_BYTES (128 * LDA_S * 2)   // 18432
#define B_BYTES (BK * LDB_S * 2)    // 17408
#define OFF_AL  A_BYTES
#define OFF_B   (2 * A_BYTES)
#define STAGE_BYTES (2 * A_BYTES + B_BYTES)       // 54272
#define STAGES  4
#define SMEM_TOTAL_GEMM (STAGES * STAGE_BYTES)    // 217088

template <bool RELU, bool BIAS, bool OSPLIT>
__global__ __launch_bounds__(512) void hgemm512(
    const __half* __restrict__ Ahi, const __half* __restrict__ Alo,
    const __half* __restrict__ Bh,
    const float* __restrict__ bias,
    float* __restrict__ C,
    __half* __restrict__ Chi, __half* __restrict__ Clo,
    int M, int N, int K)
{
    extern __shared__ char smem[];
    const uint32_t sm_base = smem_u32(smem);

    const int tid = threadIdx.x;
    const int lane = tid & 31;
    const int wid = tid >> 5;
    const int wm = (wid & 3) * 32;
    const int wn = (wid >> 2) * 32;
    const int bm = blockIdx.y * 128;
    const int bn = blockIdx.x * 128;

    const int a_row = tid >> 2, a_col = (tid & 3) * 16;
    const int b_row = tid >> 3, b_col = (tid & 7) * 16;
    const __half* Agh = Ahi + (size_t)(bm + a_row) * K + a_col;
    const __half* Agl = Alo + (size_t)(bm + a_row) * K + a_col;
    const __half* Bg = Bh + (size_t)b_row * N + bn + b_col;
    const uint32_t a_dst = sm_base + a_row * (LDA_S * 2) + a_col * 2;
    const uint32_t b_dst = sm_base + b_row * (LDB_S * 2) + b_col * 2;

#define LOAD_STAGE(stg, k0)                                                    \
    {                                                                          \
        uint32_t sb = (stg) * STAGE_BYTES;                                     \
        const __half* ah = Agh + (k0);                                         \
        const __half* al = Agl + (k0);                                         \
        cpa16(a_dst + sb, ah);                 cpa16(a_dst + sb + 16, ah + 8); \
        cpa16(a_dst + sb + OFF_AL, al);        cpa16(a_dst + sb + OFF_AL + 16, al + 8); \
        const __half* bp = Bg + (size_t)(k0) * N;                              \
        cpa16(b_dst + sb + OFF_B, bp);         cpa16(b_dst + sb + OFF_B + 16, bp + 8); \
    }

    float acc[2][4][4];
#pragma unroll
    for (int i = 0; i < 2; i++)
#pragma unroll
        for (int j = 0; j < 4; j++)
#pragma unroll
            for (int r = 0; r < 4; r++) acc[i][j][r] = 0.f;

    const int ktiles = K / BK;

#pragma unroll
    for (int s = 0; s < STAGES - 1; s++) {
        if (s < ktiles) LOAD_STAGE(s, s * BK);
        cp_commit();
    }

    const int a_r = lane & 15, a_c8 = (lane >> 4) * 8;
    const int b_r = lane & 15, b_c8 = (lane >> 4) * 8;

    for (int it = 0; it < ktiles; it++) {
        cp_wait<STAGES - 2>();
        __syncthreads();

        if (it + STAGES - 1 < ktiles) {
            int ns = (it + STAGES - 1) % STAGES;
            LOAD_STAGE(ns, (it + STAGES - 1) * BK);
        }
        cp_commit();

        const uint32_t sb = sm_base + (it % STAGES) * STAGE_BYTES;
        const uint32_t ah_b = sb, al_b = sb + OFF_AL, bh_b = sb + OFF_B;

#pragma unroll
        for (int s = 0; s < 4; s++) {          // four k16 slices per BK=64
            const int ks = s * 16;
            uint32_t ah[2][4], al[2][4], bb[2][4];
#pragma unroll
            for (int am = 0; am < 2; am++) {
                uint32_t addr = ah_b + ((wm + am * 16 + a_r) * LDA_S + ks + a_c8) * 2;
                ldsm_x4(ah[am][0], ah[am][1], ah[am][2], ah[am][3], addr);
            }
#pragma unroll
            for (int p = 0; p < 2; p++) {
                uint32_t addr = bh_b + ((ks + b_r) * LDB_S + wn + p * 16 + b_c8) * 2;
                ldsm_x4t(bb[p][0], bb[p][1], bb[p][2], bb[p][3], addr);
            }
            // hi term
#pragma unroll
            for (int am = 0; am < 2; am++)
#pragma unroll
                for (int p = 0; p < 2; p++) {
                    mma16816h(acc[am][p * 2 + 0], ah[am], bb[p][0], bb[p][1]);
                    mma16816h(acc[am][p * 2 + 1], ah[am], bb[p][2], bb[p][3]);
                }
            // lo term
#pragma unroll
            for (int am = 0; am < 2; am++) {
                uint32_t addr = al_b + ((wm + am * 16 + a_r) * LDA_S + ks + a_c8) * 2;
                ldsm_x4(al[am][0], al[am][1], al[am][2], al[am][3], addr);
            }
#pragma unroll
            for (int am = 0; am < 2; am++)
#pragma unroll
                for (int p = 0; p < 2; p++) {
                    mma16816h(acc[am][p * 2 + 0], al[am], bb[p][0], bb[p][1]);
                    mma16816h(acc[am][p * 2 + 1], al[am], bb[p][2], bb[p][3]);
                }
        }
        __syncthreads();
    }

    // epilogue (validated mapping)
#pragma unroll
    for (int am = 0; am < 2; am++) {
        const int r0 = bm + wm + am * 16 + (lane >> 2);
#pragma unroll
        for (int an = 0; an < 4; an++) {
            const int c = bn + wn + an * 8 + (lane & 3) * 2;
            float v0 = acc[am][an][0], v1 = acc[am][an][1];
            float v2 = acc[am][an][2], v3 = acc[am][an][3];
            if (BIAS) {
                float bb0 = bias[c], bb1 = bias[c + 1];
                v0 += bb0; v1 += bb1; v2 += bb0; v3 += bb1;
            }
            if (RELU) {
                v0 = fmaxf(v0, 0.f); v1 = fmaxf(v1, 0.f);
                v2 = fmaxf(v2, 0.f); v3 = fmaxf(v3, 0.f);
            }
            if (OSPLIT) {
                __half h0, l0, h1, l1;
                size_t i0 = (size_t)r0 * N + c, i1 = (size_t)(r0 + 8) * N + c;
                split1h(v0, h0, l0); split1h(v1, h1, l1);
                __half2 hh; hh.x = h0; hh.y = h1;
                __half2 ll; ll.x = l0; ll.y = l1;
                *(__half2*)(Chi + i0) = hh;
                *(__half2*)(Clo + i0) = ll;
                split1h(v2, h0, l0); split1h(v3, h1, l1);
                hh.x = h0; hh.y = h1; ll.x = l0; ll.y = l1;
                *(__half2*)(Chi + i1) = hh;
                *(__half2*)(Clo + i1) = ll;
            } else {
                float* p0 = C + (size_t)r0 * N + c;
                float* p1 = C + (size_t)(r0 + 8) * N + c;
                p0[0] = v0; p0[1] = v1;
                p1[0] = v2; p1[1] = v3;
            }
        }
    }
#undef LOAD_STAGE
}

// ---------------- pooling: mean over groups of 4 rows -> split fp16 --------------
__global__ void pool_mean_split(const float* __restrict__ full,
                                __half* __restrict__ hi,
                                __half* __restrict__ lo)
{
    int idx = blockIdx.x * blockDim.x + threadIdx.x;
    int d = idx % D_;
    int p = (idx / D_) % POOL;
    int b = idx / (D_ * POOL);
    const float* src = full + ((size_t)b * CTX + p * 4) * D_ + d;
    float v = 0.25f * (src[0] + src[D_] + src[2 * D_] + src[3 * D_]);
    __half h, l;
    split1h(v, h, l);
    hi[idx] = h; lo[idx] = l;
}

// ---------------- attention (fp32 math, fp16-split output) -----------------------
__device__ __forceinline__ void attn_store_split(
    __half* __restrict__ hi, __half* __restrict__ lo,
    size_t base, const float* o, float inv)
{
#pragma unroll
    for (int i = 0; i < HD; i += 4) {
        __half h[4], l[4];
#pragma unroll
        for (int j = 0; j < 4; j++) split1h(o[i + j] * inv, h[j], l[j]);
        *(uint2*)(hi + base + i) = *(uint2*)h;
        *(uint2*)(lo + base + i) = *(uint2*)l;
    }
}

__global__ __launch_bounds__(128) void cross_attn(
    const float* __restrict__ Q, const float* __restrict__ K,
    const float* __restrict__ V,
    __half* __restrict__ Ohi, __half* __restrict__ Olo)
{
    const int b = blockIdx.z, h = blockIdx.y;
    const int r = blockIdx.x * 128 + threadIdx.x;
    const size_t qrow = (size_t)b * S_TOT + CTX + r;

    const float* q = Q + qrow * D_ + h * HD;
    float qv[HD];
#pragma unroll
    for (int i = 0; i < HD; i += 4) {
        float4 t = *(const float4*)(q + i);
        qv[i] = t.x; qv[i + 1] = t.y; qv[i + 2] = t.z; qv[i + 3] = t.w;
    }

    const float* Kb = K + (size_t)b * POOL * D_ + h * HD;
    const float* Vb = V + (size_t)b * POOL * D_ + h * HD;

    float m = -1e30f, l = 0.f;
    float o[HD];
#pragma unroll
    for (int i = 0; i < HD; i++) o[i] = 0.f;

    for (int j = 0; j < POOL; j++) {
        const float* krow = Kb + (size_t)j * D_;
        float s0 = 0.f, s1 = 0.f, s2 = 0.f, s3 = 0.f;
#pragma unroll
        for (int i4 = 0; i4 < 16; i4++) {
            float4 k4 = *(const float4*)(krow + i4 * 4);
            s0 = fmaf(qv[i4 * 4 + 0], k4.x, s0);
            s1 = fmaf(qv[i4 * 4 + 1], k4.y, s1);
            s2 = fmaf(qv[i4 * 4 + 2], k4.z, s2);
            s3 = fmaf(qv[i4 * 4 + 3], k4.w, s3);
        }
        float s = ((s0 + s1) + (s2 + s3)) * 0.125f;

        float mn = fmaxf(m, s);
        float corr = __expf(m - mn);
        float p = __expf(s - mn);
        l = l * corr + p;
        m = mn;

        const float* vrow = Vb + (size_t)j * D_;
#pragma unroll
        for (int i4 = 0; i4 < 16; i4++) {
            float4 v4 = *(const float4*)(vrow + i4 * 4);
            o[i4 * 4 + 0] = o[i4 * 4 + 0] * corr + p * v4.x;
            o[i4 * 4 + 1] = o[i4 * 4 + 1] * corr + p * v4.y;
            o[i4 * 4 + 2] = o[i4 * 4 + 2] * corr + p * v4.z;
            o[i4 * 4 + 3] = o[i4 * 4 + 3] * corr + p * v4.w;
        }
    }
    attn_store_split(Ohi, Olo, qrow * D_ + h * HD, o, 1.f / l);
}

__global__ __launch_bounds__(128) void causal_attn(
    const float* __restrict__ Q, const float* __restrict__ K,
    const float* __restrict__ V,
    __half* __restrict__ Ohi, __half* __restrict__ Olo)
{
    const int b = blockIdx.z, h = blockIdx.y;
    const int qp = blockIdx.x * 128 + threadIdx.x;
    const size_t qrow = (size_t)b * S_TOT + qp;

    const float* q = Q + qrow * D_ + h * HD;
    float qv[HD];
#pragma unroll
    for (int i = 0; i < HD; i += 4) {
        float4 t = *(const float4*)(q + i);
        qv[i] = t.x; qv[i + 1] = t.y; qv[i + 2] = t.z; qv[i + 3] = t.w;
    }

    const float* Kb = K + (size_t)b * CTX * D_ + h * HD;
    const float* Vb = V + (size_t)b * CTX * D_ + h * HD;

    float m = -1e30f, l = 0.f;
    float o[HD];
#pragma unroll
    for (int i = 0; i < HD; i++) o[i] = 0.f;

    for (int j = 0; j <= qp; j++) {
        const float* krow = Kb + (size_t)j * D_;
        float s0 = 0.f, s1 = 0.f, s2 = 0.f, s3 = 0.f;
#pragma unroll
        for (int i4 = 0; i4 < 16; i4++) {
            float4 k4 = *(const float4*)(krow + i4 * 4);
            s0 = fmaf(qv[i4 * 4 + 0], k4.x, s0);
            s1 = fmaf(qv[i4 * 4 + 1], k4.y, s1);
            s2 = fmaf(qv[i4 * 4 + 2], k4.z, s2);
            s3 = fmaf(qv[i4 * 4 + 3], k4.w, s3);
        }
        float s = ((s0 + s1) + (s2 + s3)) * 0.125f;

        float mn = fmaxf(m, s);
        float corr = __expf(m - mn);
        float p = __expf(s - mn);
        l = l * corr + p;
        m = mn;

        const float* vrow = Vb + (size_t)j * D_;
#pragma unroll
        for (int i4 = 0; i4 < 16; i4++) {
            float4 v4 = *(const float4*)(vrow + i4 * 4);
            o[i4 * 4 + 0] = o[i4 * 4 + 0] * corr + p * v4.x;
            o[i4 * 4 + 1] = o[i4 * 4 + 1] * corr + p * v4.y;
            o[i4 * 4 + 2] = o[i4 * 4 + 2] * corr + p * v4.z;
            o[i4 * 4 + 3] = o[i4 * 4 + 3] * corr + p * v4.w;
        }
    }
    attn_store_split(Ohi, Olo, qrow * D_ + h * HD, o, 1.f / l);
}

// ---------------- host launcher --------------------------------------------------
extern "C" void kernel_launch(void* const* d_in, const int* in_sizes, int n_in,
                              void* d_out, int out_size)
{
    const float* hs = (const float*)d_in[0];
    const float* Wq = (const float*)d_in[1];
    const float* Wk = (const float*)d_in[2];
    const float* Wv = (const float*)d_in[3];
    const float* Wo = (const float*)d_in[4];
    const float* W1 = (const float*)d_in[5];
    const float* b1 = (const float*)d_in[6];
    const float* W2 = (const float*)d_in[7];
    const float* b2 = (const float*)d_in[8];
    float* out = (float*)d_out;

    float *comp_full, *Qb, *Kin, *Vin, *Kc, *Vc;
    __half *hsH, *hsL, *attH, *attL, *mlpH, *mlpL, *cmpH, *cmpL;
    __half *WqH, *WkH, *WvH, *WoH, *W1H, *W2H;
    cudaGetSymbolAddress((void**)&comp_full, g_comp_full);
    cudaGetSymbolAddress((void**)&Qb, g_Q);
    cudaGetSymbolAddress((void**)&Kin, g_Kinit);
    cudaGetSymbolAddress((void**)&Vin, g_Vinit);
    cudaGetSymbolAddress((void**)&Kc, g_Kcomp);
    cudaGetSymbolAddress((void**)&Vc, g_Vcomp);
    cudaGetSymbolAddress((void**)&hsH, g_hs_hi);   cudaGetSymbolAddress((void**)&hsL, g_hs_lo);
    cudaGetSymbolAddress((void**)&attH, g_att_hi); cudaGetSymbolAddress((void**)&attL, g_att_lo);
    cudaGetSymbolAddress((void**)&mlpH, g_mlp_hi); cudaGetSymbolAddress((void**)&mlpL, g_mlp_lo);
    cudaGetSymbolAddress((void**)&cmpH, g_comp_hi); cudaGetSymbolAddress((void**)&cmpL, g_comp_lo);
    cudaGetSymbolAddress((void**)&WqH, g_Wq_h);
    cudaGetSymbolAddress((void**)&WkH, g_Wk_h);
    cudaGetSymbolAddress((void**)&WvH, g_Wv_h);
    cudaGetSymbolAddress((void**)&WoH, g_Wo_h);
    cudaGetSymbolAddress((void**)&W1H, g_W1_h);
    cudaGetSymbolAddress((void**)&W2H, g_W2_h);

    cudaFuncSetAttribute(hgemm512<false, false, false>,
                         cudaFuncAttributeMaxDynamicSharedMemorySize, SMEM_TOTAL_GEMM);
    cudaFuncSetAttribute(hgemm512<true, true, true>,
                         cudaFuncAttributeMaxDynamicSharedMemorySize, SMEM_TOTAL_GEMM);
    cudaFuncSetAttribute(hgemm512<false, true, false>,
                         cudaFuncAttributeMaxDynamicSharedMemorySize, SMEM_TOTAL_GEMM);

    // 0) split activations (fp16 hi/lo), convert weights (fp16 single)
    {
        int n4 = (B_ * S_TOT * D_) / 4;
        split_f16<<<(n4 + 255) / 256, 256>>>(hs, hsH, hsL, n4);
        int w4 = (D_ * D_) / 4;
        conv_f16<<<(w4 + 255) / 256, 256>>>(Wq, WqH, w4);
        conv_f16<<<(w4 + 255) / 256, 256>>>(Wk, WkH, w4);
        conv_f16<<<(w4 + 255) / 256, 256>>>(Wv, WvH, w4);
        conv_f16<<<(w4 + 255) / 256, 256>>>(Wo, WoH, w4);
        int f4 = (D_ * DFF) / 4;
        conv_f16<<<(f4 + 255) / 256, 256>>>(W1, W1H, f4);
        conv_f16<<<(f4 + 255) / 256, 256>>>(W2, W2H, f4);
    }

    // 1) MLP on initial tokens (per batch) -> split output
    for (int b = 0; b < B_; b++) {
        hgemm512<true, true, true><<<dim3(DFF / 128, CTX / 128), 512, SMEM_TOTAL_GEMM>>>(
            hsH + (size_t)b * S_TOT * D_, hsL + (size_t)b * S_TOT * D_,
            W1H, b1, nullptr,
            mlpH + (size_t)b * CTX * DFF, mlpL + (size_t)b * CTX * DFF,
            CTX, DFF, D_);
    }
    for (int b = 0; b < B_; b++) {
        hgemm512<false, true, false><<<dim3(D_ / 128, CTX / 128), 512, SMEM_TOTAL_GEMM>>>(
            mlpH + (size_t)b * CTX * DFF, mlpL + (size_t)b * CTX * DFF,
            W2H, b2, comp_full + (size_t)b * CTX * D_, nullptr, nullptr,
            CTX, D_, DFF);
    }

    // 2) pool -> split comp
    pool_mean_split<<<(B_ * POOL * D_) / 256, 256>>>(comp_full, cmpH, cmpL);

    // 3) Q for ALL tokens
    hgemm512<false, false, false><<<dim3(D_ / 128, (B_ * S_TOT) / 128), 512, SMEM_TOTAL_GEMM>>>(
        hsH, hsL, WqH, nullptr, Qb, nullptr, nullptr, B_ * S_TOT, D_, D_);

    // 4) K,V
    for (int b = 0; b < B_; b++) {
        hgemm512<false, false, false><<<dim3(D_ / 128, CTX / 128), 512, SMEM_TOTAL_GEMM>>>(
            hsH + (size_t)b * S_TOT * D_, hsL + (size_t)b * S_TOT * D_,
            WkH, nullptr, Kin + (size_t)b * CTX * D_, nullptr, nullptr,
            CTX, D_, D_);
        hgemm512<false, false, false><<<dim3(D_ / 128, CTX / 128), 512, SMEM_TOTAL_GEMM>>>(
            hsH + (size_t)b * S_TOT * D_, hsL + (size_t)b * S_TOT * D_,
            WvH, nullptr, Vin + (size_t)b * CTX * D_, nullptr, nullptr,
            CTX, D_, D_);
    }
    hgemm512<false, false, false><<<dim3(D_ / 128, (B_ * POOL) / 128), 512, SMEM_TOTAL_GEMM>>>(
        cmpH, cmpL, WkH, nullptr, Kc, nullptr, nullptr, B_ * POOL, D_, D_);
    hgemm512<false, false, false><<<dim3(D_ / 128, (B_ * POOL) / 128), 512, SMEM_TOTAL_GEMM>>>(
        cmpH, cmpL, WvH, nullptr, Vc, nullptr, nullptr, B_ * POOL, D_, D_);

    // 5) attention -> split att
    cross_attn<<<dim3(REM / 128, NH, B_), 128>>>(Qb, Kc, Vc, attH, attL);
    causal_attn<<<dim3(CTX / 128, NH, B_), 128>>>(Qb, Kin, Vin, attH, attL);

    // 6) output projection into d_out
    hgemm512<false, false, false><<<dim3(D_ / 128, (B_ * S_TOT) / 128), 512, SMEM_TOTAL_GEMM>>>(
        attH, attL, WoH, nullptr, out, nullptr, nullptr, B_ * S_TOT, D_, D_);

    (void)in_sizes; (void)n_in; (void)out_size;
}

// round 11
// speedup vs baseline: 1.4751x; 1.0260x over previous
#include <cuda_runtime.h>
#include <cuda_fp16.h>
#include <math.h>
#include <stdint.h>

#define B_    2
#define S_TOT 16384
#define D_    1024
#define CTX   1024
#define POOL  256
#define REM   15360
#define NH    16
#define HD    64
#define DFF   512

// ---------------- scratch (static device globals; no allocation) ----------------
__device__ float g_comp_full[B_ * CTX * D_];
__device__ float g_Q[(size_t)B_ * S_TOT * D_];
__device__ float g_Kinit[B_ * CTX * D_];
__device__ float g_Vinit[B_ * CTX * D_];
__device__ float g_Kcomp[B_ * POOL * D_];
__device__ float g_Vcomp[B_ * POOL * D_];

__device__ __half g_hs_hi[(size_t)B_ * S_TOT * D_];
__device__ __half g_hs_lo[(size_t)B_ * S_TOT * D_];
__device__ __half g_att_hi[(size_t)B_ * S_TOT * D_];
__device__ __half g_att_lo[(size_t)B_ * S_TOT * D_];
__device__ __half g_mlp_hi[B_ * CTX * DFF];
__device__ __half g_mlp_lo[B_ * CTX * DFF];
__device__ __half g_comp_hi[B_ * POOL * D_];
__device__ __half g_comp_lo[B_ * POOL * D_];
__device__ __half g_Wq_h[D_ * D_];
__device__ __half g_Wk_h[D_ * D_];
__device__ __half g_Wv_h[D_ * D_];
__device__ __half g_Wo_h[D_ * D_];
__device__ __half g_W1_h[D_ * DFF];
__device__ __half g_W2_h[DFF * D_];

// ---------------- helpers --------------------------------------------------------
__device__ __forceinline__ uint32_t smem_u32(const void* p) {
    return (uint32_t)__cvta_generic_to_shared(p);
}
__device__ __forceinline__ void cpa16(uint32_t dst, const void* src) {
    asm volatile("cp.async.cg.shared.global [%0],[%1],16;" :: "r"(dst), "l"(src));
}
__device__ __forceinline__ void cp_commit() {
    asm volatile("cp.async.commit_group;");
}
template <int NG>
__device__ __forceinline__ void cp_wait() {
    asm volatile("cp.async.wait_group %0;" :: "n"(NG));
}
__device__ __forceinline__ void ldsm_x4(uint32_t& r0, uint32_t& r1,
                                        uint32_t& r2, uint32_t& r3, uint32_t a) {
    asm volatile("ldmatrix.sync.aligned.m8n8.x4.shared.b16 {%0,%1,%2,%3},[%4];"
                 : "=r"(r0), "=r"(r1), "=r"(r2), "=r"(r3) : "r"(a));
}
__device__ __forceinline__ void ldsm_x4t(uint32_t& r0, uint32_t& r1,
                                         uint32_t& r2, uint32_t& r3, uint32_t a) {
    asm volatile("ldmatrix.sync.aligned.m8n8.x4.trans.shared.b16 {%0,%1,%2,%3},[%4];"
                 : "=r"(r0), "=r"(r1), "=r"(r2), "=r"(r3) : "r"(a));
}
__device__ __forceinline__ void mma16816h(float* c, const uint32_t* a,
                                          uint32_t b0, uint32_t b1) {
    asm volatile(
        "mma.sync.aligned.m16n8k16.row.col.f32.f16.f16.f32 "
        "{%0,%1,%2,%3},{%4,%5,%6,%7},{%8,%9},{%0,%1,%2,%3};"
        : "+f"(c[0]), "+f"(c[1]), "+f"(c[2]), "+f"(c[3])
        : "r"(a[0]), "r"(a[1]), "r"(a[2]), "r"(a[3]), "r"(b0), "r"(b1));
}
__device__ __forceinline__ void split1h(float x, __half& h, __half& l) {
    h = __float2half_rn(x);
    l = __float2half_rn(x - __half2float(h));
}

// ---------------- fp32 -> (hi, lo) fp16 split, vectorized ------------------------
__global__ void split_f16(const float* __restrict__ src,
                          __half* __restrict__ hi,
                          __half* __restrict__ lo, int n4)
{
    int i = blockIdx.x * blockDim.x + threadIdx.x;
    if (i >= n4) return;
    float4 v = ((const float4*)src)[i];
    __half h[4], l[4];
    split1h(v.x, h[0], l[0]); split1h(v.y, h[1], l[1]);
    split1h(v.z, h[2], l[2]); split1h(v.w, h[3], l[3]);
    ((uint2*)hi)[i] = *(uint2*)h;
    ((uint2*)lo)[i] = *(uint2*)l;
}

__global__ void conv_f16(const float* __restrict__ src, __half* __restrict__ dst, int n4)
{
    int i = blockIdx.x * blockDim.x + threadIdx.x;
    if (i >= n4) return;
    float4 v = ((const float4*)src)[i];
    __half h[4];
    h[0] = __float2half_rn(v.x); h[1] = __float2half_rn(v.y);
    h[2] = __float2half_rn(v.z); h[3] = __float2half_rn(v.w);
    ((uint2*)dst)[i] = *(uint2*)h;
}

// ================= fp16 2-term GEMM, 2 CTAs/SM co-residency ======================
// C = (Ah + Al) @ B ; BM=BN=128, BK=32, 3-stage cp.async pipeline,
// 256 threads = 8 warps (4m x 2n), warp tile 32x64. smem 87552 -> 2 CTAs/SM.
// blockIdx.z = batch: A += z*strideA, C/Chi/Clo += z*strideC.
#define BK      32
#define LDA_S   40      // fp16 elems per A smem row (32 + 8 pad)
#define LDB_S   136     // fp16 elems per B smem row (128 + 8 pad)
#define A_BYTES (128 * LDA_S * 2)   // 10240
#define B_BYTES (BK * LDB_S * 2)    // 8704
#define OFF_AL  A_BYTES
#define OFF_B   (2 * A_BYTES)
#define STAGE_BYTES (2 * A_BYTES + B_BYTES)       // 29184
#define STAGES  3
#define SMEM_TOTAL_GEMM (STAGES * STAGE_BYTES)    // 87552

template <bool RELU, bool BIAS, bool OSPLIT>
__global__ __launch_bounds__(256, 2) void hgemm2c(
    const __half* __restrict__ Ahi, const __half* __restrict__ Alo,
    const __half* __restrict__ Bh,
    const float* __restrict__ bias,
    float* __restrict__ C,
    __half* __restrict__ Chi, __half* __restrict__ Clo,
    int M, int N, int K, size_t strideA, size_t strideC)
{
    extern __shared__ char smem[];
    const uint32_t sm_base = smem_u32(smem);

    const int tid = threadIdx.x;
    const int lane = tid & 31;
    const int wid = tid >> 5;
    const int wm = (wid & 3) * 32;      // warp m offset
    const int wn = (wid >> 2) * 64;     // warp n offset
    const int bm = blockIdx.y * 128;
    const int bn = blockIdx.x * 128;
    const size_t zA = (size_t)blockIdx.z * strideA;
    const size_t zC = (size_t)blockIdx.z * strideC;

    const int a_row = tid >> 1, a_col = (tid & 1) * 16;
    const int b_row = tid >> 3, b_col = (tid & 7) * 16;
    const __half* Agh = Ahi + zA + (size_t)(bm + a_row) * K + a_col;
    const __half* Agl = Alo + zA + (size_t)(bm + a_row) * K + a_col;
    const __half* Bg = Bh + (size_t)b_row * N + bn + b_col;
    const uint32_t a_dst = sm_base + a_row * (LDA_S * 2) + a_col * 2;
    const uint32_t b_dst = sm_base + b_row * (LDB_S * 2) + b_col * 2;

#define LOAD_STAGE(stg, k0)                                                    \
    {                                                                          \
        uint32_t sb = (stg) * STAGE_BYTES;                                     \
        const __half* ah = Agh + (k0);                                         \
        const __half* al = Agl + (k0);                                         \
        cpa16(a_dst + sb, ah);                 cpa16(a_dst + sb + 16, ah + 8); \
        cpa16(a_dst + sb + OFF_AL, al);        cpa16(a_dst + sb + OFF_AL + 16, al + 8); \
        const __half* bp = Bg + (size_t)(k0) * N;                              \
        cpa16(b_dst + sb + OFF_B, bp);         cpa16(b_dst + sb + OFF_B + 16, bp + 8); \
    }

    float acc[2][8][4];
#pragma unroll
    for (int i = 0; i < 2; i++)
#pragma unroll
        for (int j = 0; j < 8; j++)
#pragma unroll
            for (int r = 0; r < 4; r++) acc[i][j][r] = 0.f;

    const int ktiles = K / BK;

#pragma unroll
    for (int s = 0; s < STAGES - 1; s++) {
        if (s < ktiles) LOAD_STAGE(s, s * BK);
        cp_commit();
    }

    const int a_r = lane & 15, a_c8 = (lane >> 4) * 8;
    const int b_r = lane & 15, b_c8 = (lane >> 4) * 8;

    for (int it = 0; it < ktiles; it++) {
        cp_wait<STAGES - 2>();
        __syncthreads();

        if (it + STAGES - 1 < ktiles) {
            int ns = (it + STAGES - 1) % STAGES;
            LOAD_STAGE(ns, (it + STAGES - 1) * BK);
        }
        cp_commit();

        const uint32_t sb = sm_base + (it % STAGES) * STAGE_BYTES;
        const uint32_t ah_b = sb, al_b = sb + OFF_AL, bh_b = sb + OFF_B;

#pragma unroll
        for (int s = 0; s < 2; s++) {          // two k16 slices per BK=32
            const int ks = s * 16;
            uint32_t ah[2][4], al[2][4], bb[4][4];
#pragma unroll
            for (int am = 0; am < 2; am++) {
                uint32_t addr = ah_b + ((wm + am * 16 + a_r) * LDA_S + ks + a_c8) * 2;
                ldsm_x4(ah[am][0], ah[am][1], ah[am][2], ah[am][3], addr);
            }
#pragma unroll
            for (int p = 0; p < 4; p++) {
                uint32_t addr = bh_b + ((ks + b_r) * LDB_S + wn + p * 16 + b_c8) * 2;
                ldsm_x4t(bb[p][0], bb[p][1], bb[p][2], bb[p][3], addr);
            }
            // hi term
#pragma unroll
            for (int am = 0; am < 2; am++)
#pragma unroll
                for (int p = 0; p < 4; p++) {
                    mma16816h(acc[am][p * 2 + 0], ah[am], bb[p][0], bb[p][1]);
                    mma16816h(acc[am][p * 2 + 1], ah[am], bb[p][2], bb[p][3]);
                }
            // lo term
#pragma unroll
            for (int am = 0; am < 2; am++) {
                uint32_t addr = al_b + ((wm + am * 16 + a_r) * LDA_S + ks + a_c8) * 2;
                ldsm_x4(al[am][0], al[am][1], al[am][2], al[am][3], addr);
            }
#pragma unroll
            for (int am = 0; am < 2; am++)
#pragma unroll
                for (int p = 0; p < 4; p++) {
                    mma16816h(acc[am][p * 2 + 0], al[am], bb[p][0], bb[p][1]);
                    mma16816h(acc[am][p * 2 + 1], al[am], bb[p][2], bb[p][3]);
                }
        }
        __syncthreads();
    }

    // epilogue (validated mapping)
#pragma unroll
    for (int am = 0; am < 2; am++) {
        const int r0 = bm + wm + am * 16 + (lane >> 2);
#pragma unroll
        for (int an = 0; an < 8; an++) {
            const int c = bn + wn + an * 8 + (lane & 3) * 2;
            float v0 = acc[am][an][0], v1 = acc[am][an][1];
            float v2 = acc[am][an][2], v3 = acc[am][an][3];
            if (BIAS) {
                float bb0 = bias[c], bb1 = bias[c + 1];
                v0 += bb0; v1 += bb1; v2 += bb0; v3 += bb1;
            }
            if (RELU) {
                v0 = fmaxf(v0, 0.f); v1 = fmaxf(v1, 0.f);
                v2 = fmaxf(v2, 0.f); v3 = fmaxf(v3, 0.f);
            }
            if (OSPLIT) {
                __half h0, l0, h1, l1;
                size_t i0 = zC + (size_t)r0 * N + c, i1 = zC + (size_t)(r0 + 8) * N + c;
                split1h(v0, h0, l0); split1h(v1, h1, l1);
                __half2 hh; hh.x = h0; hh.y = h1;
                __half2 ll; ll.x = l0; ll.y = l1;
                *(__half2*)(Chi + i0) = hh;
                *(__half2*)(Clo + i0) = ll;
                split1h(v2, h0, l0); split1h(v3, h1, l1);
                hh.x = h0; hh.y = h1; ll.x = l0; ll.y = l1;
                *(__half2*)(Chi + i1) = hh;
                *(__half2*)(Clo + i1) = ll;
            } else {
                float* p0 = C + zC + (size_t)r0 * N + c;
                float* p1 = C + zC + (size_t)(r0 + 8) * N + c;
                p0[0] = v0; p0[1] = v1;
                p1[0] = v2; p1[1] = v3;
            }
        }
    }
#undef LOAD_STAGE
}

// ---------------- pooling: mean over groups of 4 rows -> split fp16 --------------
__global__ void pool_mean_split(const float* __restrict__ full,
                                __half* __restrict__ hi,
                                __half* __restrict__ lo)
{
    int idx = blockIdx.x * blockDim.x + threadIdx.x;
    int d = idx % D_;
    int p = (idx / D_) % POOL;
    int b = idx / (D_ * POOL);
    const float* src = full + ((size_t)b * CTX + p * 4) * D_ + d;
    float v = 0.25f * (src[0] + src[D_] + src[2 * D_] + src[3 * D_]);
    __half h, l;
    split1h(v, h, l);
    hi[idx] = h; lo[idx] = l;
}

// ---------------- attention (fp32 math, fp16-split output) -----------------------
__device__ __forceinline__ void attn_store_split(
    __half* __restrict__ hi, __half* __restrict__ lo,
    size_t base, const float* o, float inv)
{
#pragma unroll
    for (int i = 0; i < HD; i += 4) {
        __half h[4], l[4];
#pragma unroll
        for (int j = 0; j < 4; j++) split1h(o[i + j] * inv, h[j], l[j]);
        *(uint2*)(hi + base + i) = *(uint2*)h;
        *(uint2*)(lo + base + i) = *(uint2*)l;
    }
}

__global__ __launch_bounds__(128) void cross_attn(
    const float* __restrict__ Q, const float* __restrict__ K,
    const float* __restrict__ V,
    __half* __restrict__ Ohi, __half* __restrict__ Olo)
{
    const int b = blockIdx.z, h = blockIdx.y;
    const int r = blockIdx.x * 128 + threadIdx.x;
    const size_t qrow = (size_t)b * S_TOT + CTX + r;

    const float* q = Q + qrow * D_ + h * HD;
    float qv[HD];
#pragma unroll
    for (int i = 0; i < HD; i += 4) {
        float4 t = *(const float4*)(q + i);
        qv[i] = t.x; qv[i + 1] = t.y; qv[i + 2] = t.z; qv[i + 3] = t.w;
    }

    const float* Kb = K + (size_t)b * POOL * D_ + h * HD;
    const float* Vb = V + (size_t)b * POOL * D_ + h * HD;

    float m = -1e30f, l = 0.f;
    float o[HD];
#pragma unroll
    for (int i = 0; i < HD; i++) o[i] = 0.f;

    for (int j = 0; j < POOL; j++) {
        const float* krow = Kb + (size_t)j * D_;
        float s0 = 0.f, s1 = 0.f, s2 = 0.f, s3 = 0.f;
#pragma unroll
        for (int i4 = 0; i4 < 16; i4++) {
            float4 k4 = *(const float4*)(krow + i4 * 4);
            s0 = fmaf(qv[i4 * 4 + 0], k4.x, s0);
            s1 = fmaf(qv[i4 * 4 + 1], k4.y, s1);
            s2 = fmaf(qv[i4 * 4 + 2], k4.z, s2);
            s3 = fmaf(qv[i4 * 4 + 3], k4.w, s3);
        }
        float s = ((s0 + s1) + (s2 + s3)) * 0.125f;

        float mn = fmaxf(m, s);
        float corr = __expf(m - mn);
        float p = __expf(s - mn);
        l = l * corr + p;
        m = mn;

        const float* vrow = Vb + (size_t)j * D_;
#pragma unroll
        for (int i4 = 0; i4 < 16; i4++) {
            float4 v4 = *(const float4*)(vrow + i4 * 4);
            o[i4 * 4 + 0] = o[i4 * 4 + 0] * corr + p * v4.x;
            o[i4 * 4 + 1] = o[i4 * 4 + 1] * corr + p * v4.y;
            o[i4 * 4 + 2] = o[i4 * 4 + 2] * corr + p * v4.z;
            o[i4 * 4 + 3] = o[i4 * 4 + 3] * corr + p * v4.w;
        }
    }
    attn_store_split(Ohi, Olo, qrow * D_ + h * HD, o, 1.f / l);
}

__global__ __launch_bounds__(128) void causal_attn(
    const float* __restrict__ Q, const float* __restrict__ K,
    const float* __restrict__ V,
    __half* __restrict__ Ohi, __half* __restrict__ Olo)
{
    const int b = blockIdx.z, h = blockIdx.y;
    const int qp = blockIdx.x * 128 + threadIdx.x;
    const size_t qrow = (size_t)b * S_TOT + qp;

    const float* q = Q + qrow * D_ + h * HD;
    float qv[HD];
#pragma unroll
    for (int i = 0; i < HD; i += 4) {
        float4 t = *(const float4*)(q + i);
        qv[i] = t.x; qv[i + 1] = t.y; qv[i + 2] = t.z; qv[i + 3] = t.w;
    }

    const float* Kb = K + (size_t)b * CTX * D_ + h * HD;
    const float* Vb = V + (size_t)b * CTX * D_ + h * HD;

    float m = -1e30f, l = 0.f;
    float o[HD];
#pragma unroll
    for (int i = 0; i < HD; i++) o[i] = 0.f;

    for (int j = 0; j <= qp; j++) {
        const float* krow = Kb + (size_t)j * D_;
        float s0 = 0.f, s1 = 0.f, s2 = 0.f, s3 = 0.f;
#pragma unroll
        for (int i4 = 0; i4 < 16; i4++) {
            float4 k4 = *(const float4*)(krow + i4 * 4);
            s0 = fmaf(qv[i4 * 4 + 0], k4.x, s0);
            s1 = fmaf(qv[i4 * 4 + 1], k4.y, s1);
            s2 = fmaf(qv[i4 * 4 + 2], k4.z, s2);
            s3 = fmaf(qv[i4 * 4 + 3], k4.w, s3);
        }
        float s = ((s0 + s1) + (s2 + s3)) * 0.125f;

        float mn = fmaxf(m, s);
        float corr = __expf(m - mn);
        float p = __expf(s - mn);
        l = l * corr + p;
        m = mn;

        const float* vrow = Vb + (size_t)j * D_;
#pragma unroll
        for (int i4 = 0; i4 < 16; i4++) {
            float4 v4 = *(const float4*)(vrow + i4 * 4);
            o[i4 * 4 + 0] = o[i4 * 4 + 0] * corr + p * v4.x;
            o[i4 * 4 + 1] = o[i4 * 4 + 1] * corr + p * v4.y;
            o[i4 * 4 + 2] = o[i4 * 4 + 2] * corr + p * v4.z;
            o[i4 * 4 + 3] = o[i4 * 4 + 3] * corr + p * v4.w;
        }
    }
    attn_store_split(Ohi, Olo, qrow * D_ + h * HD, o, 1.f / l);
}

// ---------------- host launcher --------------------------------------------------
extern "C" void kernel_launch(void* const* d_in, const int* in_sizes, int n_in,
                              void* d_out, int out_size)
{
    const float* hs = (const float*)d_in[0];
    const float* Wq = (const float*)d_in[1];
    const float* Wk = (const float*)d_in[2];
    const float* Wv = (const float*)d_in[3];
    const float* Wo = (const float*)d_in[4];
    const float* W1 = (const float*)d_in[5];
    const float* b1 = (const float*)d_in[6];
    const float* W2 = (const float*)d_in[7];
    const float* b2 = (const float*)d_in[8];
    float* out = (float*)d_out;

    float *comp_full, *Qb, *Kin, *Vin, *Kc, *Vc;
    __half *hsH, *hsL, *attH, *attL, *mlpH, *mlpL, *cmpH, *cmpL;
    __half *WqH, *WkH, *WvH, *WoH, *W1H, *W2H;
    cudaGetSymbolAddress((void**)&comp_full, g_comp_full);
    cudaGetSymbolAddress((void**)&Qb, g_Q);
    cudaGetSymbolAddress((void**)&Kin, g_Kinit);
    cudaGetSymbolAddress((void**)&Vin, g_Vinit);
    cudaGetSymbolAddress((void**)&Kc, g_Kcomp);
    cudaGetSymbolAddress((void**)&Vc, g_Vcomp);
    cudaGetSymbolAddress((void**)&hsH, g_hs_hi);   cudaGetSymbolAddress((void**)&hsL, g_hs_lo);
    cudaGetSymbolAddress((void**)&attH, g_att_hi); cudaGetSymbolAddress((void**)&attL, g_att_lo);
    cudaGetSymbolAddress((void**)&mlpH, g_mlp_hi); cudaGetSymbolAddress((void**)&mlpL, g_mlp_lo);
    cudaGetSymbolAddress((void**)&cmpH, g_comp_hi); cudaGetSymbolAddress((void**)&cmpL, g_comp_lo);
    cudaGetSymbolAddress((void**)&WqH, g_Wq_h);
    cudaGetSymbolAddress((void**)&WkH, g_Wk_h);
    cudaGetSymbolAddress((void**)&WvH, g_Wv_h);
    cudaGetSymbolAddress((void**)&WoH, g_Wo_h);
    cudaGetSymbolAddress((void**)&W1H, g_W1_h);
    cudaGetSymbolAddress((void**)&W2H, g_W2_h);

    cudaFuncSetAttribute(hgemm2c<false, false, false>,
                         cudaFuncAttributeMaxDynamicSharedMemorySize, SMEM_TOTAL_GEMM);
    cudaFuncSetAttribute(hgemm2c<true, true, true>,
                         cudaFuncAttributeMaxDynamicSharedMemorySize, SMEM_TOTAL_GEMM);
    cudaFuncSetAttribute(hgemm2c<false, true, false>,
                         cudaFuncAttributeMaxDynamicSharedMemorySize, SMEM_TOTAL_GEMM);

    // 0) split activations (fp16 hi/lo), convert weights (fp16 single)
    {
        int n4 = (B_ * S_TOT * D_) / 4;
        split_f16<<<(n4 + 255) / 256, 256>>>(hs, hsH, hsL, n4);
        int w4 = (D_ * D_) / 4;
        conv_f16<<<(w4 + 255) / 256, 256>>>(Wq, WqH, w4);
        conv_f16<<<(w4 + 255) / 256, 256>>>(Wk, WkH, w4);
        conv_f16<<<(w4 + 255) / 256, 256>>>(Wv, WvH, w4);
        conv_f16<<<(w4 + 255) / 256, 256>>>(Wo, WoH, w4);
        int f4 = (D_ * DFF) / 4;
        conv_f16<<<(f4 + 255) / 256, 256>>>(W1, W1H, f4);
        conv_f16<<<(f4 + 255) / 256, 256>>>(W2, W2H, f4);
    }

    // 1) MLP on initial tokens (batched via grid.z) -> split output
    hgemm2c<true, true, true><<<dim3(DFF / 128, CTX / 128, B_), 256, SMEM_TOTAL_GEMM>>>(
        hsH, hsL, W1H, b1, nullptr, mlpH, mlpL,
        CTX, DFF, D_, (size_t)S_TOT * D_, (size_t)CTX * DFF);
    hgemm2c<false, true, false><<<dim3(D_ / 128, CTX / 128, B_), 256, SMEM_TOTAL_GEMM>>>(
        mlpH, mlpL, W2H, b2, comp_full, nullptr, nullptr,
        CTX, D_, DFF, (size_t)CTX * DFF, (size_t)CTX * D_);

    // 2) pool -> split comp
    pool_mean_split<<<(B_ * POOL * D_) / 256, 256>>>(comp_full, cmpH, cmpL);

    // 3) Q for ALL tokens (contiguous, z=1)
    hgemm2c<false, false, false><<<dim3(D_ / 128, (B_ * S_TOT) / 128, 1), 256, SMEM_TOTAL_GEMM>>>(
        hsH, hsL, WqH, nullptr, Qb, nullptr, nullptr, B_ * S_TOT, D_, D_, 0, 0);

    // 4) K,V init (batched via grid.z), K,V comp (contiguous)
    hgemm2c<false, false, false><<<dim3(D_ / 128, CTX / 128, B_), 256, SMEM_TOTAL_GEMM>>>(
        hsH, hsL, WkH, nullptr, Kin, nullptr, nullptr,
        CTX, D_, D_, (size_t)S_TOT * D_, (size_t)CTX * D_);
    hgemm2c<false, false, false><<<dim3(D_ / 128, CTX / 128, B_), 256, SMEM_TOTAL_GEMM>>>(
        hsH, hsL, WvH, nullptr, Vin, nullptr, nullptr,
        CTX, D_, D_, (size_t)S_TOT * D_, (size_t)CTX * D_);
    hgemm2c<false, false, false><<<dim3(D_ / 128, (B_ * POOL) / 128, 1), 256, SMEM_TOTAL_GEMM>>>(
        cmpH, cmpL, WkH, nullptr, Kc, nullptr, nullptr, B_ * POOL, D_, D_, 0, 0);
    hgemm2c<false, false, false><<<dim3(D_ / 128, (B_ * POOL) / 128, 1), 256, SMEM_TOTAL_GEMM>>>(
        cmpH, cmpL, WvH, nullptr, Vc, nullptr, nullptr, B_ * POOL, D_, D_, 0, 0);

    // 5) attention -> split att
    cross_attn<<<dim3(REM / 128, NH, B_), 128>>>(Qb, Kc, Vc, attH, attL);
    causal_attn<<<dim3(CTX / 128, NH, B_), 128>>>(Qb, Kin, Vin, attH, attL);

    // 6) output projection into d_out
    hgemm2c<false, false, false><<<dim3(D_ / 128, (B_ * S_TOT) / 128, 1), 256, SMEM_TOTAL_GEMM>>>(
        attH, attL, WoH, nullptr, out, nullptr, nullptr, B_ * S_TOT, D_, D_, 0, 0);

    (void)in_sizes; (void)n_in; (void)out_size;
}

// round 15
// speedup vs baseline: 1.5172x; 1.0285x over previous
#include <cuda_runtime.h>
#include <cuda_fp16.h>
#include <math.h>
#include <stdint.h>

#define B_    2
#define S_TOT 16384
#define D_    1024
#define CTX   1024
#define POOL  256
#define REM   15360
#define NH    16
#define HD    64
#define DFF   512

// ---------------- scratch (static device globals; no allocation) ----------------
__device__ float g_comp_full[B_ * CTX * D_];
__device__ float g_Q[(size_t)B_ * S_TOT * D_];
__device__ float g_Kinit[B_ * CTX * D_];
__device__ float g_Vinit[B_ * CTX * D_];
__device__ float g_Kcomp[B_ * POOL * D_];
__device__ float g_Vcomp[B_ * POOL * D_];

__device__ __half g_hs_hi[(size_t)B_ * S_TOT * D_];
__device__ __half g_hs_lo[(size_t)B_ * S_TOT * D_];
__device__ __half g_att_hi[(size_t)B_ * S_TOT * D_];
__device__ __half g_mlp_hi[B_ * CTX * DFF];
__device__ __half g_mlp_lo[B_ * CTX * DFF];
__device__ __half g_comp_hi[B_ * POOL * D_];
__device__ __half g_comp_lo[B_ * POOL * D_];
__device__ __half g_Wq_h[D_ * D_];
__device__ __half g_Wk_h[D_ * D_];
__device__ __half g_Wv_h[D_ * D_];
__device__ __half g_Wo_h[D_ * D_];
__device__ __half g_W1_h[D_ * DFF];
__device__ __half g_W2_h[DFF * D_];

// ---------------- helpers --------------------------------------------------------
__device__ __forceinline__ uint32_t smem_u32(const void* p) {
    return (uint32_t)__cvta_generic_to_shared(p);
}
__device__ __forceinline__ void cpa16(uint32_t dst, const void* src) {
    asm volatile("cp.async.cg.shared.global [%0],[%1],16;" :: "r"(dst), "l"(src));
}
__device__ __forceinline__ void cp_commit() {
    asm volatile("cp.async.commit_group;");
}
template <int NG>
__device__ __forceinline__ void cp_wait() {
    asm volatile("cp.async.wait_group %0;" :: "n"(NG));
}
__device__ __forceinline__ void ldsm_x4(uint32_t& r0, uint32_t& r1,
                                        uint32_t& r2, uint32_t& r3, uint32_t a) {
    asm volatile("ldmatrix.sync.aligned.m8n8.x4.shared.b16 {%0,%1,%2,%3},[%4];"
                 : "=r"(r0), "=r"(r1), "=r"(r2), "=r"(r3) : "r"(a));
}
__device__ __forceinline__ void ldsm_x4t(uint32_t& r0, uint32_t& r1,
                                         uint32_t& r2, uint32_t& r3, uint32_t a) {
    asm volatile("ldmatrix.sync.aligned.m8n8.x4.trans.shared.b16 {%0,%1,%2,%3},[%4];"
                 : "=r"(r0), "=r"(r1), "=r"(r2), "=r"(r3) : "r"(a));
}
__device__ __forceinline__ void mma16816h(float* c, const uint32_t* a,
                                          uint32_t b0, uint32_t b1) {
    asm volatile(
        "mma.sync.aligned.m16n8k16.row.col.f32.f16.f16.f32 "
        "{%0,%1,%2,%3},{%4,%5,%6,%7},{%8,%9},{%0,%1,%2,%3};"
        : "+f"(c[0]), "+f"(c[1]), "+f"(c[2]), "+f"(c[3])
        : "r"(a[0]), "r"(a[1]), "r"(a[2]), "r"(a[3]), "r"(b0), "r"(b1));
}
__device__ __forceinline__ void split1h(float x, __half& h, __half& l) {
    h = __float2half_rn(x);
    l = __float2half_rn(x - __half2float(h));
}

// ---------------- fp32 -> (hi, lo) fp16 split, vectorized ------------------------
__global__ void split_f16(const float* __restrict__ src,
                          __half* __restrict__ hi,
                          __half* __restrict__ lo, int n4)
{
    int i = blockIdx.x * blockDim.x + threadIdx.x;
    if (i >= n4) return;
    float4 v = ((const float4*)src)[i];
    __half h[4], l[4];
    split1h(v.x, h[0], l[0]); split1h(v.y, h[1], l[1]);
    split1h(v.z, h[2], l[2]); split1h(v.w, h[3], l[3]);
    ((uint2*)hi)[i] = *(uint2*)h;
    ((uint2*)lo)[i] = *(uint2*)l;
}

__global__ void conv_f16(const float* __restrict__ src, __half* __restrict__ dst, int n4)
{
    int i = blockIdx.x * blockDim.x + threadIdx.x;
    if (i >= n4) return;
    float4 v = ((const float4*)src)[i];
    __half h[4];
    h[0] = __float2half_rn(v.x); h[1] = __float2half_rn(v.y);
    h[2] = __float2half_rn(v.z); h[3] = __float2half_rn(v.w);
    ((uint2*)dst)[i] = *(uint2*)h;
}

// ================= fp16 GEMM, 2 CTAs/SM co-residency =============================
// ALO=true : C = (Ah + Al) @ B   (A exact fp16 pair)
// ALO=false: C = Ah @ B          (single-term; A rounding ~2^-12)
// BM=BN=128, BK=32, 3-stage cp.async pipeline, 256 thr = 8 warps (4m x 2n).
#define BK      32
#define LDA_S   40
#define LDB_S   136
#define A_BYTES (128 * LDA_S * 2)
#define B_BYTES (BK * LDB_S * 2)
#define OFF_AL  A_BYTES
#define OFF_B   (2 * A_BYTES)
#define STAGE_BYTES (2 * A_BYTES + B_BYTES)       // 29184
#define STAGES  3
#define SMEM_TOTAL_GEMM (STAGES * STAGE_BYTES)    // 87552

template <bool RELU, bool BIAS, bool OSPLIT, bool ALO>
__global__ __launch_bounds__(256, 2) void hgemm2c(
    const __half* __restrict__ Ahi, const __half* __restrict__ Alo,
    const __half* __restrict__ Bh,
    const float* __restrict__ bias,
    float* __restrict__ C,
    __half* __restrict__ Chi, __half* __restrict__ Clo,
    int M, int N, int K, size_t strideA, size_t strideC)
{
    extern __shared__ char smem[];
    const uint32_t sm_base = smem_u32(smem);

    const int tid = threadIdx.x;
    const int lane = tid & 31;
    const int wid = tid >> 5;
    const int wm = (wid & 3) * 32;
    const int wn = (wid >> 2) * 64;
    const int bm = blockIdx.y * 128;
    const int bn = blockIdx.x * 128;
    const size_t zA = (size_t)blockIdx.z * strideA;
    const size_t zC = (size_t)blockIdx.z * strideC;

    const int a_row = tid >> 1, a_col = (tid & 1) * 16;
    const int b_row = tid >> 3, b_col = (tid & 7) * 16;
    const __half* Agh = Ahi + zA + (size_t)(bm + a_row) * K + a_col;
    const __half* Agl = ALO ? (Alo + zA + (size_t)(bm + a_row) * K + a_col) : Agh;
    const __half* Bg = Bh + (size_t)b_row * N + bn + b_col;
    const uint32_t a_dst = sm_base + a_row * (LDA_S * 2) + a_col * 2;
    const uint32_t b_dst = sm_base + b_row * (LDB_S * 2) + b_col * 2;

#define LOAD_STAGE(stg, k0)                                                    \
    {                                                                          \
        uint32_t sb = (stg) * STAGE_BYTES;                                     \
        const __half* ah = Agh + (k0);                                         \
        cpa16(a_dst + sb, ah);                 cpa16(a_dst + sb + 16, ah + 8); \
        if (ALO) {                                                             \
            const __half* al = Agl + (k0);                                     \
            cpa16(a_dst + sb + OFF_AL, al);                                    \
            cpa16(a_dst + sb + OFF_AL + 16, al + 8);                           \
        }                                                                      \
        const __half* bp = Bg + (size_t)(k0) * N;                              \
        cpa16(b_dst + sb + OFF_B, bp);         cpa16(b_dst + sb + OFF_B + 16, bp + 8); \
    }

    float acc[2][8][4];
#pragma unroll
    for (int i = 0; i < 2; i++)
#pragma unroll
        for (int j = 0; j < 8; j++)
#pragma unroll
            for (int r = 0; r < 4; r++) acc[i][j][r] = 0.f;

    const int ktiles = K / BK;

#pragma unroll
    for (int s = 0; s < STAGES - 1; s++) {
        if (s < ktiles) LOAD_STAGE(s, s * BK);
        cp_commit();
    }

    const int a_r = lane & 15, a_c8 = (lane >> 4) * 8;
    const int b_r = lane & 15, b_c8 = (lane >> 4) * 8;

    for (int it = 0; it < ktiles; it++) {
        cp_wait<STAGES - 2>();
        __syncthreads();

        if (it + STAGES - 1 < ktiles) {
            int ns = (it + STAGES - 1) % STAGES;
            LOAD_STAGE(ns, (it + STAGES - 1) * BK);
        }
        cp_commit();

        const uint32_t sb = sm_base + (it % STAGES) * STAGE_BYTES;
        const uint32_t ah_b = sb, al_b = sb + OFF_AL, bh_b = sb + OFF_B;

#pragma unroll
        for (int s = 0; s < 2; s++) {
            const int ks = s * 16;
            uint32_t ah[2][4], al[2][4], bb[4][4];
#pragma unroll
            for (int am = 0; am < 2; am++) {
                uint32_t addr = ah_b + ((wm + am * 16 + a_r) * LDA_S + ks + a_c8) * 2;
                ldsm_x4(ah[am][0], ah[am][1], ah[am][2], ah[am][3], addr);
            }
#pragma unroll
            for (int p = 0; p < 4; p++) {
                uint32_t addr = bh_b + ((ks + b_r) * LDB_S + wn + p * 16 + b_c8) * 2;
                ldsm_x4t(bb[p][0], bb[p][1], bb[p][2], bb[p][3], addr);
            }
#pragma unroll
            for (int am = 0; am < 2; am++)
#pragma unroll
                for (int p = 0; p < 4; p++) {
                    mma16816h(acc[am][p * 2 + 0], ah[am], bb[p][0], bb[p][1]);
                    mma16816h(acc[am][p * 2 + 1], ah[am], bb[p][2], bb[p][3]);
                }
            if (ALO) {
#pragma unroll
                for (int am = 0; am < 2; am++) {
                    uint32_t addr = al_b + ((wm + am * 16 + a_r) * LDA_S + ks + a_c8) * 2;
                    ldsm_x4(al[am][0], al[am][1], al[am][2], al[am][3], addr);
                }
#pragma unroll
                for (int am = 0; am < 2; am++)
#pragma unroll
                    for (int p = 0; p < 4; p++) {
                        mma16816h(acc[am][p * 2 + 0], al[am], bb[p][0], bb[p][1]);
                        mma16816h(acc[am][p * 2 + 1], al[am], bb[p][2], bb[p][3]);
                    }
            }
        }
        __syncthreads();
    }

#pragma unroll
    for (int am = 0; am < 2; am++) {
        const int r0 = bm + wm + am * 16 + (lane >> 2);
#pragma unroll
        for (int an = 0; an < 8; an++) {
            const int c = bn + wn + an * 8 + (lane & 3) * 2;
            float v0 = acc[am][an][0], v1 = acc[am][an][1];
            float v2 = acc[am][an][2], v3 = acc[am][an][3];
            if (BIAS) {
                float bb0 = bias[c], bb1 = bias[c + 1];
                v0 += bb0; v1 += bb1; v2 += bb0; v3 += bb1;
            }
            if (RELU) {
                v0 = fmaxf(v0, 0.f); v1 = fmaxf(v1, 0.f);
                v2 = fmaxf(v2, 0.f); v3 = fmaxf(v3, 0.f);
            }
            if (OSPLIT) {
                __half h0, l0, h1, l1;
                size_t i0 = zC + (size_t)r0 * N + c, i1 = zC + (size_t)(r0 + 8) * N + c;
                split1h(v0, h0, l0); split1h(v1, h1, l1);
                __half2 hh; hh.x = h0; hh.y = h1;
                __half2 ll; ll.x = l0; ll.y = l1;
                *(__half2*)(Chi + i0) = hh;
                *(__half2*)(Clo + i0) = ll;
                split1h(v2, h0, l0); split1h(v3, h1, l1);
                hh.x = h0; hh.y = h1; ll.x = l0; ll.y = l1;
                *(__half2*)(Chi + i1) = hh;
                *(__half2*)(Clo + i1) = ll;
            } else {
                float* p0 = C + zC + (size_t)r0 * N + c;
                float* p1 = C + zC + (size_t)(r0 + 8) * N + c;
                p0[0] = v0; p0[1] = v1;
                p1[0] = v2; p1[1] = v3;
            }
        }
    }
#undef LOAD_STAGE
}

// ---------------- pooling: mean over groups of 4 rows -> split fp16 --------------
__global__ void pool_mean_split(const float* __restrict__ full,
                                __half* __restrict__ hi,
                                __half* __restrict__ lo)
{
    int idx = blockIdx.x * blockDim.x + threadIdx.x;
    int d = idx % D_;
    int p = (idx / D_) % POOL;
    int b = idx / (D_ * POOL);
    const float* src = full + ((size_t)b * CTX + p * 4) * D_ + d;
    float v = 0.25f * (src[0] + src[D_] + src[2 * D_] + src[3 * D_]);
    __half h, l;
    split1h(v, h, l);
    hi[idx] = h; lo[idx] = l;
}

// ---------------- attention (fp32 math, fp16-hi output) --------------------------
__device__ __forceinline__ void attn_store_hi(
    __half* __restrict__ hi, size_t base, const float* o, float inv)
{
#pragma unroll
    for (int i = 0; i < HD; i += 4) {
        __half h[4];
#pragma unroll
        for (int j = 0; j < 4; j++) h[j] = __float2half_rn(o[i + j] * inv);
        *(uint2*)(hi + base + i) = *(uint2*)h;
    }
}

__global__ __launch_bounds__(128) void cross_attn(
    const float* __restrict__ Q, const float* __restrict__ K,
    const float* __restrict__ V, __half* __restrict__ Ohi)
{
    const int b = blockIdx.z, h = blockIdx.y;
    const int r = blockIdx.x * 128 + threadIdx.x;
    const size_t qrow = (size_t)b * S_TOT + CTX + r;

    const float* q = Q + qrow * D_ + h * HD;
    float qv[HD];
#pragma unroll
    for (int i = 0; i < HD; i += 4) {
        float4 t = *(const float4*)(q + i);
        qv[i] = t.x; qv[i + 1] = t.y; qv[i + 2] = t.z; qv[i + 3] = t.w;
    }

    const float* Kb = K + (size_t)b * POOL * D_ + h * HD;
    const float* Vb = V + (size_t)b * POOL * D_ + h * HD;

    float m = -1e30f, l = 0.f;
    float o[HD];
#pragma unroll
    for (int i = 0; i < HD; i++) o[i] = 0.f;

    for (int j = 0; j < POOL; j++) {
        const float* krow = Kb + (size_t)j * D_;
        float s0 = 0.f, s1 = 0.f, s2 = 0.f, s3 = 0.f;
#pragma unroll
        for (int i4 = 0; i4 < 16; i4++) {
            float4 k4 = *(const float4*)(krow + i4 * 4);
            s0 = fmaf(qv[i4 * 4 + 0], k4.x, s0);
            s1 = fmaf(qv[i4 * 4 + 1], k4.y, s1);
            s2 = fmaf(qv[i4 * 4 + 2], k4.z, s2);
            s3 = fmaf(qv[i4 * 4 + 3], k4.w, s3);
        }
        float s = ((s0 + s1) + (s2 + s3)) * 0.125f;

        float mn = fmaxf(m, s);
        float corr = __expf(m - mn);
        float p = __expf(s - mn);
        l = l * corr + p;
        m = mn;

        const float* vrow = Vb + (size_t)j * D_;
#pragma unroll
        for (int i4 = 0; i4 < 16; i4++) {
            float4 v4 = *(const float4*)(vrow + i4 * 4);
            o[i4 * 4 + 0] = o[i4 * 4 + 0] * corr + p * v4.x;
            o[i4 * 4 + 1] = o[i4 * 4 + 1] * corr + p * v4.y;
            o[i4 * 4 + 2] = o[i4 * 4 + 2] * corr + p * v4.z;
            o[i4 * 4 + 3] = o[i4 * 4 + 3] * corr + p * v4.w;
        }
    }
    attn_store_hi(Ohi, qrow * D_ + h * HD, o, 1.f / l);
}

__global__ __launch_bounds__(128) void causal_attn(
    const float* __restrict__ Q, const float* __restrict__ K,
    const float* __restrict__ V, __half* __restrict__ Ohi)
{
    const int b = blockIdx.z, h = blockIdx.y;
    const int qp = blockIdx.x * 128 + threadIdx.x;
    const size_t qrow = (size_t)b * S_TOT + qp;

    const float* q = Q + qrow * D_ + h * HD;
    float qv[HD];
#pragma unroll
    for (int i = 0; i < HD; i += 4) {
        float4 t = *(const float4*)(q + i);
        qv[i] = t.x; qv[i + 1] = t.y; qv[i + 2] = t.z; qv[i + 3] = t.w;
    }

    const float* Kb = K + (size_t)b * CTX * D_ + h * HD;
    const float* Vb = V + (size_t)b * CTX * D_ + h * HD;

    float m = -1e30f, l = 0.f;
    float o[HD];
#pragma unroll
    for (int i = 0; i < HD; i++) o[i] = 0.f;

    for (int j = 0; j <= qp; j++) {
        const float* krow = Kb + (size_t)j * D_;
        float s0 = 0.f, s1 = 0.f, s2 = 0.f, s3 = 0.f;
#pragma unroll
        for (int i4 = 0; i4 < 16; i4++) {
            float4 k4 = *(const float4*)(krow + i4 * 4);
            s0 = fmaf(qv[i4 * 4 + 0], k4.x, s0);
            s1 = fmaf(qv[i4 * 4 + 1], k4.y, s1);
            s2 = fmaf(qv[i4 * 4 + 2], k4.z, s2);
            s3 = fmaf(qv[i4 * 4 + 3], k4.w, s3);
        }
        float s = ((s0 + s1) + (s2 + s3)) * 0.125f;

        float mn = fmaxf(m, s);
        float corr = __expf(m - mn);
        float p = __expf(s - mn);
        l = l * corr + p;
        m = mn;

        const float* vrow = Vb + (size_t)j * D_;
#pragma unroll
        for (int i4 = 0; i4 < 16; i4++) {
            float4 v4 = *(const float4*)(vrow + i4 * 4);
            o[i4 * 4 + 0] = o[i4 * 4 + 0] * corr + p * v4.x;
            o[i4 * 4 + 1] = o[i4 * 4 + 1] * corr + p * v4.y;
            o[i4 * 4 + 2] = o[i4 * 4 + 2] * corr + p * v4.z;
            o[i4 * 4 + 3] = o[i4 * 4 + 3] * corr + p * v4.w;
        }
    }
    attn_store_hi(Ohi, qrow * D_ + h * HD, o, 1.f / l);
}

// ---------------- host launcher (single stream; known-good structure) ------------
extern "C" void kernel_launch(void* const* d_in, const int* in_sizes, int n_in,
                              void* d_out, int out_size)
{
    const float* hs = (const float*)d_in[0];
    const float* Wq = (const float*)d_in[1];
    const float* Wk = (const float*)d_in[2];
    const float* Wv = (const float*)d_in[3];
    const float* Wo = (const float*)d_in[4];
    const float* W1 = (const float*)d_in[5];
    const float* b1 = (const float*)d_in[6];
    const float* W2 = (const float*)d_in[7];
    const float* b2 = (const float*)d_in[8];
    float* out = (float*)d_out;

    float *comp_full, *Qb, *Kin, *Vin, *Kc, *Vc;
    __half *hsH, *hsL, *attH, *mlpH, *mlpL, *cmpH, *cmpL;
    __half *WqH, *WkH, *WvH, *WoH, *W1H, *W2H;
    cudaGetSymbolAddress((void**)&comp_full, g_comp_full);
    cudaGetSymbolAddress((void**)&Qb, g_Q);
    cudaGetSymbolAddress((void**)&Kin, g_Kinit);
    cudaGetSymbolAddress((void**)&Vin, g_Vinit);
    cudaGetSymbolAddress((void**)&Kc, g_Kcomp);
    cudaGetSymbolAddress((void**)&Vc, g_Vcomp);
    cudaGetSymbolAddress((void**)&hsH, g_hs_hi);   cudaGetSymbolAddress((void**)&hsL, g_hs_lo);
    cudaGetSymbolAddress((void**)&attH, g_att_hi);
    cudaGetSymbolAddress((void**)&mlpH, g_mlp_hi); cudaGetSymbolAddress((void**)&mlpL, g_mlp_lo);
    cudaGetSymbolAddress((void**)&cmpH, g_comp_hi); cudaGetSymbolAddress((void**)&cmpL, g_comp_lo);
    cudaGetSymbolAddress((void**)&WqH, g_Wq_h);
    cudaGetSymbolAddress((void**)&WkH, g_Wk_h);
    cudaGetSymbolAddress((void**)&WvH, g_Wv_h);
    cudaGetSymbolAddress((void**)&WoH, g_Wo_h);
    cudaGetSymbolAddress((void**)&W1H, g_W1_h);
    cudaGetSymbolAddress((void**)&W2H, g_W2_h);

    cudaFuncSetAttribute(hgemm2c<false, false, false, true>,
                         cudaFuncAttributeMaxDynamicSharedMemorySize, SMEM_TOTAL_GEMM);
    cudaFuncSetAttribute(hgemm2c<true, true, true, true>,
                         cudaFuncAttributeMaxDynamicSharedMemorySize, SMEM_TOTAL_GEMM);
    cudaFuncSetAttribute(hgemm2c<false, true, false, true>,
                         cudaFuncAttributeMaxDynamicSharedMemorySize, SMEM_TOTAL_GEMM);
    cudaFuncSetAttribute(hgemm2c<false, false, false, false>,
                         cudaFuncAttributeMaxDynamicSharedMemorySize, SMEM_TOTAL_GEMM);

    const size_t sTOK = (size_t)S_TOT * D_;

    // #1..#5: split hs, convert attention weights
    {
        int n4 = (B_ * S_TOT * D_) / 4;
        split_f16<<<(n4 + 255) / 256, 256>>>(hs, hsH, hsL, n4);       // #1
        int w4 = (D_ * D_) / 4;
        conv_f16<<<(w4 + 255) / 256, 256>>>(Wq, WqH, w4);             // #2
        conv_f16<<<(w4 + 255) / 256, 256>>>(Wk, WkH, w4);             // #3
        conv_f16<<<(w4 + 255) / 256, 256>>>(Wv, WvH, w4);             // #4
        conv_f16<<<(w4 + 255) / 256, 256>>>(Wo, WoH, w4);             // #5
    }

    // #6: BIG Q projection (all 32768 rows) — this is what ncu -s 5 -c 1 captures
    hgemm2c<false, false, false, true><<<dim3(D_ / 128, (B_ * S_TOT) / 128, 1), 256, SMEM_TOTAL_GEMM>>>(
        hsH, hsL, WqH, nullptr, Qb, nullptr, nullptr, B_ * S_TOT, D_, D_, 0, 0);

    // MLP weights + MLP + pool + comp K/V
    {
        int f4 = (D_ * DFF) / 4;
        conv_f16<<<(f4 + 255) / 256, 256>>>(W1, W1H, f4);
        conv_f16<<<(f4 + 255) / 256, 256>>>(W2, W2H, f4);
    }
    hgemm2c<true, true, true, true><<<dim3(DFF / 128, CTX / 128, B_), 256, SMEM_TOTAL_GEMM>>>(
        hsH, hsL, W1H, b1, nullptr, mlpH, mlpL,
        CTX, DFF, D_, sTOK, (size_t)CTX * DFF);
    hgemm2c<false, true, false, true><<<dim3(D_ / 128, CTX / 128, B_), 256, SMEM_TOTAL_GEMM>>>(
        mlpH, mlpL, W2H, b2, comp_full, nullptr, nullptr,
        CTX, D_, DFF, (size_t)CTX * DFF, (size_t)CTX * D_);
    pool_mean_split<<<(B_ * POOL * D_) / 256, 256>>>(comp_full, cmpH, cmpL);
    hgemm2c<false, false, false, true><<<dim3(D_ / 128, (B_ * POOL) / 128, 1), 256, SMEM_TOTAL_GEMM>>>(
        cmpH, cmpL, WkH, nullptr, Kc, nullptr, nullptr, B_ * POOL, D_, D_, 0, 0);
    hgemm2c<false, false, false, true><<<dim3(D_ / 128, (B_ * POOL) / 128, 1), 256, SMEM_TOTAL_GEMM>>>(
        cmpH, cmpL, WvH, nullptr, Vc, nullptr, nullptr, B_ * POOL, D_, D_, 0, 0);

    // K,V on initial tokens (batched grid.z)
    hgemm2c<false, false, false, true><<<dim3(D_ / 128, CTX / 128, B_), 256, SMEM_TOTAL_GEMM>>>(
        hsH, hsL, WkH, nullptr, Kin, nullptr, nullptr,
        CTX, D_, D_, sTOK, (size_t)CTX * D_);
    hgemm2c<false, false, false, true><<<dim3(D_ / 128, CTX / 128, B_), 256, SMEM_TOTAL_GEMM>>>(
        hsH, hsL, WvH, nullptr, Vin, nullptr, nullptr,
        CTX, D_, D_, sTOK, (size_t)CTX * D_);

    // attention -> fp16-hi att
    cross_attn<<<dim3(REM / 128, NH, B_), 128>>>(Qb, Kc, Vc, attH);
    causal_attn<<<dim3(CTX / 128, NH, B_), 128>>>(Qb, Kin, Vin, attH);

    // output projection (single-term A) into d_out
    hgemm2c<false, false, false, false><<<dim3(D_ / 128, (B_ * S_TOT) / 128, 1), 256, SMEM_TOTAL_GEMM>>>(
        attH, nullptr, WoH, nullptr, out, nullptr, nullptr, B_ * S_TOT, D_, D_, 0, 0);

    (void)in_sizes; (void)n_in; (void)out_size;
}

// round 16
// speedup vs baseline: 1.5865x; 1.0457x over previous
#include <cuda_runtime.h>
#include <cuda_fp16.h>
#include <math.h>
#include <stdint.h>

#define B_    2
#define S_TOT 16384
#define D_    1024
#define CTX   1024
#define POOL  256
#define REM   15360
#define NH    16
#define HD    64
#define DFF   512

// ---------------- scratch (static device globals; no allocation) ----------------
__device__ float g_comp_full[B_ * CTX * D_];
__device__ float g_Q[(size_t)B_ * S_TOT * D_];
__device__ float g_Kinit[B_ * CTX * D_];
__device__ float g_Vinit[B_ * CTX * D_];
__device__ float g_Kcomp[B_ * POOL * D_];
__device__ float g_Vcomp[B_ * POOL * D_];

__device__ __half g_hs_h[(size_t)B_ * S_TOT * D_];
__device__ __half g_att_h[(size_t)B_ * S_TOT * D_];
__device__ __half g_mlp_h[B_ * CTX * DFF];
__device__ __half g_comp_h[B_ * POOL * D_];
__device__ __half g_Wq_h[D_ * D_];
__device__ __half g_Wk_h[D_ * D_];
__device__ __half g_Wv_h[D_ * D_];
__device__ __half g_Wo_h[D_ * D_];
__device__ __half g_W1_h[D_ * DFF];
__device__ __half g_W2_h[DFF * D_];

// ---------------- helpers --------------------------------------------------------
__device__ __forceinline__ uint32_t smem_u32(const void* p) {
    return (uint32_t)__cvta_generic_to_shared(p);
}
__device__ __forceinline__ void cpa16(uint32_t dst, const void* src) {
    asm volatile("cp.async.cg.shared.global [%0],[%1],16;" :: "r"(dst), "l"(src));
}
__device__ __forceinline__ void cp_commit() {
    asm volatile("cp.async.commit_group;");
}
template <int NG>
__device__ __forceinline__ void cp_wait() {
    asm volatile("cp.async.wait_group %0;" :: "n"(NG));
}
__device__ __forceinline__ void ldsm_x4(uint32_t& r0, uint32_t& r1,
                                        uint32_t& r2, uint32_t& r3, uint32_t a) {
    asm volatile("ldmatrix.sync.aligned.m8n8.x4.shared.b16 {%0,%1,%2,%3},[%4];"
                 : "=r"(r0), "=r"(r1), "=r"(r2), "=r"(r3) : "r"(a));
}
__device__ __forceinline__ void ldsm_x4t(uint32_t& r0, uint32_t& r1,
                                         uint32_t& r2, uint32_t& r3, uint32_t a) {
    asm volatile("ldmatrix.sync.aligned.m8n8.x4.trans.shared.b16 {%0,%1,%2,%3},[%4];"
                 : "=r"(r0), "=r"(r1), "=r"(r2), "=r"(r3) : "r"(a));
}
__device__ __forceinline__ void mma16816h(float* c, const uint32_t* a,
                                          uint32_t b0, uint32_t b1) {
    asm volatile(
        "mma.sync.aligned.m16n8k16.row.col.f32.f16.f16.f32 "
        "{%0,%1,%2,%3},{%4,%5,%6,%7},{%8,%9},{%0,%1,%2,%3};"
        : "+f"(c[0]), "+f"(c[1]), "+f"(c[2]), "+f"(c[3])
        : "r"(a[0]), "r"(a[1]), "r"(a[2]), "r"(a[3]), "r"(b0), "r"(b1));
}

// ---------------- fp32 -> fp16 convert, vectorized -------------------------------
__global__ void conv_f16(const float* __restrict__ src, __half* __restrict__ dst, int n4)
{
    int i = blockIdx.x * blockDim.x + threadIdx.x;
    if (i >= n4) return;
    float4 v = ((const float4*)src)[i];
    __half h[4];
    h[0] = __float2half_rn(v.x); h[1] = __float2half_rn(v.y);
    h[2] = __float2half_rn(v.z); h[3] = __float2half_rn(v.w);
    ((uint2*)dst)[i] = *(uint2*)h;
}

// ================= pure fp16 GEMM (fp32 accum), 2 CTAs/SM ========================
// C = A @ B, both operands single fp16. BM=BN=128, BK=32, 4-stage cp.async
// pipeline, 256 thr = 8 warps (4m x 2n), warp tile 32x64. smem 75776 -> 2 CTAs/SM.
// blockIdx.z = batch: A += z*strideA, C += z*strideC.
#define BK      32
#define LDA_S   40
#define LDB_S   136
#define A_BYTES (128 * LDA_S * 2)                 // 10240
#define B_BYTES (BK * LDB_S * 2)                  // 8704
#define OFF_B   A_BYTES
#define STAGE_BYTES (A_BYTES + B_BYTES)           // 18944
#define STAGES  4
#define SMEM_TOTAL_GEMM (STAGES * STAGE_BYTES)    // 75776

template <bool RELU, bool BIAS, bool OHALF>
__global__ __launch_bounds__(256, 2) void hgemm2c(
    const __half* __restrict__ Ah,
    const __half* __restrict__ Bh,
    const float* __restrict__ bias,
    float* __restrict__ C,
    __half* __restrict__ Ch,
    int M, int N, int K, size_t strideA, size_t strideC)
{
    extern __shared__ char smem[];
    const uint32_t sm_base = smem_u32(smem);

    const int tid = threadIdx.x;
    const int lane = tid & 31;
    const int wid = tid >> 5;
    const int wm = (wid & 3) * 32;
    const int wn = (wid >> 2) * 64;
    const int bm = blockIdx.y * 128;
    const int bn = blockIdx.x * 128;
    const size_t zA = (size_t)blockIdx.z * strideA;
    const size_t zC = (size_t)blockIdx.z * strideC;

    const int a_row = tid >> 1, a_col = (tid & 1) * 16;
    const int b_row = tid >> 3, b_col = (tid & 7) * 16;
    const __half* Ag = Ah + zA + (size_t)(bm + a_row) * K + a_col;
    const __half* Bg = Bh + (size_t)b_row * N + bn + b_col;
    const uint32_t a_dst = sm_base + a_row * (LDA_S * 2) + a_col * 2;
    const uint32_t b_dst = sm_base + b_row * (LDB_S * 2) + b_col * 2;

#define LOAD_STAGE(stg, k0)                                                    \
    {                                                                          \
        uint32_t sb = (stg) * STAGE_BYTES;                                     \
        const __half* ap = Ag + (k0);                                          \
        cpa16(a_dst + sb, ap);                 cpa16(a_dst + sb + 16, ap + 8); \
        const __half* bp = Bg + (size_t)(k0) * N;                              \
        cpa16(b_dst + sb + OFF_B, bp);         cpa16(b_dst + sb + OFF_B + 16, bp + 8); \
    }

    float acc[2][8][4];
#pragma unroll
    for (int i = 0; i < 2; i++)
#pragma unroll
        for (int j = 0; j < 8; j++)
#pragma unroll
            for (int r = 0; r < 4; r++) acc[i][j][r] = 0.f;

    const int ktiles = K / BK;

#pragma unroll
    for (int s = 0; s < STAGES - 1; s++) {
        if (s < ktiles) LOAD_STAGE(s, s * BK);
        cp_commit();
    }

    const int a_r = lane & 15, a_c8 = (lane >> 4) * 8;
    const int b_r = lane & 15, b_c8 = (lane >> 4) * 8;

    for (int it = 0; it < ktiles; it++) {
        cp_wait<STAGES - 2>();
        __syncthreads();

        if (it + STAGES - 1 < ktiles) {
            int ns = (it + STAGES - 1) % STAGES;
            LOAD_STAGE(ns, (it + STAGES - 1) * BK);
        }
        cp_commit();

        const uint32_t sb = sm_base + (it % STAGES) * STAGE_BYTES;
        const uint32_t ah_b = sb, bh_b = sb + OFF_B;

#pragma unroll
        for (int s = 0; s < 2; s++) {
            const int ks = s * 16;
            uint32_t ah[2][4], bb[4][4];
#pragma unroll
            for (int am = 0; am < 2; am++) {
                uint32_t addr = ah_b + ((wm + am * 16 + a_r) * LDA_S + ks + a_c8) * 2;
                ldsm_x4(ah[am][0], ah[am][1], ah[am][2], ah[am][3], addr);
            }
#pragma unroll
            for (int p = 0; p < 4; p++) {
                uint32_t addr = bh_b + ((ks + b_r) * LDB_S + wn + p * 16 + b_c8) * 2;
                ldsm_x4t(bb[p][0], bb[p][1], bb[p][2], bb[p][3], addr);
            }
#pragma unroll
            for (int am = 0; am < 2; am++)
#pragma unroll
                for (int p = 0; p < 4; p++) {
                    mma16816h(acc[am][p * 2 + 0], ah[am], bb[p][0], bb[p][1]);
                    mma16816h(acc[am][p * 2 + 1], ah[am], bb[p][2], bb[p][3]);
                }
        }
        __syncthreads();
    }

#pragma unroll
    for (int am = 0; am < 2; am++) {
        const int r0 = bm + wm + am * 16 + (lane >> 2);
#pragma unroll
        for (int an = 0; an < 8; an++) {
            const int c = bn + wn + an * 8 + (lane & 3) * 2;
            float v0 = acc[am][an][0], v1 = acc[am][an][1];
            float v2 = acc[am][an][2], v3 = acc[am][an][3];
            if (BIAS) {
                float bb0 = bias[c], bb1 = bias[c + 1];
                v0 += bb0; v1 += bb1; v2 += bb0; v3 += bb1;
            }
            if (RELU) {
                v0 = fmaxf(v0, 0.f); v1 = fmaxf(v1, 0.f);
                v2 = fmaxf(v2, 0.f); v3 = fmaxf(v3, 0.f);
            }
            if (OHALF) {
                size_t i0 = zC + (size_t)r0 * N + c, i1 = zC + (size_t)(r0 + 8) * N + c;
                __half2 hh;
                hh.x = __float2half_rn(v0); hh.y = __float2half_rn(v1);
                *(__half2*)(Ch + i0) = hh;
                hh.x = __float2half_rn(v2); hh.y = __float2half_rn(v3);
                *(__half2*)(Ch + i1) = hh;
            } else {
                float* p0 = C + zC + (size_t)r0 * N + c;
                float* p1 = C + zC + (size_t)(r0 + 8) * N + c;
                p0[0] = v0; p0[1] = v1;
                p1[0] = v2; p1[1] = v3;
            }
        }
    }
#undef LOAD_STAGE
}

// ---------------- pooling: mean over groups of 4 rows -> fp16 --------------------
__global__ void pool_mean_h(const float* __restrict__ full, __half* __restrict__ dst)
{
    int idx = blockIdx.x * blockDim.x + threadIdx.x;
    int d = idx % D_;
    int p = (idx / D_) % POOL;
    int b = idx / (D_ * POOL);
    const float* src = full + ((size_t)b * CTX + p * 4) * D_ + d;
    float v = 0.25f * (src[0] + src[D_] + src[2 * D_] + src[3 * D_]);
    dst[idx] = __float2half_rn(v);
}

// ---------------- attention (fp32 math, fp16 output) -----------------------------
__device__ __forceinline__ void attn_store_hi(
    __half* __restrict__ hi, size_t base, const float* o, float inv)
{
#pragma unroll
    for (int i = 0; i < HD; i += 4) {
        __half h[4];
#pragma unroll
        for (int j = 0; j < 4; j++) h[j] = __float2half_rn(o[i + j] * inv);
        *(uint2*)(hi + base + i) = *(uint2*)h;
    }
}

__global__ __launch_bounds__(128) void cross_attn(
    const float* __restrict__ Q, const float* __restrict__ K,
    const float* __restrict__ V, __half* __restrict__ Ohi)
{
    const int b = blockIdx.z, h = blockIdx.y;
    const int r = blockIdx.x * 128 + threadIdx.x;
    const size_t qrow = (size_t)b * S_TOT + CTX + r;

    const float* q = Q + qrow * D_ + h * HD;
    float qv[HD];
#pragma unroll
    for (int i = 0; i < HD; i += 4) {
        float4 t = *(const float4*)(q + i);
        qv[i] = t.x; qv[i + 1] = t.y; qv[i + 2] = t.z; qv[i + 3] = t.w;
    }

    const float* Kb = K + (size_t)b * POOL * D_ + h * HD;
    const float* Vb = V + (size_t)b * POOL * D_ + h * HD;

    float m = -1e30f, l = 0.f;
    float o[HD];
#pragma unroll
    for (int i = 0; i < HD; i++) o[i] = 0.f;

    for (int j = 0; j < POOL; j++) {
        const float* krow = Kb + (size_t)j * D_;
        float s0 = 0.f, s1 = 0.f, s2 = 0.f, s3 = 0.f;
#pragma unroll
        for (int i4 = 0; i4 < 16; i4++) {
            float4 k4 = *(const float4*)(krow + i4 * 4);
            s0 = fmaf(qv[i4 * 4 + 0], k4.x, s0);
            s1 = fmaf(qv[i4 * 4 + 1], k4.y, s1);
            s2 = fmaf(qv[i4 * 4 + 2], k4.z, s2);
            s3 = fmaf(qv[i4 * 4 + 3], k4.w, s3);
        }
        float s = ((s0 + s1) + (s2 + s3)) * 0.125f;

        float mn = fmaxf(m, s);
        float corr = __expf(m - mn);
        float p = __expf(s - mn);
        l = l * corr + p;
        m = mn;

        const float* vrow = Vb + (size_t)j * D_;
#pragma unroll
        for (int i4 = 0; i4 < 16; i4++) {
            float4 v4 = *(const float4*)(vrow + i4 * 4);
            o[i4 * 4 + 0] = o[i4 * 4 + 0] * corr + p * v4.x;
            o[i4 * 4 + 1] = o[i4 * 4 + 1] * corr + p * v4.y;
            o[i4 * 4 + 2] = o[i4 * 4 + 2] * corr + p * v4.z;
            o[i4 * 4 + 3] = o[i4 * 4 + 3] * corr + p * v4.w;
        }
    }
    attn_store_hi(Ohi, qrow * D_ + h * HD, o, 1.f / l);
}

__global__ __launch_bounds__(128) void causal_attn(
    const float* __restrict__ Q, const float* __restrict__ K,
    const float* __restrict__ V, __half* __restrict__ Ohi)
{
    const int b = blockIdx.z, h = blockIdx.y;
    const int qp = blockIdx.x * 128 + threadIdx.x;
    const size_t qrow = (size_t)b * S_TOT + qp;

    const float* q = Q + qrow * D_ + h * HD;
    float qv[HD];
#pragma unroll
    for (int i = 0; i < HD; i += 4) {
        float4 t = *(const float4*)(q + i);
        qv[i] = t.x; qv[i + 1] = t.y; qv[i + 2] = t.z; qv[i + 3] = t.w;
    }

    const float* Kb = K + (size_t)b * CTX * D_ + h * HD;
    const float* Vb = V + (size_t)b * CTX * D_ + h * HD;

    float m = -1e30f, l = 0.f;
    float o[HD];
#pragma unroll
    for (int i = 0; i < HD; i++) o[i] = 0.f;

    for (int j = 0; j <= qp; j++) {
        const float* krow = Kb + (size_t)j * D_;
        float s0 = 0.f, s1 = 0.f, s2 = 0.f, s3 = 0.f;
#pragma unroll
        for (int i4 = 0; i4 < 16; i4++) {
            float4 k4 = *(const float4*)(krow + i4 * 4);
            s0 = fmaf(qv[i4 * 4 + 0], k4.x, s0);
            s1 = fmaf(qv[i4 * 4 + 1], k4.y, s1);
            s2 = fmaf(qv[i4 * 4 + 2], k4.z, s2);
            s3 = fmaf(qv[i4 * 4 + 3], k4.w, s3);
        }
        float s = ((s0 + s1) + (s2 + s3)) * 0.125f;

        float mn = fmaxf(m, s);
        float corr = __expf(m - mn);
        float p = __expf(s - mn);
        l = l * corr + p;
        m = mn;

        const float* vrow = Vb + (size_t)j * D_;
#pragma unroll
        for (int i4 = 0; i4 < 16; i4++) {
            float4 v4 = *(const float4*)(vrow + i4 * 4);
            o[i4 * 4 + 0] = o[i4 * 4 + 0] * corr + p * v4.x;
            o[i4 * 4 + 1] = o[i4 * 4 + 1] * corr + p * v4.y;
            o[i4 * 4 + 2] = o[i4 * 4 + 2] * corr + p * v4.z;
            o[i4 * 4 + 3] = o[i4 * 4 + 3] * corr + p * v4.w;
        }
    }
    attn_store_hi(Ohi, qrow * D_ + h * HD, o, 1.f / l);
}

// ---------------- host launcher (single stream; known-good structure) ------------
extern "C" void kernel_launch(void* const* d_in, const int* in_sizes, int n_in,
                              void* d_out, int out_size)
{
    const float* hs = (const float*)d_in[0];
    const float* Wq = (const float*)d_in[1];
    const float* Wk = (const float*)d_in[2];
    const float* Wv = (const float*)d_in[3];
    const float* Wo = (const float*)d_in[4];
    const float* W1 = (const float*)d_in[5];
    const float* b1 = (const float*)d_in[6];
    const float* W2 = (const float*)d_in[7];
    const float* b2 = (const float*)d_in[8];
    float* out = (float*)d_out;

    float *comp_full, *Qb, *Kin, *Vin, *Kc, *Vc;
    __half *hsH, *attH, *mlpH, *cmpH;
    __half *WqH, *WkH, *WvH, *WoH, *W1H, *W2H;
    cudaGetSymbolAddress((void**)&comp_full, g_comp_full);
    cudaGetSymbolAddress((void**)&Qb, g_Q);
    cudaGetSymbolAddress((void**)&Kin, g_Kinit);
    cudaGetSymbolAddress((void**)&Vin, g_Vinit);
    cudaGetSymbolAddress((void**)&Kc, g_Kcomp);
    cudaGetSymbolAddress((void**)&Vc, g_Vcomp);
    cudaGetSymbolAddress((void**)&hsH, g_hs_h);
    cudaGetSymbolAddress((void**)&attH, g_att_h);
    cudaGetSymbolAddress((void**)&mlpH, g_mlp_h);
    cudaGetSymbolAddress((void**)&cmpH, g_comp_h);
    cudaGetSymbolAddress((void**)&WqH, g_Wq_h);
    cudaGetSymbolAddress((void**)&WkH, g_Wk_h);
    cudaGetSymbolAddress((void**)&WvH, g_Wv_h);
    cudaGetSymbolAddress((void**)&WoH, g_Wo_h);
    cudaGetSymbolAddress((void**)&W1H, g_W1_h);
    cudaGetSymbolAddress((void**)&W2H, g_W2_h);

    cudaFuncSetAttribute(hgemm2c<false, false, false>,
                         cudaFuncAttributeMaxDynamicSharedMemorySize, SMEM_TOTAL_GEMM);
    cudaFuncSetAttribute(hgemm2c<true, true, true>,
                         cudaFuncAttributeMaxDynamicSharedMemorySize, SMEM_TOTAL_GEMM);
    cudaFuncSetAttribute(hgemm2c<false, true, false>,
                         cudaFuncAttributeMaxDynamicSharedMemorySize, SMEM_TOTAL_GEMM);

    const size_t sTOK = (size_t)S_TOT * D_;

    // #1..#5: convert hs + attention weights to fp16
    {
        int n4 = (B_ * S_TOT * D_) / 4;
        conv_f16<<<(n4 + 255) / 256, 256>>>(hs, hsH, n4);             // #1
        int w4 = (D_ * D_) / 4;
        conv_f16<<<(w4 + 255) / 256, 256>>>(Wq, WqH, w4);             // #2
        conv_f16<<<(w4 + 255) / 256, 256>>>(Wk, WkH, w4);             // #3
        conv_f16<<<(w4 + 255) / 256, 256>>>(Wv, WvH, w4);             // #4
        conv_f16<<<(w4 + 255) / 256, 256>>>(Wo, WoH, w4);             // #5
    }

    // #6: BIG Q projection (all 32768 rows)
    hgemm2c<false, false, false><<<dim3(D_ / 128, (B_ * S_TOT) / 128, 1), 256, SMEM_TOTAL_GEMM>>>(
        hsH, WqH, nullptr, Qb, nullptr, B_ * S_TOT, D_, D_, 0, 0);

    // MLP weights + MLP + pool + comp K/V
    {
        int f4 = (D_ * DFF) / 4;
        conv_f16<<<(f4 + 255) / 256, 256>>>(W1, W1H, f4);
        conv_f16<<<(f4 + 255) / 256, 256>>>(W2, W2H, f4);
    }
    hgemm2c<true, true, true><<<dim3(DFF / 128, CTX / 128, B_), 256, SMEM_TOTAL_GEMM>>>(
        hsH, W1H, b1, nullptr, mlpH,
        CTX, DFF, D_, sTOK, (size_t)CTX * DFF);
    hgemm2c<false, true, false><<<dim3(D_ / 128, CTX / 128, B_), 256, SMEM_TOTAL_GEMM>>>(
        mlpH, W2H, b2, comp_full, nullptr,
        CTX, D_, DFF, (size_t)CTX * DFF, (size_t)CTX * D_);
    pool_mean_h<<<(B_ * POOL * D_) / 256, 256>>>(comp_full, cmpH);
    hgemm2c<false, false, false><<<dim3(D_ / 128, (B_ * POOL) / 128, 1), 256, SMEM_TOTAL_GEMM>>>(
        cmpH, WkH, nullptr, Kc, nullptr, B_ * POOL, D_, D_, 0, 0);
    hgemm2c<false, false, false><<<dim3(D_ / 128, (B_ * POOL) / 128, 1), 256, SMEM_TOTAL_GEMM>>>(
        cmpH, WvH, nullptr, Vc, nullptr, B_ * POOL, D_, D_, 0, 0);

    // K,V on initial tokens (batched grid.z)
    hgemm2c<false, false, false><<<dim3(D_ / 128, CTX / 128, B_), 256, SMEM_TOTAL_GEMM>>>(
        hsH, WkH, nullptr, Kin, nullptr,
        CTX, D_, D_, sTOK, (size_t)CTX * D_);
    hgemm2c<false, false, false><<<dim3(D_ / 128, CTX / 128, B_), 256, SMEM_TOTAL_GEMM>>>(
        hsH, WvH, nullptr, Vin, nullptr,
        CTX, D_, D_, sTOK, (size_t)CTX * D_);

    // attention -> fp16 att
    cross_attn<<<dim3(REM / 128, NH, B_), 128>>>(Qb, Kc, Vc, attH);
    causal_attn<<<dim3(CTX / 128, NH, B_), 128>>>(Qb, Kin, Vin, attH);

    // output projection into d_out
    hgemm2c<false, false, false><<<dim3(D_ / 128, (B_ * S_TOT) / 128, 1), 256, SMEM_TOTAL_GEMM>>>(
        attH, WoH, nullptr, out, nullptr, B_ * S_TOT, D_, D_, 0, 0);

    (void)in_sizes; (void)n_in; (void)out_size;
}

// round 17
// speedup vs baseline: 3.7048x; 2.3351x over previous
#include <cuda_runtime.h>
#include <cuda_fp16.h>
#include <math.h>
#include <stdint.h>

#define B_    2
#define S_TOT 16384
#define D_    1024
#define CTX   1024
#define POOL  256
#define REM   15360
#define NH    16
#define HD    64
#define DFF   512

// ---------------- scratch (static device globals; no allocation) ----------------
__device__ float g_comp_full[B_ * CTX * D_];
__device__ float g_Kinit[B_ * CTX * D_];
__device__ float g_Vinit[B_ * CTX * D_];

__device__ __half g_Q_h[(size_t)B_ * S_TOT * D_];
__device__ __half g_hs_h[(size_t)B_ * S_TOT * D_];
__device__ __half g_att_h[(size_t)B_ * S_TOT * D_];
__device__ __half g_mlp_h[B_ * CTX * DFF];
__device__ __half g_comp_h[B_ * POOL * D_];
__device__ __half g_Kc_h[B_ * POOL * D_];
__device__ __half g_Vc_h[B_ * POOL * D_];
__device__ __half g_Wq_h[D_ * D_];
__device__ __half g_Wk_h[D_ * D_];
__device__ __half g_Wv_h[D_ * D_];
__device__ __half g_Wo_h[D_ * D_];
__device__ __half g_W1_h[D_ * DFF];
__device__ __half g_W2_h[DFF * D_];

// ---------------- helpers --------------------------------------------------------
__device__ __forceinline__ uint32_t smem_u32(const void* p) {
    return (uint32_t)__cvta_generic_to_shared(p);
}
__device__ __forceinline__ void cpa16(uint32_t dst, const void* src) {
    asm volatile("cp.async.cg.shared.global [%0],[%1],16;" :: "r"(dst), "l"(src));
}
__device__ __forceinline__ void cp_commit() {
    asm volatile("cp.async.commit_group;");
}
template <int NG>
__device__ __forceinline__ void cp_wait() {
    asm volatile("cp.async.wait_group %0;" :: "n"(NG));
}
__device__ __forceinline__ void ldsm_x4(uint32_t& r0, uint32_t& r1,
                                        uint32_t& r2, uint32_t& r3, uint32_t a) {
    asm volatile("ldmatrix.sync.aligned.m8n8.x4.shared.b16 {%0,%1,%2,%3},[%4];"
                 : "=r"(r0), "=r"(r1), "=r"(r2), "=r"(r3) : "r"(a));
}
__device__ __forceinline__ void ldsm_x4t(uint32_t& r0, uint32_t& r1,
                                         uint32_t& r2, uint32_t& r3, uint32_t a) {
    asm volatile("ldmatrix.sync.aligned.m8n8.x4.trans.shared.b16 {%0,%1,%2,%3},[%4];"
                 : "=r"(r0), "=r"(r1), "=r"(r2), "=r"(r3) : "r"(a));
}
__device__ __forceinline__ void mma16816h(float* c, const uint32_t* a,
                                          uint32_t b0, uint32_t b1) {
    asm volatile(
        "mma.sync.aligned.m16n8k16.row.col.f32.f16.f16.f32 "
        "{%0,%1,%2,%3},{%4,%5,%6,%7},{%8,%9},{%0,%1,%2,%3};"
        : "+f"(c[0]), "+f"(c[1]), "+f"(c[2]), "+f"(c[3])
        : "r"(a[0]), "r"(a[1]), "r"(a[2]), "r"(a[3]), "r"(b0), "r"(b1));
}
__device__ __forceinline__ uint32_t pack_h2(float a, float b) {
    __half2 h; h.x = __float2half_rn(a); h.y = __float2half_rn(b);
    return *(uint32_t*)&h;
}

// ---------------- fp32 -> fp16 convert, vectorized -------------------------------
__global__ void conv_f16(const float* __restrict__ src, __half* __restrict__ dst, int n4)
{
    int i = blockIdx.x * blockDim.x + threadIdx.x;
    if (i >= n4) return;
    float4 v = ((const float4*)src)[i];
    __half h[4];
    h[0] = __float2half_rn(v.x); h[1] = __float2half_rn(v.y);
    h[2] = __float2half_rn(v.z); h[3] = __float2half_rn(v.w);
    ((uint2*)dst)[i] = *(uint2*)h;
}

// ================= pure fp16 GEMM (fp32 accum), 2 CTAs/SM ========================
#define BK      32
#define LDA_S   40
#define LDB_S   136
#define A_BYTES (128 * LDA_S * 2)
#define B_BYTES (BK * LDB_S * 2)
#define OFF_B   A_BYTES
#define STAGE_BYTES (A_BYTES + B_BYTES)           // 18944
#define STAGES  4
#define SMEM_TOTAL_GEMM (STAGES * STAGE_BYTES)    // 75776

template <bool RELU, bool BIAS, bool OHALF>
__global__ __launch_bounds__(256, 2) void hgemm2c(
    const __half* __restrict__ Ah,
    const __half* __restrict__ Bh,
    const float* __restrict__ bias,
    float* __restrict__ C,
    __half* __restrict__ Ch,
    int M, int N, int K, size_t strideA, size_t strideC)
{
    extern __shared__ char smem[];
    const uint32_t sm_base = smem_u32(smem);

    const int tid = threadIdx.x;
    const int lane = tid & 31;
    const int wid = tid >> 5;
    const int wm = (wid & 3) * 32;
    const int wn = (wid >> 2) * 64;
    const int bm = blockIdx.y * 128;
    const int bn = blockIdx.x * 128;
    const size_t zA = (size_t)blockIdx.z * strideA;
    const size_t zC = (size_t)blockIdx.z * strideC;

    const int a_row = tid >> 1, a_col = (tid & 1) * 16;
    const int b_row = tid >> 3, b_col = (tid & 7) * 16;
    const __half* Ag = Ah + zA + (size_t)(bm + a_row) * K + a_col;
    const __half* Bg = Bh + (size_t)b_row * N + bn + b_col;
    const uint32_t a_dst = sm_base + a_row * (LDA_S * 2) + a_col * 2;
    const uint32_t b_dst = sm_base + b_row * (LDB_S * 2) + b_col * 2;

#define LOAD_STAGE(stg, k0)                                                    \
    {                                                                          \
        uint32_t sb = (stg) * STAGE_BYTES;                                     \
        const __half* ap = Ag + (k0);                                          \
        cpa16(a_dst + sb, ap);                 cpa16(a_dst + sb + 16, ap + 8); \
        const __half* bp = Bg + (size_t)(k0) * N;                              \
        cpa16(b_dst + sb + OFF_B, bp);         cpa16(b_dst + sb + OFF_B + 16, bp + 8); \
    }

    float acc[2][8][4];
#pragma unroll
    for (int i = 0; i < 2; i++)
#pragma unroll
        for (int j = 0; j < 8; j++)
#pragma unroll
            for (int r = 0; r < 4; r++) acc[i][j][r] = 0.f;

    const int ktiles = K / BK;

#pragma unroll
    for (int s = 0; s < STAGES - 1; s++) {
        if (s < ktiles) LOAD_STAGE(s, s * BK);
        cp_commit();
    }

    const int a_r = lane & 15, a_c8 = (lane >> 4) * 8;
    const int b_r = lane & 15, b_c8 = (lane >> 4) * 8;

    for (int it = 0; it < ktiles; it++) {
        cp_wait<STAGES - 2>();
        __syncthreads();

        if (it + STAGES - 1 < ktiles) {
            int ns = (it + STAGES - 1) % STAGES;
            LOAD_STAGE(ns, (it + STAGES - 1) * BK);
        }
        cp_commit();

        const uint32_t sb = sm_base + (it % STAGES) * STAGE_BYTES;
        const uint32_t ah_b = sb, bh_b = sb + OFF_B;

#pragma unroll
        for (int s = 0; s < 2; s++) {
            const int ks = s * 16;
            uint32_t ah[2][4], bb[4][4];
#pragma unroll
            for (int am = 0; am < 2; am++) {
                uint32_t addr = ah_b + ((wm + am * 16 + a_r) * LDA_S + ks + a_c8) * 2;
                ldsm_x4(ah[am][0], ah[am][1], ah[am][2], ah[am][3], addr);
            }
#pragma unroll
            for (int p = 0; p < 4; p++) {
                uint32_t addr = bh_b + ((ks + b_r) * LDB_S + wn + p * 16 + b_c8) * 2;
                ldsm_x4t(bb[p][0], bb[p][1], bb[p][2], bb[p][3], addr);
            }
#pragma unroll
            for (int am = 0; am < 2; am++)
#pragma unroll
                for (int p = 0; p < 4; p++) {
                    mma16816h(acc[am][p * 2 + 0], ah[am], bb[p][0], bb[p][1]);
                    mma16816h(acc[am][p * 2 + 1], ah[am], bb[p][2], bb[p][3]);
                }
        }
        __syncthreads();
    }

#pragma unroll
    for (int am = 0; am < 2; am++) {
        const int r0 = bm + wm + am * 16 + (lane >> 2);
#pragma unroll
        for (int an = 0; an < 8; an++) {
            const int c = bn + wn + an * 8 + (lane & 3) * 2;
            float v0 = acc[am][an][0], v1 = acc[am][an][1];
            float v2 = acc[am][an][2], v3 = acc[am][an][3];
            if (BIAS) {
                float bb0 = bias[c], bb1 = bias[c + 1];
                v0 += bb0; v1 += bb1; v2 += bb0; v3 += bb1;
            }
            if (RELU) {
                v0 = fmaxf(v0, 0.f); v1 = fmaxf(v1, 0.f);
                v2 = fmaxf(v2, 0.f); v3 = fmaxf(v3, 0.f);
            }
            if (OHALF) {
                size_t i0 = zC + (size_t)r0 * N + c, i1 = zC + (size_t)(r0 + 8) * N + c;
                *(uint32_t*)(Ch + i0) = pack_h2(v0, v1);
                *(uint32_t*)(Ch + i1) = pack_h2(v2, v3);
            } else {
                float* p0 = C + zC + (size_t)r0 * N + c;
                float* p1 = C + zC + (size_t)(r0 + 8) * N + c;
                p0[0] = v0; p0[1] = v1;
                p1[0] = v2; p1[1] = v3;
            }
        }
    }
#undef LOAD_STAGE
}

// ---------------- pooling: mean over groups of 4 rows -> fp16 --------------------
__global__ void pool_mean_h(const float* __restrict__ full, __half* __restrict__ dst)
{
    int idx = blockIdx.x * blockDim.x + threadIdx.x;
    int d = idx % D_;
    int p = (idx / D_) % POOL;
    int b = idx / (D_ * POOL);
    const float* src = full + ((size_t)b * CTX + p * 4) * D_ + d;
    float v = 0.25f * (src[0] + src[D_] + src[2 * D_] + src[3 * D_]);
    dst[idx] = __float2half_rn(v);
}

// ================= tensor-core cross attention ===================================
// One CTA = 256 queries x 1 head. K/V: 256 keys in 4 chunks of 64, double-buffered.
// S = Q@K^T (fp16 mma, fp32 accum), online softmax in C-fragment layout,
// P kept in registers via C-frag -> A-frag identity, O += P@V.
#define LDH   72
#define ROWB  (LDH * 2)                    // 144 bytes per smem row
#define XA_Q_OFF 0                         // 256 rows
#define XA_KV_OFF (256 * ROWB)             // 36864
#define XA_STAGE (2 * 64 * ROWB)           // K+V chunk = 18432
#define XA_SMEM (XA_KV_OFF + 2 * XA_STAGE) // 73728

__global__ __launch_bounds__(256) void xattn_tc(
    const __half* __restrict__ Qh, const __half* __restrict__ Kc,
    const __half* __restrict__ Vc, __half* __restrict__ Ohi)
{
    extern __shared__ char smem[];
    const uint32_t sb = smem_u32(smem);
    const int tid = threadIdx.x, lane = tid & 31, wid = tid >> 5;
    const int b = blockIdx.z, h = blockIdx.y;
    const int q0 = blockIdx.x * 256;
    const size_t qbase = ((size_t)b * S_TOT + CTX + q0) * D_ + h * HD;
    const size_t kvbase = ((size_t)b * POOL) * D_ + h * HD;

    // Q tile load: thread tid -> row tid (8 x 16B)
    {
        const __half* src = Qh + qbase + (size_t)tid * D_;
        uint32_t dst = sb + XA_Q_OFF + tid * ROWB;
#pragma unroll
        for (int s = 0; s < 8; s++) cpa16(dst + s * 16, src + s * 8);
    }
    cp_commit();                                    // group: Q

#define XA_LOAD(c, stg)                                                        \
    {                                                                          \
        int row = tid >> 2;                                                    \
        int sg = (tid & 3) * 2;                                                \
        const __half* ksrc = Kc + kvbase + (size_t)((c) * 64 + row) * D_ + sg * 8; \
        const __half* vsrc = Vc + kvbase + (size_t)((c) * 64 + row) * D_ + sg * 8; \
        uint32_t kd = sb + XA_KV_OFF + (stg) * XA_STAGE + row * ROWB + sg * 16; \
        uint32_t vd = kd + 64 * ROWB;                                          \
        cpa16(kd, ksrc); cpa16(kd + 16, ksrc + 8);                             \
        cpa16(vd, vsrc); cpa16(vd + 16, vsrc + 8);                             \
    }

    XA_LOAD(0, 0);
    cp_commit();                                    // group: chunk0

    cp_wait<1>();                                   // Q ready
    __syncthreads();

    const int fr = lane & 15, fc8 = (lane >> 4) * 8;

    // Q fragments (held whole kernel)
    uint32_t q[2][4][4];
#pragma unroll
    for (int am = 0; am < 2; am++)
#pragma unroll
        for (int kk = 0; kk < 4; kk++) {
            uint32_t addr = sb + XA_Q_OFF + (wid * 32 + am * 16 + fr) * ROWB
                          + (kk * 16 + fc8) * 2;
            ldsm_x4(q[am][kk][0], q[am][kk][1], q[am][kk][2], q[am][kk][3], addr);
        }

    float m0[2] = {-1e30f, -1e30f}, m1[2] = {-1e30f, -1e30f};
    float l0[2] = {0.f, 0.f}, l1[2] = {0.f, 0.f};
    float o[2][8][4];
#pragma unroll
    for (int am = 0; am < 2; am++)
#pragma unroll
        for (int an = 0; an < 8; an++)
#pragma unroll
            for (int r = 0; r < 4; r++) o[am][an][r] = 0.f;

    for (int c = 0; c < 4; c++) {
        cp_wait<0>();
        __syncthreads();
        if (c < 3) XA_LOAD(c + 1, (c + 1) & 1);
        cp_commit();

        const uint32_t kbuf = sb + XA_KV_OFF + (c & 1) * XA_STAGE;
        const uint32_t vbuf = kbuf + 64 * ROWB;

        // ---- S = Q @ K^T ----
        float s[2][8][4];
#pragma unroll
        for (int am = 0; am < 2; am++)
#pragma unroll
            for (int an = 0; an < 8; an++)
#pragma unroll
                for (int r = 0; r < 4; r++) s[am][an][r] = 0.f;

#pragma unroll
        for (int kk = 0; kk < 4; kk++) {
            uint32_t kr[4][4];
#pragma unroll
            for (int p = 0; p < 4; p++) {
                uint32_t addr = kbuf + (p * 16 + fr) * ROWB + (kk * 16 + fc8) * 2;
                ldsm_x4(kr[p][0], kr[p][1], kr[p][2], kr[p][3], addr);
            }
#pragma unroll
            for (int am = 0; am < 2; am++)
#pragma unroll
                for (int p = 0; p < 4; p++) {
                    mma16816h(s[am][2 * p + 0], q[am][kk], kr[p][0], kr[p][2]);
                    mma16816h(s[am][2 * p + 1], q[am][kk], kr[p][1], kr[p][3]);
                }
        }

        // ---- online softmax + P packing ----
        uint32_t ph[2][4][4];
#pragma unroll
        for (int am = 0; am < 2; am++) {
            // scale
#pragma unroll
            for (int an = 0; an < 8; an++)
#pragma unroll
                for (int r = 0; r < 4; r++) s[am][an][r] *= 0.125f;
            // chunk max per row (r: elems 0,1 ; r+8: elems 2,3)
            float cm0 = -1e30f, cm1 = -1e30f;
#pragma unroll
            for (int an = 0; an < 8; an++) {
                cm0 = fmaxf(cm0, fmaxf(s[am][an][0], s[am][an][1]));
                cm1 = fmaxf(cm1, fmaxf(s[am][an][2], s[am][an][3]));
            }
            cm0 = fmaxf(cm0, __shfl_xor_sync(0xffffffff, cm0, 1));
            cm0 = fmaxf(cm0, __shfl_xor_sync(0xffffffff, cm0, 2));
            cm1 = fmaxf(cm1, __shfl_xor_sync(0xffffffff, cm1, 1));
            cm1 = fmaxf(cm1, __shfl_xor_sync(0xffffffff, cm1, 2));

            float nm0 = fmaxf(m0[am], cm0), nm1 = fmaxf(m1[am], cm1);
            float corr0 = __expf(m0[am] - nm0), corr1 = __expf(m1[am] - nm1);
            m0[am] = nm0; m1[am] = nm1;

            float sum0 = 0.f, sum1 = 0.f;
#pragma unroll
            for (int an = 0; an < 8; an++) {
                float p0 = __expf(s[am][an][0] - nm0);
                float p1 = __expf(s[am][an][1] - nm0);
                float p2 = __expf(s[am][an][2] - nm1);
                float p3 = __expf(s[am][an][3] - nm1);
                s[am][an][0] = p0; s[am][an][1] = p1;
                s[am][an][2] = p2; s[am][an][3] = p3;
                sum0 += p0 + p1; sum1 += p2 + p3;
            }
            sum0 += __shfl_xor_sync(0xffffffff, sum0, 1);
            sum0 += __shfl_xor_sync(0xffffffff, sum0, 2);
            sum1 += __shfl_xor_sync(0xffffffff, sum1, 1);
            sum1 += __shfl_xor_sync(0xffffffff, sum1, 2);
            l0[am] = l0[am] * corr0 + sum0;
            l1[am] = l1[am] * corr1 + sum1;

            // rescale O
#pragma unroll
            for (int an = 0; an < 8; an++) {
                o[am][an][0] *= corr0; o[am][an][1] *= corr0;
                o[am][an][2] *= corr1; o[am][an][3] *= corr1;
            }
            // C-frag -> A-frag packing: k-step j covers key cols 16j..16j+15
#pragma unroll
            for (int j = 0; j < 4; j++) {
                ph[am][j][0] = pack_h2(s[am][2 * j][0], s[am][2 * j][1]);
                ph[am][j][1] = pack_h2(s[am][2 * j][2], s[am][2 * j][3]);
                ph[am][j][2] = pack_h2(s[am][2 * j + 1][0], s[am][2 * j + 1][1]);
                ph[am][j][3] = pack_h2(s[am][2 * j + 1][2], s[am][2 * j + 1][3]);
            }
        }

        // ---- O += P @ V ----
#pragma unroll
        for (int kk = 0; kk < 4; kk++) {
            uint32_t vr[4][4];
#pragma unroll
            for (int p = 0; p < 4; p++) {
                uint32_t addr = vbuf + (kk * 16 + fr) * ROWB + (p * 16 + fc8) * 2;
                ldsm_x4t(vr[p][0], vr[p][1], vr[p][2], vr[p][3], addr);
            }
#pragma unroll
            for (int am = 0; am < 2; am++)
#pragma unroll
                for (int p = 0; p < 4; p++) {
                    mma16816h(o[am][2 * p + 0], ph[am][kk], vr[p][0], vr[p][1]);
                    mma16816h(o[am][2 * p + 1], ph[am][kk], vr[p][2], vr[p][3]);
                }
        }
    }

    // ---- epilogue: O / l -> fp16 ----
#pragma unroll
    for (int am = 0; am < 2; am++) {
        const int row = q0 + wid * 32 + am * 16 + (lane >> 2);
        const float i0 = 1.f / l0[am], i1 = 1.f / l1[am];
        const size_t b0 = ((size_t)b * S_TOT + CTX + row) * D_ + h * HD;
        const size_t b1 = b0 + 8 * D_;
#pragma unroll
        for (int an = 0; an < 8; an++) {
            const int col = an * 8 + (lane & 3) * 2;
            *(uint32_t*)(Ohi + b0 + col) = pack_h2(o[am][an][0] * i0, o[am][an][1] * i0);
            *(uint32_t*)(Ohi + b1 + col) = pack_h2(o[am][an][2] * i1, o[am][an][3] * i1);
        }
    }
#undef XA_LOAD
}

// ---------------- causal self attention (fp16 Q, fp32 K/V, fp16 out) -------------
__global__ __launch_bounds__(128) void causal_attn(
    const __half* __restrict__ Qh, const float* __restrict__ K,
    const float* __restrict__ V, __half* __restrict__ Ohi)
{
    const int b = blockIdx.z, h = blockIdx.y;
    const int qp = blockIdx.x * 128 + threadIdx.x;
    const size_t qrow = (size_t)b * S_TOT + qp;

    const __half* q = Qh + qrow * D_ + h * HD;
    float qv[HD];
#pragma unroll
    for (int i = 0; i < HD; i += 8) {
        uint4 u = *(const uint4*)(q + i);
        const __half2* hp = (const __half2*)&u;
#pragma unroll
        for (int j = 0; j < 4; j++) {
            float2 f = __half22float2(hp[j]);
            qv[i + 2 * j] = f.x; qv[i + 2 * j + 1] = f.y;
        }
    }

    const float* Kb = K + (size_t)b * CTX * D_ + h * HD;
    const float* Vb = V + (size_t)b * CTX * D_ + h * HD;

    float m = -1e30f, l = 0.f;
    float o[HD];
#pragma unroll
    for (int i = 0; i < HD; i++) o[i] = 0.f;

    for (int j = 0; j <= qp; j++) {
        const float* krow = Kb + (size_t)j * D_;
        float s0 = 0.f, s1 = 0.f, s2 = 0.f, s3 = 0.f;
#pragma unroll
        for (int i4 = 0; i4 < 16; i4++) {
            float4 k4 = *(const float4*)(krow + i4 * 4);
            s0 = fmaf(qv[i4 * 4 + 0], k4.x, s0);
            s1 = fmaf(qv[i4 * 4 + 1], k4.y, s1);
            s2 = fmaf(qv[i4 * 4 + 2], k4.z, s2);
            s3 = fmaf(qv[i4 * 4 + 3], k4.w, s3);
        }
        float s = ((s0 + s1) + (s2 + s3)) * 0.125f;

        float mn = fmaxf(m, s);
        float corr = __expf(m - mn);
        float p = __expf(s - mn);
        l = l * corr + p;
        m = mn;

        const float* vrow = Vb + (size_t)j * D_;
#pragma unroll
        for (int i4 = 0; i4 < 16; i4++) {
            float4 v4 = *(const float4*)(vrow + i4 * 4);
            o[i4 * 4 + 0] = o[i4 * 4 + 0] * corr + p * v4.x;
            o[i4 * 4 + 1] = o[i4 * 4 + 1] * corr + p * v4.y;
            o[i4 * 4 + 2] = o[i4 * 4 + 2] * corr + p * v4.z;
            o[i4 * 4 + 3] = o[i4 * 4 + 3] * corr + p * v4.w;
        }
    }
    float inv = 1.f / l;
    __half* op = Ohi + qrow * D_ + h * HD;
#pragma unroll
    for (int i = 0; i < HD; i += 2)
        *(uint32_t*)(op + i) = pack_h2(o[i] * inv, o[i + 1] * inv);
}

// ---------------- host launcher --------------------------------------------------
extern "C" void kernel_launch(void* const* d_in, const int* in_sizes, int n_in,
                              void* d_out, int out_size)
{
    const float* hs = (const float*)d_in[0];
    const float* Wq = (const float*)d_in[1];
    const float* Wk = (const float*)d_in[2];
    const float* Wv = (const float*)d_in[3];
    const float* Wo = (const float*)d_in[4];
    const float* W1 = (const float*)d_in[5];
    const float* b1 = (const float*)d_in[6];
    const float* W2 = (const float*)d_in[7];
    const float* b2 = (const float*)d_in[8];
    float* out = (float*)d_out;

    float *comp_full, *Kin, *Vin;
    __half *QbH, *hsH, *attH, *mlpH, *cmpH, *KcH, *VcH;
    __half *WqH, *WkH, *WvH, *WoH, *W1H, *W2H;
    cudaGetSymbolAddress((void**)&comp_full, g_comp_full);
    cudaGetSymbolAddress((void**)&Kin, g_Kinit);
    cudaGetSymbolAddress((void**)&Vin, g_Vinit);
    cudaGetSymbolAddress((void**)&QbH, g_Q_h);
    cudaGetSymbolAddress((void**)&hsH, g_hs_h);
    cudaGetSymbolAddress((void**)&attH, g_att_h);
    cudaGetSymbolAddress((void**)&mlpH, g_mlp_h);
    cudaGetSymbolAddress((void**)&cmpH, g_comp_h);
    cudaGetSymbolAddress((void**)&KcH, g_Kc_h);
    cudaGetSymbolAddress((void**)&VcH, g_Vc_h);
    cudaGetSymbolAddress((void**)&WqH, g_Wq_h);
    cudaGetSymbolAddress((void**)&WkH, g_Wk_h);
    cudaGetSymbolAddress((void**)&WvH, g_Wv_h);
    cudaGetSymbolAddress((void**)&WoH, g_Wo_h);
    cudaGetSymbolAddress((void**)&W1H, g_W1_h);
    cudaGetSymbolAddress((void**)&W2H, g_W2_h);

    cudaFuncSetAttribute(hgemm2c<false, false, false>,
                         cudaFuncAttributeMaxDynamicSharedMemorySize, SMEM_TOTAL_GEMM);
    cudaFuncSetAttribute(hgemm2c<false, false, true>,
                         cudaFuncAttributeMaxDynamicSharedMemorySize, SMEM_TOTAL_GEMM);
    cudaFuncSetAttribute(hgemm2c<true, true, true>,
                         cudaFuncAttributeMaxDynamicSharedMemorySize, SMEM_TOTAL_GEMM);
    cudaFuncSetAttribute(hgemm2c<false, true, false>,
                         cudaFuncAttributeMaxDynamicSharedMemorySize, SMEM_TOTAL_GEMM);
    cudaFuncSetAttribute(xattn_tc,
                         cudaFuncAttributeMaxDynamicSharedMemorySize, XA_SMEM);

    const size_t sTOK = (size_t)S_TOT * D_;

    // #1..#5: convert hs + attention weights
    {
        int n4 = (B_ * S_TOT * D_) / 4;
        conv_f16<<<(n4 + 255) / 256, 256>>>(hs, hsH, n4);             // #1
        int w4 = (D_ * D_) / 4;
        conv_f16<<<(w4 + 255) / 256, 256>>>(Wq, WqH, w4);             // #2
        conv_f16<<<(w4 + 255) / 256, 256>>>(Wk, WkH, w4);             // #3
        conv_f16<<<(w4 + 255) / 256, 256>>>(Wv, WvH, w4);             // #4
        conv_f16<<<(w4 + 255) / 256, 256>>>(Wo, WoH, w4);             // #5
    }

    // #6: BIG Q projection -> fp16
    hgemm2c<false, false, true><<<dim3(D_ / 128, (B_ * S_TOT) / 128, 1), 256, SMEM_TOTAL_GEMM>>>(
        hsH, WqH, nullptr, nullptr, QbH, B_ * S_TOT, D_, D_, 0, 0);

    // MLP + pool + comp K/V (fp16 outputs)
    {
        int f4 = (D_ * DFF) / 4;
        conv_f16<<<(f4 + 255) / 256, 256>>>(W1, W1H, f4);
        conv_f16<<<(f4 + 255) / 256, 256>>>(W2, W2H, f4);
    }
    hgemm2c<true, true, true><<<dim3(DFF / 128, CTX / 128, B_), 256, SMEM_TOTAL_GEMM>>>(
        hsH, W1H, b1, nullptr, mlpH,
        CTX, DFF, D_, sTOK, (size_t)CTX * DFF);
    hgemm2c<false, true, false><<<dim3(D_ / 128, CTX / 128, B_), 256, SMEM_TOTAL_GEMM>>>(
        mlpH, W2H, b2, comp_full, nullptr,
        CTX, D_, DFF, (size_t)CTX * DFF, (size_t)CTX * D_);
    pool_mean_h<<<(B_ * POOL * D_) / 256, 256>>>(comp_full, cmpH);
    hgemm2c<false, false, true><<<dim3(D_ / 128, (B_ * POOL) / 128, 1), 256, SMEM_TOTAL_GEMM>>>(
        cmpH, WkH, nullptr, nullptr, KcH, B_ * POOL, D_, D_, 0, 0);
    hgemm2c<false, false, true><<<dim3(D_ / 128, (B_ * POOL) / 128, 1), 256, SMEM_TOTAL_GEMM>>>(
        cmpH, WvH, nullptr, nullptr, VcH, B_ * POOL, D_, D_, 0, 0);

    // K,V on initial tokens (fp32, for causal)
    hgemm2c<false, false, false><<<dim3(D_ / 128, CTX / 128, B_), 256, SMEM_TOTAL_GEMM>>>(
        hsH, WkH, nullptr, Kin, nullptr,
        CTX, D_, D_, sTOK, (size_t)CTX * D_);
    hgemm2c<false, false, false><<<dim3(D_ / 128, CTX / 128, B_), 256, SMEM_TOTAL_GEMM>>>(
        hsH, WvH, nullptr, Vin, nullptr,
        CTX, D_, D_, sTOK, (size_t)CTX * D_);

    // attention
    xattn_tc<<<dim3(REM / 256, NH, B_), 256, XA_SMEM>>>(QbH, KcH, VcH, attH);
    causal_attn<<<dim3(CTX / 128, NH, B_), 128>>>(QbH, Kin, Vin, attH);

    // output projection into d_out
    hgemm2c<false, false, false><<<dim3(D_ / 128, (B_ * S_TOT) / 128, 1), 256, SMEM_TOTAL_GEMM>>>(
        attH, WoH, nullptr, out, nullptr, B_ * S_TOT, D_, D_, 0, 0);

    (void)in_sizes; (void)n_in; (void)out_size;
}